// round 6
// baseline (speedup 1.0000x reference)
#include <cuda_runtime.h>
#include <math.h>

#define T_FRAMES 256
#define NDET     16
#define HDIM     256
#define DHEAD    32
#define WINR     8
#define MWIN     272         // (2*WINR+1)*NDET
#define NTOK     16384       // 4*256*16
#define FFN      1024

__device__ float g_q[NTOK * HDIM];
__device__ float g_k[NTOK * HDIM];
__device__ float g_v[NTOK * HDIM];
__device__ float g_c[NTOK * HDIM];
__device__ float g_y[NTOK * HDIM];
__device__ float g_h[NTOK * FFN];
__device__ float g_z[NTOK * HDIM];

__device__ __forceinline__ unsigned f2tf(float f) {
    unsigned u;
    asm("cvt.rna.tf32.f32 %0, %1;" : "=r"(u) : "f"(f));
    return u;
}

__device__ __forceinline__ void mma_tf32(float c[4],
    unsigned a0, unsigned a1, unsigned a2, unsigned a3, unsigned b0, unsigned b1) {
    asm volatile(
        "mma.sync.aligned.m16n8k8.row.col.f32.tf32.tf32.f32 "
        "{%0,%1,%2,%3}, {%4,%5,%6,%7}, {%8,%9}, {%0,%1,%2,%3};\n"
        : "+f"(c[0]), "+f"(c[1]), "+f"(c[2]), "+f"(c[3])
        : "r"(a0), "r"(a1), "r"(a2), "r"(a3), "r"(b0), "r"(b1));
}

// C[M,N] = act((A[M,K] @ B[K,N] + bias) * scale). BM=128 BN=64 BK=16, 256 thr.
template <bool RELU>
__global__ __launch_bounds__(256) void gemm_tf32(
    const float* __restrict__ A, const float* __restrict__ B,
    const float* __restrict__ bias, float* __restrict__ C,
    int M, int N, int K, float scale)
{
    __shared__ unsigned As[128][20];
    __shared__ unsigned Bs[16][72];

    const int tid = threadIdx.x;
    const int warp = tid >> 5, lane = tid & 31;
    const int g = lane >> 2, tg = lane & 3;
    const int wm = (warp >> 1) << 5;
    const int wn = (warp & 1) << 5;
    const int gm0 = blockIdx.y << 7;
    const int gn0 = blockIdx.x << 6;

    const int arow = tid >> 2;
    const int ac   = (tid & 3) << 2;
    const int brow = tid >> 4;
    const int bc   = (tid & 15) << 2;

    const float* Ap = A + (long)(gm0 + arow) * K + ac;
    const float* Bp = B + (long)brow * N + gn0 + bc;

    float acc[2][4][4];
#pragma unroll
    for (int i = 0; i < 2; i++)
#pragma unroll
        for (int j = 0; j < 4; j++)
#pragma unroll
            for (int l = 0; l < 4; l++) acc[i][j][l] = 0.f;

    const int nk = K >> 4;
    float4 ra0 = *(const float4*)(Ap);
    float4 ra1 = *(const float4*)(Ap + (long)64 * K);
    float4 rb  = *(const float4*)(Bp);

    for (int kt = 0; kt < nk; kt++) {
        __syncthreads();
        As[arow][ac+0] = f2tf(ra0.x); As[arow][ac+1] = f2tf(ra0.y);
        As[arow][ac+2] = f2tf(ra0.z); As[arow][ac+3] = f2tf(ra0.w);
        As[arow+64][ac+0] = f2tf(ra1.x); As[arow+64][ac+1] = f2tf(ra1.y);
        As[arow+64][ac+2] = f2tf(ra1.z); As[arow+64][ac+3] = f2tf(ra1.w);
        Bs[brow][bc+0] = f2tf(rb.x); Bs[brow][bc+1] = f2tf(rb.y);
        Bs[brow][bc+2] = f2tf(rb.z); Bs[brow][bc+3] = f2tf(rb.w);
        __syncthreads();

        if (kt + 1 < nk) {
            ra0 = *(const float4*)(Ap + (kt + 1) * 16);
            ra1 = *(const float4*)(Ap + (long)64 * K + (kt + 1) * 16);
            rb  = *(const float4*)(Bp + (long)(kt + 1) * 16 * N);
        }

#pragma unroll
        for (int ks = 0; ks < 2; ks++) {
            const int k0 = ks << 3;
            unsigned af[2][4], bf[4][2];
#pragma unroll
            for (int mt = 0; mt < 2; mt++) {
                int r = wm + (mt << 4) + g;
                af[mt][0] = As[r][k0 + tg];
                af[mt][1] = As[r + 8][k0 + tg];
                af[mt][2] = As[r][k0 + tg + 4];
                af[mt][3] = As[r + 8][k0 + tg + 4];
            }
#pragma unroll
            for (int nt = 0; nt < 4; nt++) {
                bf[nt][0] = Bs[k0 + tg][wn + (nt << 3) + g];
                bf[nt][1] = Bs[k0 + tg + 4][wn + (nt << 3) + g];
            }
#pragma unroll
            for (int mt = 0; mt < 2; mt++)
#pragma unroll
                for (int nt = 0; nt < 4; nt++)
                    mma_tf32(acc[mt][nt], af[mt][0], af[mt][1], af[mt][2], af[mt][3],
                             bf[nt][0], bf[nt][1]);
        }
    }

#pragma unroll
    for (int mt = 0; mt < 2; mt++) {
        int row = gm0 + wm + (mt << 4) + g;
#pragma unroll
        for (int nt = 0; nt < 4; nt++) {
            int col = gn0 + wn + (nt << 3) + (tg << 1);
            float b0 = bias[col], b1 = bias[col + 1];
            float v0 = (acc[mt][nt][0] + b0) * scale;
            float v1 = (acc[mt][nt][1] + b1) * scale;
            float v2 = (acc[mt][nt][2] + b0) * scale;
            float v3 = (acc[mt][nt][3] + b1) * scale;
            if (RELU) {
                v0 = fmaxf(v0, 0.f); v1 = fmaxf(v1, 0.f);
                v2 = fmaxf(v2, 0.f); v3 = fmaxf(v3, 0.f);
            }
            *(float2*)(C + (long)row * N + col)       = make_float2(v0, v1);
            *(float2*)(C + (long)(row + 8) * N + col) = make_float2(v2, v3);
        }
    }
}

// Windowed attention: one block per (t,b,head), 256 threads, fused softmax.
#define ATTN_SMEM_BYTES ((32*272 + 272*32 + 512 + 16*276 + 272 + 16) * 4)

__global__ __launch_bounds__(256) void attn_kernel(
    const float* __restrict__ q, const float* __restrict__ k,
    const float* __restrict__ v, const unsigned char* __restrict__ kpm,
    float* __restrict__ ctx)
{
    extern __shared__ float sm[];
    float* Kt      = sm;                 // [32][272]  (k-index major)
    float* Vr      = Kt + 32 * 272;      // [272][32]
    float* Qt      = Vr + 272 * 32;      // [32][16]
    float* S       = Qt + 512;           // [16][276]
    float* maskadd = S + 16 * 276;       // [272]
    float* rowinv  = maskadd + 272;      // [16]
    float* R       = Kt;                 // alias: [8][32][16] PV partials

    const int tid = threadIdx.x;
    const int t = blockIdx.x, b = blockIdx.y, h = blockIdx.z;
    const long bt = (long)(b * T_FRAMES + t);

    for (int slot = tid; slot < 8 * MWIN; slot += 256) {
        int d4 = slot / MWIN;
        int m  = slot - d4 * MWIN;
        int w = m >> 4, n = m & 15;
        int f = t + w - WINR;
        float4 kv = make_float4(0.f, 0.f, 0.f, 0.f);
        if (f >= 0 && f < T_FRAMES)
            kv = *(const float4*)(k + ((long)((b * T_FRAMES + f) * NDET + n)) * HDIM
                                    + h * DHEAD + (d4 << 2));
        Kt[(d4 * 4 + 0) * MWIN + m] = kv.x;
        Kt[(d4 * 4 + 1) * MWIN + m] = kv.y;
        Kt[(d4 * 4 + 2) * MWIN + m] = kv.z;
        Kt[(d4 * 4 + 3) * MWIN + m] = kv.w;
    }
    for (int slot = tid; slot < 8 * MWIN; slot += 256) {
        int m = slot >> 3, d4 = slot & 7;
        int w = m >> 4, n = m & 15;
        int f = t + w - WINR;
        float4 vv = make_float4(0.f, 0.f, 0.f, 0.f);
        if (f >= 0 && f < T_FRAMES)
            vv = *(const float4*)(v + ((long)((b * T_FRAMES + f) * NDET + n)) * HDIM
                                    + h * DHEAD + (d4 << 2));
        *(float4*)(Vr + m * 32 + (d4 << 2)) = vv;
    }
    if (tid < 128) {
        int n = tid >> 3, d4 = tid & 7;
        float4 qv = *(const float4*)(q + (bt * NDET + n) * HDIM + h * DHEAD + (d4 << 2));
        Qt[(d4 * 4 + 0) * 16 + n] = qv.x;
        Qt[(d4 * 4 + 1) * 16 + n] = qv.y;
        Qt[(d4 * 4 + 2) * 16 + n] = qv.z;
        Qt[(d4 * 4 + 3) * 16 + n] = qv.w;
    }
    for (int m = tid; m < MWIN; m += 256) {
        int w = m >> 4, n = m & 15;
        int f = t + w - WINR;
        bool ok = (f >= 0) && (f < T_FRAMES) &&
                  (kpm[(b * T_FRAMES + f) * NDET + n] == 0);
        maskadd[m] = ok ? 0.f : -1e30f;
    }
    __syncthreads();

    // logits S[n][m], 4x4 register tiles
    {
        const int n0 = (tid >> 6) << 2;
        for (int mg = (tid & 63); mg < 68; mg += 64) {
            float a[4][4];
#pragma unroll
            for (int i = 0; i < 4; i++)
#pragma unroll
                for (int j = 0; j < 4; j++) a[i][j] = 0.f;
#pragma unroll 8
            for (int kk = 0; kk < 32; kk++) {
                float4 qv = *(const float4*)(Qt + kk * 16 + n0);
                float4 kv = *(const float4*)(Kt + kk * MWIN + (mg << 2));
                a[0][0] += qv.x*kv.x; a[0][1] += qv.x*kv.y; a[0][2] += qv.x*kv.z; a[0][3] += qv.x*kv.w;
                a[1][0] += qv.y*kv.x; a[1][1] += qv.y*kv.y; a[1][2] += qv.y*kv.z; a[1][3] += qv.y*kv.w;
                a[2][0] += qv.z*kv.x; a[2][1] += qv.z*kv.y; a[2][2] += qv.z*kv.z; a[2][3] += qv.z*kv.w;
                a[3][0] += qv.w*kv.x; a[3][1] += qv.w*kv.y; a[3][2] += qv.w*kv.z; a[3][3] += qv.w*kv.w;
            }
#pragma unroll
            for (int i = 0; i < 4; i++)
                *(float4*)(S + (n0 + i) * 276 + (mg << 2)) =
                    make_float4(a[i][0], a[i][1], a[i][2], a[i][3]);
        }
    }
    __syncthreads();

    // masked softmax over m (16 lanes per row)
    {
        const int n = tid >> 4, l16 = tid & 15;
        float mx = -1e30f;
        for (int m = l16; m < MWIN; m += 16) {
            float vv = S[n * 276 + m] + maskadd[m];
            S[n * 276 + m] = vv;
            mx = fmaxf(mx, vv);
        }
#pragma unroll
        for (int o = 8; o; o >>= 1) mx = fmaxf(mx, __shfl_xor_sync(0xffffffffu, mx, o));
        float sum = 0.f;
        for (int m = l16; m < MWIN; m += 16) {
            float e = __expf(S[n * 276 + m] - mx);
            S[n * 276 + m] = e;
            sum += e;
        }
#pragma unroll
        for (int o = 8; o; o >>= 1) sum += __shfl_xor_sync(0xffffffffu, sum, o);
        if (l16 == 0) rowinv[n] = 1.0f / sum;
    }
    __syncthreads();

    // ctx = P @ V, m-sum split across 8 warps, partials into R (alias of Kt)
    {
        const int dg  = tid & 7;
        const int ngc = (tid >> 3) & 3;
        const int ms  = tid >> 5;
        const int n0c = ngc << 2;
        float a[4][4];
#pragma unroll
        for (int i = 0; i < 4; i++)
#pragma unroll
            for (int j = 0; j < 4; j++) a[i][j] = 0.f;

        for (int m = ms; m < MWIN; m += 8) {
            float4 vv = *(const float4*)(Vr + m * 32 + (dg << 2));
            float p0 = S[(n0c + 0) * 276 + m];
            float p1 = S[(n0c + 1) * 276 + m];
            float p2 = S[(n0c + 2) * 276 + m];
            float p3 = S[(n0c + 3) * 276 + m];
            a[0][0] += p0*vv.x; a[0][1] += p0*vv.y; a[0][2] += p0*vv.z; a[0][3] += p0*vv.w;
            a[1][0] += p1*vv.x; a[1][1] += p1*vv.y; a[1][2] += p1*vv.z; a[1][3] += p1*vv.w;
            a[2][0] += p2*vv.x; a[2][1] += p2*vv.y; a[2][2] += p2*vv.z; a[2][3] += p2*vv.w;
            a[3][0] += p3*vv.x; a[3][1] += p3*vv.y; a[3][2] += p3*vv.z; a[3][3] += p3*vv.w;
        }
        const int lane32 = tid & 31;
#pragma unroll
        for (int i = 0; i < 4; i++)
            *(float4*)(R + ((ms * 32 + lane32) * 16) + (i << 2)) =
                make_float4(a[i][0], a[i][1], a[i][2], a[i][3]);
    }
    __syncthreads();

    for (int o = tid; o < 512; o += 256) {
        int nn = o >> 5, dd = o & 31;
        int lg  = ((nn >> 2) << 3) + (dd >> 2);
        int idx = ((nn & 3) << 2) + (dd & 3);
        float s = 0.f;
#pragma unroll
        for (int msr = 0; msr < 8; msr++) s += R[(msr * 32 + lg) * 16 + idx];
        ctx[(bt * NDET + nn) * HDIM + h * DHEAD + dd] = s * rowinv[nn];
    }
}

// residual add + LayerNorm; one warp per token (H=256 -> 8 floats/lane)
__global__ __launch_bounds__(256) void add_ln_kernel(
    const float* __restrict__ A, const float* __restrict__ Bv,
    const float* __restrict__ gw, const float* __restrict__ bw,
    float* __restrict__ out)
{
    const int tok  = (blockIdx.x << 3) + (threadIdx.x >> 5);
    const int lane = threadIdx.x & 31;
    const float4* a4 = (const float4*)(A  + (long)tok * HDIM);
    const float4* b4 = (const float4*)(Bv + (long)tok * HDIM);
    float4 p0 = a4[lane * 2], p1 = a4[lane * 2 + 1];
    float4 q0 = b4[lane * 2], q1 = b4[lane * 2 + 1];
    float vv[8] = { p0.x + q0.x, p0.y + q0.y, p0.z + q0.z, p0.w + q0.w,
                    p1.x + q1.x, p1.y + q1.y, p1.z + q1.z, p1.w + q1.w };
    float s = 0.f;
#pragma unroll
    for (int i = 0; i < 8; i++) s += vv[i];
#pragma unroll
    for (int o = 16; o; o >>= 1) s += __shfl_xor_sync(0xffffffffu, s, o);
    const float mean = s * (1.f / 256.f);
    float vs = 0.f;
#pragma unroll
    for (int i = 0; i < 8; i++) { float d = vv[i] - mean; vs += d * d; }
#pragma unroll
    for (int o = 16; o; o >>= 1) vs += __shfl_xor_sync(0xffffffffu, vs, o);
    const float rs = rsqrtf(vs * (1.f / 256.f) + 1e-5f);

    float4 g0 = ((const float4*)gw)[lane * 2], g1 = ((const float4*)gw)[lane * 2 + 1];
    float4 e0 = ((const float4*)bw)[lane * 2], e1 = ((const float4*)bw)[lane * 2 + 1];
    float4 o0, o1;
    o0.x = (vv[0]-mean)*rs*g0.x + e0.x;  o0.y = (vv[1]-mean)*rs*g0.y + e0.y;
    o0.z = (vv[2]-mean)*rs*g0.z + e0.z;  o0.w = (vv[3]-mean)*rs*g0.w + e0.w;
    o1.x = (vv[4]-mean)*rs*g1.x + e1.x;  o1.y = (vv[5]-mean)*rs*g1.y + e1.y;
    o1.z = (vv[6]-mean)*rs*g1.z + e1.z;  o1.w = (vv[7]-mean)*rs*g1.w + e1.w;
    float4* o4 = (float4*)(out + (long)tok * HDIM);
    o4[lane * 2]     = o0;
    o4[lane * 2 + 1] = o1;
}

extern "C" void kernel_launch(void* const* d_in, const int* in_sizes, int n_in,
                              void* d_out, int out_size)
{
    const float* x   = (const float*)d_in[0];
    const unsigned char* kpm = (const unsigned char*)d_in[1];
    const float* Wq = (const float*)d_in[2];
    const float* bq = (const float*)d_in[3];
    const float* Wk = (const float*)d_in[4];
    const float* bk = (const float*)d_in[5];
    const float* Wv = (const float*)d_in[6];
    const float* bv = (const float*)d_in[7];
    const float* W1 = (const float*)d_in[8];
    const float* b1 = (const float*)d_in[9];
    const float* W2 = (const float*)d_in[10];
    const float* b2 = (const float*)d_in[11];
    const float* g1 = (const float*)d_in[12];
    const float* be1 = (const float*)d_in[13];
    const float* g2 = (const float*)d_in[14];
    const float* be2 = (const float*)d_in[15];
    float* out = (float*)d_out;

    float *qb, *kb, *vb, *cb, *yb, *hb, *zb;
    cudaGetSymbolAddress((void**)&qb, g_q);
    cudaGetSymbolAddress((void**)&kb, g_k);
    cudaGetSymbolAddress((void**)&vb, g_v);
    cudaGetSymbolAddress((void**)&cb, g_c);
    cudaGetSymbolAddress((void**)&yb, g_y);
    cudaGetSymbolAddress((void**)&hb, g_h);
    cudaGetSymbolAddress((void**)&zb, g_z);

    cudaFuncSetAttribute(attn_kernel,
                         cudaFuncAttributeMaxDynamicSharedMemorySize, ATTN_SMEM_BYTES);

    const float qscale = 0.17677669529663687f; // 1/sqrt(32)
    dim3 blk(256);
    dim3 gProj(HDIM / 64, NTOK / 128);   // N=256
    dim3 gF1(FFN / 64, NTOK / 128);      // N=1024
    dim3 gF2(HDIM / 64, NTOK / 128);

    gemm_tf32<false><<<gProj, blk>>>(x, Wq, bq, qb, NTOK, HDIM, HDIM, qscale);
    gemm_tf32<false><<<gProj, blk>>>(x, Wk, bk, kb, NTOK, HDIM, HDIM, 1.0f);
    gemm_tf32<false><<<gProj, blk>>>(x, Wv, bv, vb, NTOK, HDIM, HDIM, 1.0f);

    dim3 gAttn(T_FRAMES, 4, 8);
    attn_kernel<<<gAttn, blk, ATTN_SMEM_BYTES>>>(qb, kb, vb, kpm, cb);

    add_ln_kernel<<<NTOK / 8, blk>>>(x, cb, g1, be1, yb);

    gemm_tf32<true ><<<gF1, blk>>>(yb, W1, b1, hb, NTOK, FFN, HDIM, 1.0f);
    gemm_tf32<false><<<gF2, blk>>>(hb, W2, b2, zb, NTOK, HDIM, FFN, 1.0f);

    add_ln_kernel<<<NTOK / 8, blk>>>(yb, zb, g2, be2, out);
}

// round 7
// speedup vs baseline: 1.1209x; 1.1209x over previous
#include <cuda_runtime.h>
#include <cuda_bf16.h>
#include <math.h>

#define T_FRAMES 256
#define NDET     16
#define HDIM     256
#define DHEAD    32
#define WINR     8
#define MWIN     272         // (2*WINR+1)*NDET
#define NTOK     16384       // 4*256*16
#define FFN      1024

__device__ float g_q[NTOK * HDIM];
__device__ float g_k[NTOK * HDIM];
__device__ float g_v[NTOK * HDIM];
__device__ float g_c[NTOK * HDIM];
__device__ float g_y[NTOK * HDIM];
__device__ float g_h[NTOK * FFN];
__device__ float g_z[NTOK * HDIM];

__device__ __forceinline__ unsigned f2tf(float f) {
    unsigned u;
    asm("cvt.rna.tf32.f32 %0, %1;" : "=r"(u) : "f"(f));
    return u;
}

__device__ __forceinline__ void mma_tf32(float c[4],
    unsigned a0, unsigned a1, unsigned a2, unsigned a3, unsigned b0, unsigned b1) {
    asm volatile(
        "mma.sync.aligned.m16n8k8.row.col.f32.tf32.tf32.f32 "
        "{%0,%1,%2,%3}, {%4,%5,%6,%7}, {%8,%9}, {%0,%1,%2,%3};\n"
        : "+f"(c[0]), "+f"(c[1]), "+f"(c[2]), "+f"(c[3])
        : "r"(a0), "r"(a1), "r"(a2), "r"(a3), "r"(b0), "r"(b1));
}

// C[M,N] = act((A[M,K] @ B[K,N] + bias) * scale). BM=128 BN=64 BK=16, 256 thr.
template <bool RELU>
__global__ __launch_bounds__(256) void gemm_tf32(
    const float* __restrict__ A, const float* __restrict__ B,
    const float* __restrict__ bias, float* __restrict__ C,
    int M, int N, int K, float scale)
{
    __shared__ unsigned As[128][20];
    __shared__ unsigned Bs[16][72];

    const int tid = threadIdx.x;
    const int warp = tid >> 5, lane = tid & 31;
    const int g = lane >> 2, tg = lane & 3;
    const int wm = (warp >> 1) << 5;
    const int wn = (warp & 1) << 5;
    const int gm0 = blockIdx.y << 7;
    const int gn0 = blockIdx.x << 6;

    const int arow = tid >> 2;
    const int ac   = (tid & 3) << 2;
    const int brow = tid >> 4;
    const int bc   = (tid & 15) << 2;

    const float* Ap = A + (long)(gm0 + arow) * K + ac;
    const float* Bp = B + (long)brow * N + gn0 + bc;

    float acc[2][4][4];
#pragma unroll
    for (int i = 0; i < 2; i++)
#pragma unroll
        for (int j = 0; j < 4; j++)
#pragma unroll
            for (int l = 0; l < 4; l++) acc[i][j][l] = 0.f;

    const int nk = K >> 4;
    float4 ra0 = *(const float4*)(Ap);
    float4 ra1 = *(const float4*)(Ap + (long)64 * K);
    float4 rb  = *(const float4*)(Bp);

    for (int kt = 0; kt < nk; kt++) {
        __syncthreads();
        As[arow][ac+0] = f2tf(ra0.x); As[arow][ac+1] = f2tf(ra0.y);
        As[arow][ac+2] = f2tf(ra0.z); As[arow][ac+3] = f2tf(ra0.w);
        As[arow+64][ac+0] = f2tf(ra1.x); As[arow+64][ac+1] = f2tf(ra1.y);
        As[arow+64][ac+2] = f2tf(ra1.z); As[arow+64][ac+3] = f2tf(ra1.w);
        Bs[brow][bc+0] = f2tf(rb.x); Bs[brow][bc+1] = f2tf(rb.y);
        Bs[brow][bc+2] = f2tf(rb.z); Bs[brow][bc+3] = f2tf(rb.w);
        __syncthreads();

        if (kt + 1 < nk) {
            ra0 = *(const float4*)(Ap + (kt + 1) * 16);
            ra1 = *(const float4*)(Ap + (long)64 * K + (kt + 1) * 16);
            rb  = *(const float4*)(Bp + (long)(kt + 1) * 16 * N);
        }

#pragma unroll
        for (int ks = 0; ks < 2; ks++) {
            const int k0 = ks << 3;
            unsigned af[2][4], bf[4][2];
#pragma unroll
            for (int mt = 0; mt < 2; mt++) {
                int r = wm + (mt << 4) + g;
                af[mt][0] = As[r][k0 + tg];
                af[mt][1] = As[r + 8][k0 + tg];
                af[mt][2] = As[r][k0 + tg + 4];
                af[mt][3] = As[r + 8][k0 + tg + 4];
            }
#pragma unroll
            for (int nt = 0; nt < 4; nt++) {
                bf[nt][0] = Bs[k0 + tg][wn + (nt << 3) + g];
                bf[nt][1] = Bs[k0 + tg + 4][wn + (nt << 3) + g];
            }
#pragma unroll
            for (int mt = 0; mt < 2; mt++)
#pragma unroll
                for (int nt = 0; nt < 4; nt++)
                    mma_tf32(acc[mt][nt], af[mt][0], af[mt][1], af[mt][2], af[mt][3],
                             bf[nt][0], bf[nt][1]);
        }
    }

#pragma unroll
    for (int mt = 0; mt < 2; mt++) {
        int row = gm0 + wm + (mt << 4) + g;
#pragma unroll
        for (int nt = 0; nt < 4; nt++) {
            int col = gn0 + wn + (nt << 3) + (tg << 1);
            float b0 = bias[col], b1 = bias[col + 1];
            float v0 = (acc[mt][nt][0] + b0) * scale;
            float v1 = (acc[mt][nt][1] + b1) * scale;
            float v2 = (acc[mt][nt][2] + b0) * scale;
            float v3 = (acc[mt][nt][3] + b1) * scale;
            if (RELU) {
                v0 = fmaxf(v0, 0.f); v1 = fmaxf(v1, 0.f);
                v2 = fmaxf(v2, 0.f); v3 = fmaxf(v3, 0.f);
            }
            *(float2*)(C + (long)row * N + col)       = make_float2(v0, v1);
            *(float2*)(C + (long)(row + 8) * N + col) = make_float2(v2, v3);
        }
    }
}

// ---------------- windowed attention ----------------
// One block per (t,b,head), 256 threads. K/V cached in smem as bf16 to fit
// 4 blocks/SM (54.4 KB); accumulation stays fp32.
#define KT_BYTES   (32 * 272 * 2)                  // 17408
#define VR_BYTES   (272 * 32 * 2)                  // 17408
#define QT_BYTES   (32 * 16 * 4)                   // 2048
#define S_BYTES    (16 * 276 * 4)                  // 17664
#define MASK_BYTES (272 * 4)                       // 1088
#define ATTN_SMEM_BYTES (KT_BYTES + VR_BYTES + QT_BYTES + S_BYTES + MASK_BYTES + 64)

__global__ __launch_bounds__(256) void attn_kernel(
    const float* __restrict__ q, const float* __restrict__ k,
    const float* __restrict__ v, const unsigned char* __restrict__ kpm,
    float* __restrict__ ctx)
{
    extern __shared__ char smc[];
    __nv_bfloat16* Kt = (__nv_bfloat16*)smc;                       // [32][272]
    __nv_bfloat16* Vr = (__nv_bfloat16*)(smc + KT_BYTES);          // [272][32]
    float* Qt      = (float*)(smc + KT_BYTES + VR_BYTES);          // [32][16]
    float* S       = Qt + 512;                                     // [16][276]
    float* maskadd = S + 16 * 276;                                 // [272]
    float* rowinv  = maskadd + 272;                                // [16]
    float* R       = (float*)smc;  // alias Kt: [8][32][16] fp32 = 16 KB ≤ 17 KB

    const int tid = threadIdx.x;
    const int t = blockIdx.x, b = blockIdx.y, h = blockIdx.z;
    const long bt = (long)(b * T_FRAMES + t);

    // K window, transposed (k-index major), bf16
    for (int slot = tid; slot < 8 * MWIN; slot += 256) {
        int d4 = slot / MWIN;
        int m  = slot - d4 * MWIN;
        int w = m >> 4, n = m & 15;
        int f = t + w - WINR;
        float4 kv = make_float4(0.f, 0.f, 0.f, 0.f);
        if (f >= 0 && f < T_FRAMES)
            kv = *(const float4*)(k + ((long)((b * T_FRAMES + f) * NDET + n)) * HDIM
                                    + h * DHEAD + (d4 << 2));
        Kt[(d4 * 4 + 0) * MWIN + m] = __float2bfloat16(kv.x);
        Kt[(d4 * 4 + 1) * MWIN + m] = __float2bfloat16(kv.y);
        Kt[(d4 * 4 + 2) * MWIN + m] = __float2bfloat16(kv.z);
        Kt[(d4 * 4 + 3) * MWIN + m] = __float2bfloat16(kv.w);
    }
    // V window, row major, bf16
    for (int slot = tid; slot < 8 * MWIN; slot += 256) {
        int m = slot >> 3, d4 = slot & 7;
        int w = m >> 4, n = m & 15;
        int f = t + w - WINR;
        float4 vv = make_float4(0.f, 0.f, 0.f, 0.f);
        if (f >= 0 && f < T_FRAMES)
            vv = *(const float4*)(v + ((long)((b * T_FRAMES + f) * NDET + n)) * HDIM
                                    + h * DHEAD + (d4 << 2));
        __nv_bfloat162* dst = (__nv_bfloat162*)(Vr + m * 32 + (d4 << 2));
        dst[0] = __floats2bfloat162_rn(vv.x, vv.y);
        dst[1] = __floats2bfloat162_rn(vv.z, vv.w);
    }
    // Q transposed, fp32
    if (tid < 128) {
        int n = tid >> 3, d4 = tid & 7;
        float4 qv = *(const float4*)(q + (bt * NDET + n) * HDIM + h * DHEAD + (d4 << 2));
        Qt[(d4 * 4 + 0) * 16 + n] = qv.x;
        Qt[(d4 * 4 + 1) * 16 + n] = qv.y;
        Qt[(d4 * 4 + 2) * 16 + n] = qv.z;
        Qt[(d4 * 4 + 3) * 16 + n] = qv.w;
    }
    for (int m = tid; m < MWIN; m += 256) {
        int w = m >> 4, n = m & 15;
        int f = t + w - WINR;
        bool ok = (f >= 0) && (f < T_FRAMES) &&
                  (kpm[(b * T_FRAMES + f) * NDET + n] == 0);
        maskadd[m] = ok ? 0.f : -1e30f;
    }
    __syncthreads();

    // logits S[n][m] = q[n].k[m], 4x4 register tiles, fp32 accumulate
    {
        const int n0 = (tid >> 6) << 2;
        for (int mg = (tid & 63); mg < 68; mg += 64) {
            float a[4][4];
#pragma unroll
            for (int i = 0; i < 4; i++)
#pragma unroll
                for (int j = 0; j < 4; j++) a[i][j] = 0.f;
#pragma unroll 8
            for (int kk = 0; kk < 32; kk++) {
                float4 qv = *(const float4*)(Qt + kk * 16 + n0);
                uint2 kraw = *(const uint2*)(Kt + kk * MWIN + (mg << 2));
                float2 k01 = __bfloat1622float2(*(__nv_bfloat162*)&kraw.x);
                float2 k23 = __bfloat1622float2(*(__nv_bfloat162*)&kraw.y);
                a[0][0] += qv.x*k01.x; a[0][1] += qv.x*k01.y; a[0][2] += qv.x*k23.x; a[0][3] += qv.x*k23.y;
                a[1][0] += qv.y*k01.x; a[1][1] += qv.y*k01.y; a[1][2] += qv.y*k23.x; a[1][3] += qv.y*k23.y;
                a[2][0] += qv.z*k01.x; a[2][1] += qv.z*k01.y; a[2][2] += qv.z*k23.x; a[2][3] += qv.z*k23.y;
                a[3][0] += qv.w*k01.x; a[3][1] += qv.w*k01.y; a[3][2] += qv.w*k23.x; a[3][3] += qv.w*k23.y;
            }
#pragma unroll
            for (int i = 0; i < 4; i++)
                *(float4*)(S + (n0 + i) * 276 + (mg << 2)) =
                    make_float4(a[i][0], a[i][1], a[i][2], a[i][3]);
        }
    }
    __syncthreads();

    // masked softmax over m (16 lanes per row)
    {
        const int n = tid >> 4, l16 = tid & 15;
        float mx = -1e30f;
        for (int m = l16; m < MWIN; m += 16) {
            float vv = S[n * 276 + m] + maskadd[m];
            S[n * 276 + m] = vv;
            mx = fmaxf(mx, vv);
        }
#pragma unroll
        for (int o = 8; o; o >>= 1) mx = fmaxf(mx, __shfl_xor_sync(0xffffffffu, mx, o));
        float sum = 0.f;
        for (int m = l16; m < MWIN; m += 16) {
            float e = __expf(S[n * 276 + m] - mx);
            S[n * 276 + m] = e;
            sum += e;
        }
#pragma unroll
        for (int o = 8; o; o >>= 1) sum += __shfl_xor_sync(0xffffffffu, sum, o);
        if (l16 == 0) rowinv[n] = 1.0f / sum;
    }
    __syncthreads();

    // ctx = P @ V, m-sum split across 8 warps, partials into R (alias of Kt)
    {
        const int dg  = tid & 7;
        const int ngc = (tid >> 3) & 3;
        const int ms  = tid >> 5;
        const int n0c = ngc << 2;
        float a[4][4];
#pragma unroll
        for (int i = 0; i < 4; i++)
#pragma unroll
            for (int j = 0; j < 4; j++) a[i][j] = 0.f;

        for (int m = ms; m < MWIN; m += 8) {
            uint2 vraw = *(const uint2*)(Vr + m * 32 + (dg << 2));
            float2 v01 = __bfloat1622float2(*(__nv_bfloat162*)&vraw.x);
            float2 v23 = __bfloat1622float2(*(__nv_bfloat162*)&vraw.y);
            float p0 = S[(n0c + 0) * 276 + m];
            float p1 = S[(n0c + 1) * 276 + m];
            float p2 = S[(n0c + 2) * 276 + m];
            float p3 = S[(n0c + 3) * 276 + m];
            a[0][0] += p0*v01.x; a[0][1] += p0*v01.y; a[0][2] += p0*v23.x; a[0][3] += p0*v23.y;
            a[1][0] += p1*v01.x; a[1][1] += p1*v01.y; a[1][2] += p1*v23.x; a[1][3] += p1*v23.y;
            a[2][0] += p2*v01.x; a[2][1] += p2*v01.y; a[2][2] += p2*v23.x; a[2][3] += p2*v23.y;
            a[3][0] += p3*v01.x; a[3][1] += p3*v01.y; a[3][2] += p3*v23.x; a[3][3] += p3*v23.y;
        }
        const int lane32 = tid & 31;
#pragma unroll
        for (int i = 0; i < 4; i++)
            *(float4*)(R + ((ms * 32 + lane32) * 16) + (i << 2)) =
                make_float4(a[i][0], a[i][1], a[i][2], a[i][3]);
    }
    __syncthreads();

    for (int o = tid; o < 512; o += 256) {
        int nn = o >> 5, dd = o & 31;
        int lg  = ((nn >> 2) << 3) + (dd >> 2);
        int idx = ((nn & 3) << 2) + (dd & 3);
        float s = 0.f;
#pragma unroll
        for (int msr = 0; msr < 8; msr++) s += R[(msr * 32 + lg) * 16 + idx];
        ctx[(bt * NDET + nn) * HDIM + h * DHEAD + dd] = s * rowinv[nn];
    }
}

// residual add + LayerNorm; one warp per token (H=256 -> 8 floats/lane)
__global__ __launch_bounds__(256) void add_ln_kernel(
    const float* __restrict__ A, const float* __restrict__ Bv,
    const float* __restrict__ gw, const float* __restrict__ bw,
    float* __restrict__ out)
{
    const int tok  = (blockIdx.x << 3) + (threadIdx.x >> 5);
    const int lane = threadIdx.x & 31;
    const float4* a4 = (const float4*)(A  + (long)tok * HDIM);
    const float4* b4 = (const float4*)(Bv + (long)tok * HDIM);
    float4 p0 = a4[lane * 2], p1 = a4[lane * 2 + 1];
    float4 q0 = b4[lane * 2], q1 = b4[lane * 2 + 1];
    float vv[8] = { p0.x + q0.x, p0.y + q0.y, p0.z + q0.z, p0.w + q0.w,
                    p1.x + q1.x, p1.y + q1.y, p1.z + q1.z, p1.w + q1.w };
    float s = 0.f;
#pragma unroll
    for (int i = 0; i < 8; i++) s += vv[i];
#pragma unroll
    for (int o = 16; o; o >>= 1) s += __shfl_xor_sync(0xffffffffu, s, o);
    const float mean = s * (1.f / 256.f);
    float vs = 0.f;
#pragma unroll
    for (int i = 0; i < 8; i++) { float d = vv[i] - mean; vs += d * d; }
#pragma unroll
    for (int o = 16; o; o >>= 1) vs += __shfl_xor_sync(0xffffffffu, vs, o);
    const float rs = rsqrtf(vs * (1.f / 256.f) + 1e-5f);

    float4 g0 = ((const float4*)gw)[lane * 2], g1 = ((const float4*)gw)[lane * 2 + 1];
    float4 e0 = ((const float4*)bw)[lane * 2], e1 = ((const float4*)bw)[lane * 2 + 1];
    float4 o0, o1;
    o0.x = (vv[0]-mean)*rs*g0.x + e0.x;  o0.y = (vv[1]-mean)*rs*g0.y + e0.y;
    o0.z = (vv[2]-mean)*rs*g0.z + e0.z;  o0.w = (vv[3]-mean)*rs*g0.w + e0.w;
    o1.x = (vv[4]-mean)*rs*g1.x + e1.x;  o1.y = (vv[5]-mean)*rs*g1.y + e1.y;
    o1.z = (vv[6]-mean)*rs*g1.z + e1.z;  o1.w = (vv[7]-mean)*rs*g1.w + e1.w;
    float4* o4 = (float4*)(out + (long)tok * HDIM);
    o4[lane * 2]     = o0;
    o4[lane * 2 + 1] = o1;
}

extern "C" void kernel_launch(void* const* d_in, const int* in_sizes, int n_in,
                              void* d_out, int out_size)
{
    const float* x   = (const float*)d_in[0];
    const unsigned char* kpm = (const unsigned char*)d_in[1];
    const float* Wq = (const float*)d_in[2];
    const float* bq = (const float*)d_in[3];
    const float* Wk = (const float*)d_in[4];
    const float* bk = (const float*)d_in[5];
    const float* Wv = (const float*)d_in[6];
    const float* bv = (const float*)d_in[7];
    const float* W1 = (const float*)d_in[8];
    const float* b1 = (const float*)d_in[9];
    const float* W2 = (const float*)d_in[10];
    const float* b2 = (const float*)d_in[11];
    const float* g1 = (const float*)d_in[12];
    const float* be1 = (const float*)d_in[13];
    const float* g2 = (const float*)d_in[14];
    const float* be2 = (const float*)d_in[15];
    float* out = (float*)d_out;

    float *qb, *kb, *vb, *cb, *yb, *hb, *zb;
    cudaGetSymbolAddress((void**)&qb, g_q);
    cudaGetSymbolAddress((void**)&kb, g_k);
    cudaGetSymbolAddress((void**)&vb, g_v);
    cudaGetSymbolAddress((void**)&cb, g_c);
    cudaGetSymbolAddress((void**)&yb, g_y);
    cudaGetSymbolAddress((void**)&hb, g_h);
    cudaGetSymbolAddress((void**)&zb, g_z);

    cudaFuncSetAttribute(attn_kernel,
                         cudaFuncAttributeMaxDynamicSharedMemorySize, ATTN_SMEM_BYTES);

    const float qscale = 0.17677669529663687f; // 1/sqrt(32)
    dim3 blk(256);
    dim3 gProj(HDIM / 64, NTOK / 128);
    dim3 gF1(FFN / 64, NTOK / 128);
    dim3 gF2(HDIM / 64, NTOK / 128);

    gemm_tf32<false><<<gProj, blk>>>(x, Wq, bq, qb, NTOK, HDIM, HDIM, qscale);
    gemm_tf32<false><<<gProj, blk>>>(x, Wk, bk, kb, NTOK, HDIM, HDIM, 1.0f);
    gemm_tf32<false><<<gProj, blk>>>(x, Wv, bv, vb, NTOK, HDIM, HDIM, 1.0f);

    dim3 gAttn(T_FRAMES, 4, 8);
    attn_kernel<<<gAttn, blk, ATTN_SMEM_BYTES>>>(qb, kb, vb, kpm, cb);

    add_ln_kernel<<<NTOK / 8, blk>>>(x, cb, g1, be1, yb);

    gemm_tf32<true ><<<gF1, blk>>>(yb, W1, b1, hb, NTOK, FFN, HDIM, 1.0f);
    gemm_tf32<false><<<gF2, blk>>>(hb, W2, b2, zb, NTOK, HDIM, FFN, 1.0f);

    add_ln_kernel<<<NTOK / 8, blk>>>(yb, zb, g2, be2, out);
}

// round 8
// speedup vs baseline: 1.6495x; 1.4715x over previous
#include <cuda_runtime.h>
#include <cuda_bf16.h>
#include <math.h>

#define T_FRAMES 256
#define NDET     16
#define HDIM     256
#define DHEAD    32
#define WINR     8
#define MWIN     272         // (2*WINR+1)*NDET
#define NTOK     16384       // 4*256*16
#define FFN      1024

__device__ float g_q[NTOK * HDIM];
__device__ float g_k[NTOK * HDIM];
__device__ float g_v[NTOK * HDIM];
__device__ float g_c[NTOK * HDIM];
__device__ float g_y[NTOK * HDIM];
__device__ float g_h[NTOK * FFN];
__device__ float g_z[NTOK * HDIM];

__device__ __forceinline__ unsigned f2tf(float f) {
    unsigned u;
    asm("cvt.rna.tf32.f32 %0, %1;" : "=r"(u) : "f"(f));
    return u;
}

__device__ __forceinline__ void mma_tf32(float c[4],
    unsigned a0, unsigned a1, unsigned a2, unsigned a3, unsigned b0, unsigned b1) {
    asm volatile(
        "mma.sync.aligned.m16n8k8.row.col.f32.tf32.tf32.f32 "
        "{%0,%1,%2,%3}, {%4,%5,%6,%7}, {%8,%9}, {%0,%1,%2,%3};\n"
        : "+f"(c[0]), "+f"(c[1]), "+f"(c[2]), "+f"(c[3])
        : "r"(a0), "r"(a1), "r"(a2), "r"(a3), "r"(b0), "r"(b1));
}

__device__ __forceinline__ void mma_bf16(float c[4],
    unsigned a0, unsigned a1, unsigned a2, unsigned a3, unsigned b0, unsigned b1) {
    asm volatile(
        "mma.sync.aligned.m16n8k16.row.col.f32.bf16.bf16.f32 "
        "{%0,%1,%2,%3}, {%4,%5,%6,%7}, {%8,%9}, {%0,%1,%2,%3};\n"
        : "+f"(c[0]), "+f"(c[1]), "+f"(c[2]), "+f"(c[3])
        : "r"(a0), "r"(a1), "r"(a2), "r"(a3), "r"(b0), "r"(b1));
}

__device__ __forceinline__ void ldsm_x4(unsigned& r0, unsigned& r1, unsigned& r2, unsigned& r3,
                                        unsigned addr) {
    asm volatile("ldmatrix.sync.aligned.m8n8.x4.shared.b16 {%0,%1,%2,%3}, [%4];"
                 : "=r"(r0), "=r"(r1), "=r"(r2), "=r"(r3) : "r"(addr));
}
__device__ __forceinline__ void ldsm_x2(unsigned& r0, unsigned& r1, unsigned addr) {
    asm volatile("ldmatrix.sync.aligned.m8n8.x2.shared.b16 {%0,%1}, [%2];"
                 : "=r"(r0), "=r"(r1) : "r"(addr));
}
__device__ __forceinline__ void ldsm_x2t(unsigned& r0, unsigned& r1, unsigned addr) {
    asm volatile("ldmatrix.sync.aligned.m8n8.x2.trans.shared.b16 {%0,%1}, [%2];"
                 : "=r"(r0), "=r"(r1) : "r"(addr));
}

// C[M,N] = act((A[M,K] @ B[K,N] + bias) * scale). BM=128 BN=64 BK=16, 256 thr.
template <bool RELU>
__global__ __launch_bounds__(256) void gemm_tf32(
    const float* __restrict__ A, const float* __restrict__ B,
    const float* __restrict__ bias, float* __restrict__ C,
    int M, int N, int K, float scale)
{
    __shared__ unsigned As[128][20];
    __shared__ unsigned Bs[16][72];

    const int tid = threadIdx.x;
    const int warp = tid >> 5, lane = tid & 31;
    const int g = lane >> 2, tg = lane & 3;
    const int wm = (warp >> 1) << 5;
    const int wn = (warp & 1) << 5;
    const int gm0 = blockIdx.y << 7;
    const int gn0 = blockIdx.x << 6;

    const int arow = tid >> 2;
    const int ac   = (tid & 3) << 2;
    const int brow = tid >> 4;
    const int bc   = (tid & 15) << 2;

    const float* Ap = A + (long)(gm0 + arow) * K + ac;
    const float* Bp = B + (long)brow * N + gn0 + bc;

    float acc[2][4][4];
#pragma unroll
    for (int i = 0; i < 2; i++)
#pragma unroll
        for (int j = 0; j < 4; j++)
#pragma unroll
            for (int l = 0; l < 4; l++) acc[i][j][l] = 0.f;

    const int nk = K >> 4;
    float4 ra0 = *(const float4*)(Ap);
    float4 ra1 = *(const float4*)(Ap + (long)64 * K);
    float4 rb  = *(const float4*)(Bp);

    for (int kt = 0; kt < nk; kt++) {
        __syncthreads();
        As[arow][ac+0] = f2tf(ra0.x); As[arow][ac+1] = f2tf(ra0.y);
        As[arow][ac+2] = f2tf(ra0.z); As[arow][ac+3] = f2tf(ra0.w);
        As[arow+64][ac+0] = f2tf(ra1.x); As[arow+64][ac+1] = f2tf(ra1.y);
        As[arow+64][ac+2] = f2tf(ra1.z); As[arow+64][ac+3] = f2tf(ra1.w);
        Bs[brow][bc+0] = f2tf(rb.x); Bs[brow][bc+1] = f2tf(rb.y);
        Bs[brow][bc+2] = f2tf(rb.z); Bs[brow][bc+3] = f2tf(rb.w);
        __syncthreads();

        if (kt + 1 < nk) {
            ra0 = *(const float4*)(Ap + (kt + 1) * 16);
            ra1 = *(const float4*)(Ap + (long)64 * K + (kt + 1) * 16);
            rb  = *(const float4*)(Bp + (long)(kt + 1) * 16 * N);
        }

#pragma unroll
        for (int ks = 0; ks < 2; ks++) {
            const int k0 = ks << 3;
            unsigned af[2][4], bf[4][2];
#pragma unroll
            for (int mt = 0; mt < 2; mt++) {
                int r = wm + (mt << 4) + g;
                af[mt][0] = As[r][k0 + tg];
                af[mt][1] = As[r + 8][k0 + tg];
                af[mt][2] = As[r][k0 + tg + 4];
                af[mt][3] = As[r + 8][k0 + tg + 4];
            }
#pragma unroll
            for (int nt = 0; nt < 4; nt++) {
                bf[nt][0] = Bs[k0 + tg][wn + (nt << 3) + g];
                bf[nt][1] = Bs[k0 + tg + 4][wn + (nt << 3) + g];
            }
#pragma unroll
            for (int mt = 0; mt < 2; mt++)
#pragma unroll
                for (int nt = 0; nt < 4; nt++)
                    mma_tf32(acc[mt][nt], af[mt][0], af[mt][1], af[mt][2], af[mt][3],
                             bf[nt][0], bf[nt][1]);
        }
    }

#pragma unroll
    for (int mt = 0; mt < 2; mt++) {
        int row = gm0 + wm + (mt << 4) + g;
#pragma unroll
        for (int nt = 0; nt < 4; nt++) {
            int col = gn0 + wn + (nt << 3) + (tg << 1);
            float b0 = bias[col], b1 = bias[col + 1];
            float v0 = (acc[mt][nt][0] + b0) * scale;
            float v1 = (acc[mt][nt][1] + b1) * scale;
            float v2 = (acc[mt][nt][2] + b0) * scale;
            float v3 = (acc[mt][nt][3] + b1) * scale;
            if (RELU) {
                v0 = fmaxf(v0, 0.f); v1 = fmaxf(v1, 0.f);
                v2 = fmaxf(v2, 0.f); v3 = fmaxf(v3, 0.f);
            }
            *(float2*)(C + (long)row * N + col)       = make_float2(v0, v1);
            *(float2*)(C + (long)(row + 8) * N + col) = make_float2(v2, v3);
        }
    }
}

// ---------------- windowed attention, tensor-core version ----------------
// One block per (t,b,head), 256 threads (8 warps).
// smem (bytes):
//   Kb  [272][40] bf16   @ 0      (21760)   rows: m-window, cols: dhead (pad 40)
//   Vb  [272][40] bf16   @ 21760  (21760)
//   Qb  [16][40]  bf16   @ 43520  (1280)
//   Pb  [16][280] bf16   @ 44800  (8960)    logits, then exp weights
//   mask[272]     f32    @ 53760  (1088)
//   rinv[16]      f32    @ 54848  (64)
//   Rr  [8][32][4] f32   aliases Kb (4096)  PV partial fragments
#define KB_OFF   0
#define VB_OFF   21760
#define QB_OFF   43520
#define PB_OFF   44800
#define MASK_OFF 53760
#define RINV_OFF 54848
#define ATTN_SMEM_BYTES 54912

__global__ __launch_bounds__(256) void attn_kernel(
    const float* __restrict__ q, const float* __restrict__ k,
    const float* __restrict__ v, const unsigned char* __restrict__ kpm,
    float* __restrict__ ctx)
{
    extern __shared__ char smc[];
    __nv_bfloat16* Kb = (__nv_bfloat16*)(smc + KB_OFF);
    __nv_bfloat16* Vb = (__nv_bfloat16*)(smc + VB_OFF);
    __nv_bfloat16* Qb = (__nv_bfloat16*)(smc + QB_OFF);
    __nv_bfloat16* Pb = (__nv_bfloat16*)(smc + PB_OFF);
    float* maskadd = (float*)(smc + MASK_OFF);
    float* rowinv  = (float*)(smc + RINV_OFF);
    float* Rr      = (float*)(smc + KB_OFF);   // alias Kb after logits

    const unsigned sbase = (unsigned)__cvta_generic_to_shared(smc);
    const int tid = threadIdx.x;
    const int w = tid >> 5, lane = tid & 31;
    const int t = blockIdx.x, b = blockIdx.y, h = blockIdx.z;
    const long bt = (long)(b * T_FRAMES + t);

    // ---- stage K and V windows (bf16, [m][40]) ----
    for (int slot = tid; slot < 8 * MWIN; slot += 256) {
        int m = slot >> 3, k4 = slot & 7;
        int wf = m >> 4, n = m & 15;
        int f = t + wf - WINR;
        float4 kv = make_float4(0.f, 0.f, 0.f, 0.f);
        float4 vv = make_float4(0.f, 0.f, 0.f, 0.f);
        if (f >= 0 && f < T_FRAMES) {
            long base = ((long)((b * T_FRAMES + f) * NDET + n)) * HDIM + h * DHEAD + (k4 << 2);
            kv = *(const float4*)(k + base);
            vv = *(const float4*)(v + base);
        }
        __nv_bfloat162* kd = (__nv_bfloat162*)(Kb + m * 40 + (k4 << 2));
        kd[0] = __floats2bfloat162_rn(kv.x, kv.y);
        kd[1] = __floats2bfloat162_rn(kv.z, kv.w);
        __nv_bfloat162* vd = (__nv_bfloat162*)(Vb + m * 40 + (k4 << 2));
        vd[0] = __floats2bfloat162_rn(vv.x, vv.y);
        vd[1] = __floats2bfloat162_rn(vv.z, vv.w);
    }
    // ---- Q [16][40] bf16 ----
    if (tid < 128) {
        int n = tid >> 3, k4 = tid & 7;
        float4 qv = *(const float4*)(q + (bt * NDET + n) * HDIM + h * DHEAD + (k4 << 2));
        __nv_bfloat162* qd = (__nv_bfloat162*)(Qb + n * 40 + (k4 << 2));
        qd[0] = __floats2bfloat162_rn(qv.x, qv.y);
        qd[1] = __floats2bfloat162_rn(qv.z, qv.w);
    }
    // ---- mask ----
    for (int m = tid; m < MWIN; m += 256) {
        int wf = m >> 4, n = m & 15;
        int f = t + wf - WINR;
        bool ok = (f >= 0) && (f < T_FRAMES) &&
                  (kpm[(b * T_FRAMES + f) * NDET + n] == 0);
        maskadd[m] = ok ? 0.f : -1e30f;
    }
    __syncthreads();

    // ---- logits: Pb[n][m] = Q @ K^T via bf16 mma ----
    {
        // A fragments (Q 16x32, two k-steps of 16)
        unsigned qaddr = sbase + QB_OFF + (((lane & 15) * 40 + ((lane >> 4) << 3)) << 1);
        unsigned a0[4], a1[4];
        ldsm_x4(a0[0], a0[1], a0[2], a0[3], qaddr);        // k 0..15
        ldsm_x4(a1[0], a1[1], a1[2], a1[3], qaddr + 32);   // k 16..31

        const int lr = lane & 7;
        const int hg = (lane >> 3) & 1;
        for (int tw = w; tw < 34; tw += 8) {
            int m0 = tw << 3;
            float c[4] = {0.f, 0.f, 0.f, 0.f};
            unsigned baddr = sbase + KB_OFF + (((m0 + lr) * 40 + (hg << 3)) << 1);
            unsigned b0, b1, b2, b3;
            ldsm_x2(b0, b1, baddr);        // k 0..15
            ldsm_x2(b2, b3, baddr + 32);   // k 16..31
            mma_bf16(c, a0[0], a0[1], a0[2], a0[3], b0, b1);
            mma_bf16(c, a1[0], a1[1], a1[2], a1[3], b2, b3);
            int row = lane >> 2, mc = m0 + ((lane & 3) << 1);
            *(__nv_bfloat162*)(Pb + row * 280 + mc)       = __floats2bfloat162_rn(c[0], c[1]);
            *(__nv_bfloat162*)(Pb + (row + 8) * 280 + mc) = __floats2bfloat162_rn(c[2], c[3]);
        }
    }
    __syncthreads();

    // ---- masked softmax over m; Pb <- bf16(exp(x-max)), rowinv = 1/sum ----
    {
        const int n = tid >> 4, l16 = tid & 15;
        float mx = -1e30f;
        for (int m = l16; m < MWIN; m += 16) {
            float vv = __bfloat162float(Pb[n * 280 + m]) + maskadd[m];
            mx = fmaxf(mx, vv);
        }
#pragma unroll
        for (int o = 8; o; o >>= 1) mx = fmaxf(mx, __shfl_xor_sync(0xffffffffu, mx, o));
        float sum = 0.f;
        for (int m = l16; m < MWIN; m += 16) {
            float vv = __bfloat162float(Pb[n * 280 + m]) + maskadd[m];
            float e = __expf(vv - mx);
            Pb[n * 280 + m] = __float2bfloat16(e);
            sum += e;
        }
#pragma unroll
        for (int o = 8; o; o >>= 1) sum += __shfl_xor_sync(0xffffffffu, sum, o);
        if (l16 == 0) rowinv[n] = 1.0f / sum;
    }
    __syncthreads();

    // ---- PV: ctx[16][32] = Pb @ Vb via bf16 mma, k split across warp pairs ----
    {
        const int d0  = (w & 3) << 3;
        const int ks0 = (w < 4) ? 0 : 9;
        const int ks1 = (w < 4) ? 9 : 17;
        float c[4] = {0.f, 0.f, 0.f, 0.f};
        for (int ks = ks0; ks < ks1; ks++) {
            int m0 = ks << 4;
            unsigned aaddr = sbase + PB_OFF +
                ((((lane & 15) * 280) + m0 + ((lane >> 4) << 3)) << 1);
            unsigned a0, a1, a2, a3;
            ldsm_x4(a0, a1, a2, a3, aaddr);
            unsigned baddr = sbase + VB_OFF + (((m0 + (lane & 15)) * 40 + d0) << 1);
            unsigned b0, b1;
            ldsm_x2t(b0, b1, baddr);
            mma_bf16(c, a0, a1, a2, a3, b0, b1);
        }
        *(float4*)(Rr + ((w << 5) + lane) * 4) = make_float4(c[0], c[1], c[2], c[3]);
    }
    __syncthreads();

    // ---- combine warp-pair partials, normalize, store ----
    {
        const int n0 = tid >> 5, d = tid & 31;
        const int tile = d >> 3;
        const int fl = (n0 << 2) + ((d & 7) >> 1);
        const int r = d & 1;
        float v1 = Rr[((tile << 5) + fl) * 4 + r] + Rr[(((tile + 4) << 5) + fl) * 4 + r];
        float v2 = Rr[((tile << 5) + fl) * 4 + r + 2] + Rr[(((tile + 4) << 5) + fl) * 4 + r + 2];
        ctx[(bt * NDET + n0) * HDIM + h * DHEAD + d]       = v1 * rowinv[n0];
        ctx[(bt * NDET + n0 + 8) * HDIM + h * DHEAD + d]   = v2 * rowinv[n0 + 8];
    }
}

// residual add + LayerNorm; one warp per token (H=256 -> 8 floats/lane)
__global__ __launch_bounds__(256) void add_ln_kernel(
    const float* __restrict__ A, const float* __restrict__ Bv,
    const float* __restrict__ gw, const float* __restrict__ bw,
    float* __restrict__ out)
{
    const int tok  = (blockIdx.x << 3) + (threadIdx.x >> 5);
    const int lane = threadIdx.x & 31;
    const float4* a4 = (const float4*)(A  + (long)tok * HDIM);
    const float4* b4 = (const float4*)(Bv + (long)tok * HDIM);
    float4 p0 = a4[lane * 2], p1 = a4[lane * 2 + 1];
    float4 q0 = b4[lane * 2], q1 = b4[lane * 2 + 1];
    float vv[8] = { p0.x + q0.x, p0.y + q0.y, p0.z + q0.z, p0.w + q0.w,
                    p1.x + q1.x, p1.y + q1.y, p1.z + q1.z, p1.w + q1.w };
    float s = 0.f;
#pragma unroll
    for (int i = 0; i < 8; i++) s += vv[i];
#pragma unroll
    for (int o = 16; o; o >>= 1) s += __shfl_xor_sync(0xffffffffu, s, o);
    const float mean = s * (1.f / 256.f);
    float vs = 0.f;
#pragma unroll
    for (int i = 0; i < 8; i++) { float d = vv[i] - mean; vs += d * d; }
#pragma unroll
    for (int o = 16; o; o >>= 1) vs += __shfl_xor_sync(0xffffffffu, vs, o);
    const float rs = rsqrtf(vs * (1.f / 256.f) + 1e-5f);

    float4 g0 = ((const float4*)gw)[lane * 2], g1 = ((const float4*)gw)[lane * 2 + 1];
    float4 e0 = ((const float4*)bw)[lane * 2], e1 = ((const float4*)bw)[lane * 2 + 1];
    float4 o0, o1;
    o0.x = (vv[0]-mean)*rs*g0.x + e0.x;  o0.y = (vv[1]-mean)*rs*g0.y + e0.y;
    o0.z = (vv[2]-mean)*rs*g0.z + e0.z;  o0.w = (vv[3]-mean)*rs*g0.w + e0.w;
    o1.x = (vv[4]-mean)*rs*g1.x + e1.x;  o1.y = (vv[5]-mean)*rs*g1.y + e1.y;
    o1.z = (vv[6]-mean)*rs*g1.z + e1.z;  o1.w = (vv[7]-mean)*rs*g1.w + e1.w;
    float4* o4 = (float4*)(out + (long)tok * HDIM);
    o4[lane * 2]     = o0;
    o4[lane * 2 + 1] = o1;
}

extern "C" void kernel_launch(void* const* d_in, const int* in_sizes, int n_in,
                              void* d_out, int out_size)
{
    const float* x   = (const float*)d_in[0];
    const unsigned char* kpm = (const unsigned char*)d_in[1];
    const float* Wq = (const float*)d_in[2];
    const float* bq = (const float*)d_in[3];
    const float* Wk = (const float*)d_in[4];
    const float* bk = (const float*)d_in[5];
    const float* Wv = (const float*)d_in[6];
    const float* bv = (const float*)d_in[7];
    const float* W1 = (const float*)d_in[8];
    const float* b1 = (const float*)d_in[9];
    const float* W2 = (const float*)d_in[10];
    const float* b2 = (const float*)d_in[11];
    const float* g1 = (const float*)d_in[12];
    const float* be1 = (const float*)d_in[13];
    const float* g2 = (const float*)d_in[14];
    const float* be2 = (const float*)d_in[15];
    float* out = (float*)d_out;

    float *qb, *kb, *vb, *cb, *yb, *hb, *zb;
    cudaGetSymbolAddress((void**)&qb, g_q);
    cudaGetSymbolAddress((void**)&kb, g_k);
    cudaGetSymbolAddress((void**)&vb, g_v);
    cudaGetSymbolAddress((void**)&cb, g_c);
    cudaGetSymbolAddress((void**)&yb, g_y);
    cudaGetSymbolAddress((void**)&hb, g_h);
    cudaGetSymbolAddress((void**)&zb, g_z);

    cudaFuncSetAttribute(attn_kernel,
                         cudaFuncAttributeMaxDynamicSharedMemorySize, ATTN_SMEM_BYTES);

    const float qscale = 0.17677669529663687f; // 1/sqrt(32)
    dim3 blk(256);
    dim3 gProj(HDIM / 64, NTOK / 128);
    dim3 gF1(FFN / 64, NTOK / 128);
    dim3 gF2(HDIM / 64, NTOK / 128);

    gemm_tf32<false><<<gProj, blk>>>(x, Wq, bq, qb, NTOK, HDIM, HDIM, qscale);
    gemm_tf32<false><<<gProj, blk>>>(x, Wk, bk, kb, NTOK, HDIM, HDIM, 1.0f);
    gemm_tf32<false><<<gProj, blk>>>(x, Wv, bv, vb, NTOK, HDIM, HDIM, 1.0f);

    dim3 gAttn(T_FRAMES, 4, 8);
    attn_kernel<<<gAttn, blk, ATTN_SMEM_BYTES>>>(qb, kb, vb, kpm, cb);

    add_ln_kernel<<<NTOK / 8, blk>>>(x, cb, g1, be1, yb);

    gemm_tf32<true ><<<gF1, blk>>>(yb, W1, b1, hb, NTOK, FFN, HDIM, 1.0f);
    gemm_tf32<false><<<gF2, blk>>>(hb, W2, b2, zb, NTOK, HDIM, FFN, 1.0f);

    add_ln_kernel<<<NTOK / 8, blk>>>(yb, zb, g2, be2, out);
}

// round 9
// speedup vs baseline: 1.8822x; 1.1411x over previous
#include <cuda_runtime.h>
#include <cuda_bf16.h>
#include <math.h>

#define T_FRAMES 256
#define NDET     16
#define HDIM     256
#define DHEAD    32
#define WINR     8
#define MWIN     272         // (2*WINR+1)*NDET
#define NTOK     16384       // 4*256*16
#define FFN      1024

__device__ float g_q[NTOK * HDIM];   // used as bf16 (half occupied)
__device__ float g_k[NTOK * HDIM];
__device__ float g_v[NTOK * HDIM];
__device__ float g_c[NTOK * HDIM];
__device__ float g_y[NTOK * HDIM];
__device__ float g_h[NTOK * FFN];
__device__ float g_z[NTOK * HDIM];

__device__ __forceinline__ void mma_bf16(float c[4],
    unsigned a0, unsigned a1, unsigned a2, unsigned a3, unsigned b0, unsigned b1) {
    asm volatile(
        "mma.sync.aligned.m16n8k16.row.col.f32.bf16.bf16.f32 "
        "{%0,%1,%2,%3}, {%4,%5,%6,%7}, {%8,%9}, {%0,%1,%2,%3};\n"
        : "+f"(c[0]), "+f"(c[1]), "+f"(c[2]), "+f"(c[3])
        : "r"(a0), "r"(a1), "r"(a2), "r"(a3), "r"(b0), "r"(b1));
}

__device__ __forceinline__ void ldsm_x4(unsigned& r0, unsigned& r1, unsigned& r2, unsigned& r3,
                                        unsigned addr) {
    asm volatile("ldmatrix.sync.aligned.m8n8.x4.shared.b16 {%0,%1,%2,%3}, [%4];"
                 : "=r"(r0), "=r"(r1), "=r"(r2), "=r"(r3) : "r"(addr));
}
__device__ __forceinline__ void ldsm_x2(unsigned& r0, unsigned& r1, unsigned addr) {
    asm volatile("ldmatrix.sync.aligned.m8n8.x2.shared.b16 {%0,%1}, [%2];"
                 : "=r"(r0), "=r"(r1) : "r"(addr));
}
__device__ __forceinline__ void ldsm_x2t(unsigned& r0, unsigned& r1, unsigned addr) {
    asm volatile("ldmatrix.sync.aligned.m8n8.x2.trans.shared.b16 {%0,%1}, [%2];"
                 : "=r"(r0), "=r"(r1) : "r"(addr));
}

__device__ __forceinline__ void store2(float* p, float a, float b) {
    *(float2*)p = make_float2(a, b);
}
__device__ __forceinline__ void store2(__nv_bfloat16* p, float a, float b) {
    *(__nv_bfloat162*)p = __floats2bfloat162_rn(a, b);
}

// ---------------- bf16 tensor-core GEMM ----------------
// C[M,N] = act((A[M,K] @ B[K,N] + bias) * scale); A,B fp32 in gmem, bf16 in smem.
// BM=128 BN=64 BK=32, 256 threads (8 warps, 4m x 2n), warp tile 32x32.
template <bool RELU, typename OutT>
__global__ __launch_bounds__(256) void gemm_bf16(
    const float* __restrict__ A, const float* __restrict__ B,
    const float* __restrict__ bias, OutT* __restrict__ C,
    int M, int N, int K, float scale)
{
    __shared__ __nv_bfloat16 As[128][40];   // 80B rows: 5x16B chunks, coprime 8
    __shared__ __nv_bfloat16 Bs[32][72];    // 144B rows: 9 chunks, coprime 8

    const int tid = threadIdx.x;
    const int warp = tid >> 5, lane = tid & 31;
    const int wm = (warp >> 1) << 5;     // 0,32,64,96
    const int wn = (warp & 1) << 5;      // 0,32
    const int gm0 = blockIdx.y << 7;
    const int gn0 = blockIdx.x << 6;

    const int arow = tid >> 1;           // 0..127
    const int ac   = (tid & 1) << 4;     // 0,16
    const int brow = tid >> 3;           // 0..31
    const int bc   = (tid & 7) << 3;     // 0..56

    const float* Ap = A + (long)(gm0 + arow) * K + ac;
    const float* Bp = B + (long)brow * N + gn0 + bc;

    const unsigned asb = (unsigned)__cvta_generic_to_shared(&As[0][0]);
    const unsigned bsb = (unsigned)__cvta_generic_to_shared(&Bs[0][0]);
    const unsigned abase = asb + (((wm + (lane & 15)) * 40 + ((lane >> 4) << 3)) << 1);
    const unsigned bbase = bsb + ((((lane & 15)) * 72 + wn) << 1);

    float acc[2][4][4];
#pragma unroll
    for (int i = 0; i < 2; i++)
#pragma unroll
        for (int j = 0; j < 4; j++)
#pragma unroll
            for (int l = 0; l < 4; l++) acc[i][j][l] = 0.f;

    const int nk = K >> 5;
    float4 ra[4], rb[2];
#pragma unroll
    for (int i = 0; i < 4; i++) ra[i] = *(const float4*)(Ap + (i << 2));
#pragma unroll
    for (int i = 0; i < 2; i++) rb[i] = *(const float4*)(Bp + (i << 2));

    for (int kt = 0; kt < nk; kt++) {
        __syncthreads();
        {
            __nv_bfloat162 ha[8];
#pragma unroll
            for (int i = 0; i < 4; i++) {
                ha[i * 2 + 0] = __floats2bfloat162_rn(ra[i].x, ra[i].y);
                ha[i * 2 + 1] = __floats2bfloat162_rn(ra[i].z, ra[i].w);
            }
            *(uint4*)&As[arow][ac]     = *(uint4*)&ha[0];
            *(uint4*)&As[arow][ac + 8] = *(uint4*)&ha[4];
            __nv_bfloat162 hb[4];
#pragma unroll
            for (int i = 0; i < 2; i++) {
                hb[i * 2 + 0] = __floats2bfloat162_rn(rb[i].x, rb[i].y);
                hb[i * 2 + 1] = __floats2bfloat162_rn(rb[i].z, rb[i].w);
            }
            *(uint4*)&Bs[brow][bc] = *(uint4*)&hb[0];
        }
        __syncthreads();

        if (kt + 1 < nk) {
#pragma unroll
            for (int i = 0; i < 4; i++)
                ra[i] = *(const float4*)(Ap + (kt + 1) * 32 + (i << 2));
#pragma unroll
            for (int i = 0; i < 2; i++)
                rb[i] = *(const float4*)(Bp + (long)(kt + 1) * 32 * N + (i << 2));
        }

#pragma unroll
        for (int ks = 0; ks < 2; ks++) {
            unsigned af[2][4];
            ldsm_x4(af[0][0], af[0][1], af[0][2], af[0][3], abase + ks * 32);
            ldsm_x4(af[1][0], af[1][1], af[1][2], af[1][3], abase + 1280 + ks * 32);
            unsigned bf[4][2];
#pragma unroll
            for (int nt = 0; nt < 4; nt++)
                ldsm_x2t(bf[nt][0], bf[nt][1], bbase + ks * 2304 + nt * 16);
#pragma unroll
            for (int mt = 0; mt < 2; mt++)
#pragma unroll
                for (int nt = 0; nt < 4; nt++)
                    mma_bf16(acc[mt][nt], af[mt][0], af[mt][1], af[mt][2], af[mt][3],
                             bf[nt][0], bf[nt][1]);
        }
    }

#pragma unroll
    for (int mt = 0; mt < 2; mt++) {
        int row = gm0 + wm + (mt << 4) + (lane >> 2);
#pragma unroll
        for (int nt = 0; nt < 4; nt++) {
            int col = gn0 + wn + (nt << 3) + ((lane & 3) << 1);
            float b0 = bias[col], b1 = bias[col + 1];
            float v0 = (acc[mt][nt][0] + b0) * scale;
            float v1 = (acc[mt][nt][1] + b1) * scale;
            float v2 = (acc[mt][nt][2] + b0) * scale;
            float v3 = (acc[mt][nt][3] + b1) * scale;
            if (RELU) {
                v0 = fmaxf(v0, 0.f); v1 = fmaxf(v1, 0.f);
                v2 = fmaxf(v2, 0.f); v3 = fmaxf(v3, 0.f);
            }
            store2(C + (long)row * N + col, v0, v1);
            store2(C + (long)(row + 8) * N + col, v2, v3);
        }
    }
}

// ---------------- windowed attention, tensor-core, bf16 q/k/v inputs ----------------
#define KB_OFF   0
#define VB_OFF   21760
#define QB_OFF   43520
#define PB_OFF   44800
#define MASK_OFF 53760
#define RINV_OFF 54848
#define ATTN_SMEM_BYTES 54912

__global__ __launch_bounds__(256) void attn_kernel(
    const __nv_bfloat16* __restrict__ q, const __nv_bfloat16* __restrict__ k,
    const __nv_bfloat16* __restrict__ v, const unsigned char* __restrict__ kpm,
    float* __restrict__ ctx)
{
    extern __shared__ char smc[];
    __nv_bfloat16* Kb = (__nv_bfloat16*)(smc + KB_OFF);   // [272][40]
    __nv_bfloat16* Vb = (__nv_bfloat16*)(smc + VB_OFF);   // [272][40]
    __nv_bfloat16* Qb = (__nv_bfloat16*)(smc + QB_OFF);   // [16][40]
    __nv_bfloat16* Pb = (__nv_bfloat16*)(smc + PB_OFF);   // [16][280]
    float* maskadd = (float*)(smc + MASK_OFF);
    float* rowinv  = (float*)(smc + RINV_OFF);
    float* Rr      = (float*)(smc + KB_OFF);   // alias Kb after logits

    const unsigned sbase = (unsigned)__cvta_generic_to_shared(smc);
    const int tid = threadIdx.x;
    const int w = tid >> 5, lane = tid & 31;
    const int t = blockIdx.x, b = blockIdx.y, h = blockIdx.z;
    const long bt = (long)(b * T_FRAMES + t);

    // ---- stage K,V windows: pure 16B copies (bf16 in gmem already) ----
    for (int slot = tid; slot < 4 * MWIN; slot += 256) {
        int m = slot >> 2, k8 = slot & 3;
        int wf = m >> 4, n = m & 15;
        int f = t + wf - WINR;
        uint4 kv = make_uint4(0, 0, 0, 0), vv = make_uint4(0, 0, 0, 0);
        if (f >= 0 && f < T_FRAMES) {
            long base = ((long)((b * T_FRAMES + f) * NDET + n)) * HDIM + h * DHEAD + (k8 << 3);
            kv = *(const uint4*)(k + base);
            vv = *(const uint4*)(v + base);
        }
        *(uint4*)(Kb + m * 40 + (k8 << 3)) = kv;
        *(uint4*)(Vb + m * 40 + (k8 << 3)) = vv;
    }
    if (tid < 64) {
        int n = tid >> 2, k8 = tid & 3;
        *(uint4*)(Qb + n * 40 + (k8 << 3)) =
            *(const uint4*)(q + (bt * NDET + n) * HDIM + h * DHEAD + (k8 << 3));
    }
    for (int m = tid; m < MWIN; m += 256) {
        int wf = m >> 4, n = m & 15;
        int f = t + wf - WINR;
        bool ok = (f >= 0) && (f < T_FRAMES) &&
                  (kpm[(b * T_FRAMES + f) * NDET + n] == 0);
        maskadd[m] = ok ? 0.f : -1e30f;
    }
    __syncthreads();

    // ---- logits: Pb[n][m] = Q @ K^T ----
    {
        unsigned qaddr = sbase + QB_OFF + (((lane & 15) * 40 + ((lane >> 4) << 3)) << 1);
        unsigned a0[4], a1[4];
        ldsm_x4(a0[0], a0[1], a0[2], a0[3], qaddr);
        ldsm_x4(a1[0], a1[1], a1[2], a1[3], qaddr + 32);

        const int lr = lane & 7;
        const int hg = (lane >> 3) & 1;
        for (int tw = w; tw < 34; tw += 8) {
            int m0 = tw << 3;
            float c[4] = {0.f, 0.f, 0.f, 0.f};
            unsigned baddr = sbase + KB_OFF + (((m0 + lr) * 40 + (hg << 3)) << 1);
            unsigned b0, b1, b2, b3;
            ldsm_x2(b0, b1, baddr);
            ldsm_x2(b2, b3, baddr + 32);
            mma_bf16(c, a0[0], a0[1], a0[2], a0[3], b0, b1);
            mma_bf16(c, a1[0], a1[1], a1[2], a1[3], b2, b3);
            int row = lane >> 2, mc = m0 + ((lane & 3) << 1);
            *(__nv_bfloat162*)(Pb + row * 280 + mc)       = __floats2bfloat162_rn(c[0], c[1]);
            *(__nv_bfloat162*)(Pb + (row + 8) * 280 + mc) = __floats2bfloat162_rn(c[2], c[3]);
        }
    }
    __syncthreads();

    // ---- masked softmax; Pb <- bf16(exp(x-max)), rowinv = 1/sum ----
    {
        const int n = tid >> 4, l16 = tid & 15;
        float mx = -1e30f;
        for (int m = l16; m < MWIN; m += 16) {
            float vv = __bfloat162float(Pb[n * 280 + m]) + maskadd[m];
            mx = fmaxf(mx, vv);
        }
#pragma unroll
        for (int o = 8; o; o >>= 1) mx = fmaxf(mx, __shfl_xor_sync(0xffffffffu, mx, o));
        float sum = 0.f;
        for (int m = l16; m < MWIN; m += 16) {
            float vv = __bfloat162float(Pb[n * 280 + m]) + maskadd[m];
            float e = __expf(vv - mx);
            Pb[n * 280 + m] = __float2bfloat16(e);
            sum += e;
        }
#pragma unroll
        for (int o = 8; o; o >>= 1) sum += __shfl_xor_sync(0xffffffffu, sum, o);
        if (l16 == 0) rowinv[n] = 1.0f / sum;
    }
    __syncthreads();

    // ---- PV: ctx[16][32] = Pb @ Vb, k-split across warp pairs ----
    {
        const int d0  = (w & 3) << 3;
        const int ks0 = (w < 4) ? 0 : 9;
        const int ks1 = (w < 4) ? 9 : 17;
        float c[4] = {0.f, 0.f, 0.f, 0.f};
        for (int ks = ks0; ks < ks1; ks++) {
            int m0 = ks << 4;
            unsigned aaddr = sbase + PB_OFF +
                ((((lane & 15) * 280) + m0 + ((lane >> 4) << 3)) << 1);
            unsigned a0, a1, a2, a3;
            ldsm_x4(a0, a1, a2, a3, aaddr);
            unsigned baddr = sbase + VB_OFF + (((m0 + (lane & 15)) * 40 + d0) << 1);
            unsigned b0, b1;
            ldsm_x2t(b0, b1, baddr);
            mma_bf16(c, a0, a1, a2, a3, b0, b1);
        }
        *(float4*)(Rr + ((w << 5) + lane) * 4) = make_float4(c[0], c[1], c[2], c[3]);
    }
    __syncthreads();

    {
        const int n0 = tid >> 5, d = tid & 31;
        const int tile = d >> 3;
        const int fl = (n0 << 2) + ((d & 7) >> 1);
        const int r = d & 1;
        float v1 = Rr[((tile << 5) + fl) * 4 + r] + Rr[(((tile + 4) << 5) + fl) * 4 + r];
        float v2 = Rr[((tile << 5) + fl) * 4 + r + 2] + Rr[(((tile + 4) << 5) + fl) * 4 + r + 2];
        ctx[(bt * NDET + n0) * HDIM + h * DHEAD + d]     = v1 * rowinv[n0];
        ctx[(bt * NDET + n0 + 8) * HDIM + h * DHEAD + d] = v2 * rowinv[n0 + 8];
    }
}

// residual add + LayerNorm; one warp per token
__global__ __launch_bounds__(256) void add_ln_kernel(
    const float* __restrict__ A, const float* __restrict__ Bv,
    const float* __restrict__ gw, const float* __restrict__ bw,
    float* __restrict__ out)
{
    const int tok  = (blockIdx.x << 3) + (threadIdx.x >> 5);
    const int lane = threadIdx.x & 31;
    const float4* a4 = (const float4*)(A  + (long)tok * HDIM);
    const float4* b4 = (const float4*)(Bv + (long)tok * HDIM);
    float4 p0 = a4[lane * 2], p1 = a4[lane * 2 + 1];
    float4 q0 = b4[lane * 2], q1 = b4[lane * 2 + 1];
    float vv[8] = { p0.x + q0.x, p0.y + q0.y, p0.z + q0.z, p0.w + q0.w,
                    p1.x + q1.x, p1.y + q1.y, p1.z + q1.z, p1.w + q1.w };
    float s = 0.f;
#pragma unroll
    for (int i = 0; i < 8; i++) s += vv[i];
#pragma unroll
    for (int o = 16; o; o >>= 1) s += __shfl_xor_sync(0xffffffffu, s, o);
    const float mean = s * (1.f / 256.f);
    float vs = 0.f;
#pragma unroll
    for (int i = 0; i < 8; i++) { float d = vv[i] - mean; vs += d * d; }
#pragma unroll
    for (int o = 16; o; o >>= 1) vs += __shfl_xor_sync(0xffffffffu, vs, o);
    const float rs = rsqrtf(vs * (1.f / 256.f) + 1e-5f);

    float4 g0 = ((const float4*)gw)[lane * 2], g1 = ((const float4*)gw)[lane * 2 + 1];
    float4 e0 = ((const float4*)bw)[lane * 2], e1 = ((const float4*)bw)[lane * 2 + 1];
    float4 o0, o1;
    o0.x = (vv[0]-mean)*rs*g0.x + e0.x;  o0.y = (vv[1]-mean)*rs*g0.y + e0.y;
    o0.z = (vv[2]-mean)*rs*g0.z + e0.z;  o0.w = (vv[3]-mean)*rs*g0.w + e0.w;
    o1.x = (vv[4]-mean)*rs*g1.x + e1.x;  o1.y = (vv[5]-mean)*rs*g1.y + e1.y;
    o1.z = (vv[6]-mean)*rs*g1.z + e1.z;  o1.w = (vv[7]-mean)*rs*g1.w + e1.w;
    float4* o4 = (float4*)(out + (long)tok * HDIM);
    o4[lane * 2]     = o0;
    o4[lane * 2 + 1] = o1;
}

extern "C" void kernel_launch(void* const* d_in, const int* in_sizes, int n_in,
                              void* d_out, int out_size)
{
    const float* x   = (const float*)d_in[0];
    const unsigned char* kpm = (const unsigned char*)d_in[1];
    const float* Wq = (const float*)d_in[2];
    const float* bq = (const float*)d_in[3];
    const float* Wk = (const float*)d_in[4];
    const float* bk = (const float*)d_in[5];
    const float* Wv = (const float*)d_in[6];
    const float* bv = (const float*)d_in[7];
    const float* W1 = (const float*)d_in[8];
    const float* b1 = (const float*)d_in[9];
    const float* W2 = (const float*)d_in[10];
    const float* b2 = (const float*)d_in[11];
    const float* g1 = (const float*)d_in[12];
    const float* be1 = (const float*)d_in[13];
    const float* g2 = (const float*)d_in[14];
    const float* be2 = (const float*)d_in[15];
    float* out = (float*)d_out;

    float *qf, *kf, *vf, *cb, *yb, *hb, *zb;
    cudaGetSymbolAddress((void**)&qf, g_q);
    cudaGetSymbolAddress((void**)&kf, g_k);
    cudaGetSymbolAddress((void**)&vf, g_v);
    cudaGetSymbolAddress((void**)&cb, g_c);
    cudaGetSymbolAddress((void**)&yb, g_y);
    cudaGetSymbolAddress((void**)&hb, g_h);
    cudaGetSymbolAddress((void**)&zb, g_z);
    __nv_bfloat16* qb = (__nv_bfloat16*)qf;
    __nv_bfloat16* kb = (__nv_bfloat16*)kf;
    __nv_bfloat16* vb = (__nv_bfloat16*)vf;

    cudaFuncSetAttribute(attn_kernel,
                         cudaFuncAttributeMaxDynamicSharedMemorySize, ATTN_SMEM_BYTES);

    const float qscale = 0.17677669529663687f; // 1/sqrt(32)
    dim3 blk(256);
    dim3 gProj(HDIM / 64, NTOK / 128);
    dim3 gF1(FFN / 64, NTOK / 128);
    dim3 gF2(HDIM / 64, NTOK / 128);

    gemm_bf16<false, __nv_bfloat16><<<gProj, blk>>>(x, Wq, bq, qb, NTOK, HDIM, HDIM, qscale);
    gemm_bf16<false, __nv_bfloat16><<<gProj, blk>>>(x, Wk, bk, kb, NTOK, HDIM, HDIM, 1.0f);
    gemm_bf16<false, __nv_bfloat16><<<gProj, blk>>>(x, Wv, bv, vb, NTOK, HDIM, HDIM, 1.0f);

    dim3 gAttn(T_FRAMES, 4, 8);
    attn_kernel<<<gAttn, blk, ATTN_SMEM_BYTES>>>(qb, kb, vb, kpm, cb);

    add_ln_kernel<<<NTOK / 8, blk>>>(x, cb, g1, be1, yb);

    gemm_bf16<true,  float><<<gF1, blk>>>(yb, W1, b1, hb, NTOK, FFN, HDIM, 1.0f);
    gemm_bf16<false, float><<<gF2, blk>>>(hb, W2, b2, zb, NTOK, HDIM, FFN, 1.0f);

    add_ln_kernel<<<NTOK / 8, blk>>>(yb, zb, g2, be2, out);
}

// round 10
// speedup vs baseline: 2.5161x; 1.3368x over previous
#include <cuda_runtime.h>
#include <cuda_bf16.h>
#include <math.h>

#define T_FRAMES 256
#define NDET     16
#define HDIM     256
#define DHEAD    32
#define WINR     8
#define MWIN     272         // (2*WINR+1)*NDET
#define NTOK     16384       // 4*256*16
#define FFN      1024

// fp32 scratch
__device__ float g_c[NTOK * HDIM];
__device__ float g_y[NTOK * HDIM];
__device__ float g_z[NTOK * HDIM];
// bf16 scratch
__device__ __nv_bfloat16 g_xb[NTOK * HDIM];
__device__ __nv_bfloat16 g_qb[NTOK * HDIM];
__device__ __nv_bfloat16 g_kb[NTOK * HDIM];
__device__ __nv_bfloat16 g_vb[NTOK * HDIM];
__device__ __nv_bfloat16 g_y16[NTOK * HDIM];
__device__ __nv_bfloat16 g_h16[NTOK * FFN];
__device__ __nv_bfloat16 g_wq[HDIM * HDIM];
__device__ __nv_bfloat16 g_wk[HDIM * HDIM];
__device__ __nv_bfloat16 g_wv[HDIM * HDIM];
__device__ __nv_bfloat16 g_w1[HDIM * FFN];
__device__ __nv_bfloat16 g_w2[FFN * HDIM];

__device__ __forceinline__ void mma_bf16(float c[4],
    unsigned a0, unsigned a1, unsigned a2, unsigned a3, unsigned b0, unsigned b1) {
    asm volatile(
        "mma.sync.aligned.m16n8k16.row.col.f32.bf16.bf16.f32 "
        "{%0,%1,%2,%3}, {%4,%5,%6,%7}, {%8,%9}, {%0,%1,%2,%3};\n"
        : "+f"(c[0]), "+f"(c[1]), "+f"(c[2]), "+f"(c[3])
        : "r"(a0), "r"(a1), "r"(a2), "r"(a3), "r"(b0), "r"(b1));
}
__device__ __forceinline__ void ldsm_x4(unsigned& r0, unsigned& r1, unsigned& r2, unsigned& r3,
                                        unsigned addr) {
    asm volatile("ldmatrix.sync.aligned.m8n8.x4.shared.b16 {%0,%1,%2,%3}, [%4];"
                 : "=r"(r0), "=r"(r1), "=r"(r2), "=r"(r3) : "r"(addr));
}
__device__ __forceinline__ void ldsm_x2(unsigned& r0, unsigned& r1, unsigned addr) {
    asm volatile("ldmatrix.sync.aligned.m8n8.x2.shared.b16 {%0,%1}, [%2];"
                 : "=r"(r0), "=r"(r1) : "r"(addr));
}
__device__ __forceinline__ void ldsm_x2t(unsigned& r0, unsigned& r1, unsigned addr) {
    asm volatile("ldmatrix.sync.aligned.m8n8.x2.trans.shared.b16 {%0,%1}, [%2];"
                 : "=r"(r0), "=r"(r1) : "r"(addr));
}
__device__ __forceinline__ void cp16(unsigned saddr, const void* gaddr) {
    asm volatile("cp.async.cg.shared.global [%0], [%1], 16;\n"
                 :: "r"(saddr), "l"(gaddr));
}
#define CP_COMMIT() asm volatile("cp.async.commit_group;\n" ::: "memory")
#define CP_WAIT1()  asm volatile("cp.async.wait_group 1;\n" ::: "memory")
#define CP_WAIT0()  asm volatile("cp.async.wait_group 0;\n" ::: "memory")

__device__ __forceinline__ void store2(float* p, float a, float b) {
    *(float2*)p = make_float2(a, b);
}
__device__ __forceinline__ void store2(__nv_bfloat16* p, float a, float b) {
    *(__nv_bfloat162*)p = __floats2bfloat162_rn(a, b);
}

// ---- fp32 -> bf16 conversion: up to 3 tensors via blockIdx.y ----
__global__ __launch_bounds__(256) void cvt3_kernel(
    const float* __restrict__ a, const float* __restrict__ b, const float* __restrict__ c,
    __nv_bfloat16* oa, __nv_bfloat16* ob, __nv_bfloat16* oc, int n)
{
    const float* src = (blockIdx.y == 0) ? a : (blockIdx.y == 1) ? b : c;
    __nv_bfloat16* dst = (blockIdx.y == 0) ? oa : (blockIdx.y == 1) ? ob : oc;
    int i = (blockIdx.x * 256 + threadIdx.x) << 2;
    if (i < n) {
        float4 v = *(const float4*)(src + i);
        __nv_bfloat162 h0 = __floats2bfloat162_rn(v.x, v.y);
        __nv_bfloat162 h1 = __floats2bfloat162_rn(v.z, v.w);
        *(__nv_bfloat162*)(dst + i)     = h0;
        *(__nv_bfloat162*)(dst + i + 2) = h1;
    }
}

// ---------------- bf16 tensor-core GEMM, cp.async double-buffered ----------------
// C[M,N] = act((A[M,K] @ B[K,N] + bias) * scale); A,B bf16 in gmem.
// BM=128 BN=64 BK=32, 256 threads (8 warps, 4m x 2n), warp tile 32x32.
template <bool RELU, typename OutT>
__global__ __launch_bounds__(256) void gemm_cp(
    const __nv_bfloat16* __restrict__ A, const __nv_bfloat16* __restrict__ B,
    const float* __restrict__ bias, OutT* __restrict__ C,
    int M, int N, int K, float scale)
{
    __shared__ __nv_bfloat16 As[2][128][40];   // 80B rows, conflict-free ldsm
    __shared__ __nv_bfloat16 Bs[2][32][72];    // 144B rows

    const int tid = threadIdx.x;
    const int warp = tid >> 5, lane = tid & 31;
    const int wm = (warp >> 1) << 5;
    const int wn = (warp & 1) << 5;
    const int gm0 = blockIdx.y << 7;
    const int gn0 = blockIdx.x << 6;

    // cp.async mapping
    const int arow = tid >> 1;               // 0..127
    const int ac16a = (tid & 1) << 1;        // chunk pair start: 0 or 2 (of 4 chunks)
    const int brow = tid >> 3;               // 0..31
    const int bc16 = tid & 7;                // 0..7

    const unsigned asb = (unsigned)__cvta_generic_to_shared(&As[0][0][0]);
    const unsigned bsb = (unsigned)__cvta_generic_to_shared(&Bs[0][0][0]);
    const unsigned a_sdst = asb + ((arow * 40 + (ac16a << 3)) << 1);
    const unsigned b_sdst = bsb + ((brow * 72 + (bc16 << 3)) << 1);
    const __nv_bfloat16* a_gsrc = A + (long)(gm0 + arow) * K + (ac16a << 3);
    const __nv_bfloat16* b_gsrc = B + (long)brow * N + gn0 + (bc16 << 3);

    // ldmatrix bases (stage 0)
    const unsigned abase = asb + (((wm + (lane & 15)) * 40 + ((lane >> 4) << 3)) << 1);
    const unsigned bbase = bsb + (((lane & 15) * 72 + wn) << 1);

    float acc[2][4][4];
#pragma unroll
    for (int i = 0; i < 2; i++)
#pragma unroll
        for (int j = 0; j < 4; j++)
#pragma unroll
            for (int l = 0; l < 4; l++) acc[i][j][l] = 0.f;

    const int nk = K >> 5;

    // prologue: stage 0 loads
    cp16(a_sdst,      a_gsrc);
    cp16(a_sdst + 16, a_gsrc + 8);
    cp16(b_sdst,      b_gsrc);
    CP_COMMIT();

    for (int kt = 0; kt < nk; kt++) {
        const int s = kt & 1;
        if (kt + 1 < nk) {
            const int s1 = (kt + 1) & 1;
            const __nv_bfloat16* ag = a_gsrc + (kt + 1) * 32;
            const __nv_bfloat16* bg = b_gsrc + (long)(kt + 1) * 32 * N;
            cp16(a_sdst + s1 * 10240,      ag);
            cp16(a_sdst + s1 * 10240 + 16, ag + 8);
            cp16(b_sdst + s1 * 4608,       bg);
            CP_COMMIT();
            CP_WAIT1();
        } else {
            CP_WAIT0();
        }
        __syncthreads();

        const unsigned ab = abase + s * 10240;
        const unsigned bb = bbase + s * 4608;
#pragma unroll
        for (int ks = 0; ks < 2; ks++) {
            unsigned af[2][4];
            ldsm_x4(af[0][0], af[0][1], af[0][2], af[0][3], ab + ks * 32);
            ldsm_x4(af[1][0], af[1][1], af[1][2], af[1][3], ab + 1280 + ks * 32);
            unsigned bf[4][2];
#pragma unroll
            for (int nt = 0; nt < 4; nt++)
                ldsm_x2t(bf[nt][0], bf[nt][1], bb + ks * 2304 + nt * 16);
#pragma unroll
            for (int mt = 0; mt < 2; mt++)
#pragma unroll
                for (int nt = 0; nt < 4; nt++)
                    mma_bf16(acc[mt][nt], af[mt][0], af[mt][1], af[mt][2], af[mt][3],
                             bf[nt][0], bf[nt][1]);
        }
        __syncthreads();
    }

#pragma unroll
    for (int mt = 0; mt < 2; mt++) {
        int row = gm0 + wm + (mt << 4) + (lane >> 2);
#pragma unroll
        for (int nt = 0; nt < 4; nt++) {
            int col = gn0 + wn + (nt << 3) + ((lane & 3) << 1);
            float b0 = bias[col], b1 = bias[col + 1];
            float v0 = (acc[mt][nt][0] + b0) * scale;
            float v1 = (acc[mt][nt][1] + b1) * scale;
            float v2 = (acc[mt][nt][2] + b0) * scale;
            float v3 = (acc[mt][nt][3] + b1) * scale;
            if (RELU) {
                v0 = fmaxf(v0, 0.f); v1 = fmaxf(v1, 0.f);
                v2 = fmaxf(v2, 0.f); v3 = fmaxf(v3, 0.f);
            }
            store2(C + (long)row * N + col, v0, v1);
            store2(C + (long)(row + 8) * N + col, v2, v3);
        }
    }
}

// ---------------- windowed attention, tensor-core, bf16 q/k/v ----------------
#define KB_OFF   0
#define VB_OFF   21760
#define QB_OFF   43520
#define PB_OFF   44800
#define MASK_OFF 53760
#define RINV_OFF 54848
#define ATTN_SMEM_BYTES 54912

__global__ __launch_bounds__(256) void attn_kernel(
    const __nv_bfloat16* __restrict__ q, const __nv_bfloat16* __restrict__ k,
    const __nv_bfloat16* __restrict__ v, const unsigned char* __restrict__ kpm,
    float* __restrict__ ctx)
{
    extern __shared__ char smc[];
    __nv_bfloat16* Kb = (__nv_bfloat16*)(smc + KB_OFF);   // [272][40]
    __nv_bfloat16* Vb = (__nv_bfloat16*)(smc + VB_OFF);   // [272][40]
    __nv_bfloat16* Qb = (__nv_bfloat16*)(smc + QB_OFF);   // [16][40]
    __nv_bfloat16* Pb = (__nv_bfloat16*)(smc + PB_OFF);   // [16][280]
    float* maskadd = (float*)(smc + MASK_OFF);
    float* rowinv  = (float*)(smc + RINV_OFF);
    float* Rr      = (float*)(smc + KB_OFF);   // alias Kb after logits

    const unsigned sbase = (unsigned)__cvta_generic_to_shared(smc);
    const int tid = threadIdx.x;
    const int w = tid >> 5, lane = tid & 31;
    const int t = blockIdx.x, b = blockIdx.y, h = blockIdx.z;
    const long bt = (long)(b * T_FRAMES + t);

    // ---- stage K,V windows (16B copies) ----
    for (int slot = tid; slot < 4 * MWIN; slot += 256) {
        int m = slot >> 2, k8 = slot & 3;
        int wf = m >> 4, n = m & 15;
        int f = t + wf - WINR;
        uint4 kv = make_uint4(0, 0, 0, 0), vv = make_uint4(0, 0, 0, 0);
        if (f >= 0 && f < T_FRAMES) {
            long base = ((long)((b * T_FRAMES + f) * NDET + n)) * HDIM + h * DHEAD + (k8 << 3);
            kv = *(const uint4*)(k + base);
            vv = *(const uint4*)(v + base);
        }
        *(uint4*)(Kb + m * 40 + (k8 << 3)) = kv;
        *(uint4*)(Vb + m * 40 + (k8 << 3)) = vv;
    }
    if (tid < 64) {
        int n = tid >> 2, k8 = tid & 3;
        *(uint4*)(Qb + n * 40 + (k8 << 3)) =
            *(const uint4*)(q + (bt * NDET + n) * HDIM + h * DHEAD + (k8 << 3));
    }
    for (int m = tid; m < MWIN; m += 256) {
        int wf = m >> 4, n = m & 15;
        int f = t + wf - WINR;
        bool ok = (f >= 0) && (f < T_FRAMES) &&
                  (kpm[(b * T_FRAMES + f) * NDET + n] == 0);
        maskadd[m] = ok ? 0.f : -1e30f;
    }
    __syncthreads();

    // ---- logits: Pb[n][m] = Q @ K^T ----
    {
        unsigned qaddr = sbase + QB_OFF + (((lane & 15) * 40 + ((lane >> 4) << 3)) << 1);
        unsigned a0[4], a1[4];
        ldsm_x4(a0[0], a0[1], a0[2], a0[3], qaddr);
        ldsm_x4(a1[0], a1[1], a1[2], a1[3], qaddr + 32);

        const int lr = lane & 7;
        const int hg = (lane >> 3) & 1;
        for (int tw = w; tw < 34; tw += 8) {
            int m0 = tw << 3;
            float c[4] = {0.f, 0.f, 0.f, 0.f};
            unsigned baddr = sbase + KB_OFF + (((m0 + lr) * 40 + (hg << 3)) << 1);
            unsigned b0, b1, b2, b3;
            ldsm_x2(b0, b1, baddr);
            ldsm_x2(b2, b3, baddr + 32);
            mma_bf16(c, a0[0], a0[1], a0[2], a0[3], b0, b1);
            mma_bf16(c, a1[0], a1[1], a1[2], a1[3], b2, b3);
            int row = lane >> 2, mc = m0 + ((lane & 3) << 1);
            *(__nv_bfloat162*)(Pb + row * 280 + mc)       = __floats2bfloat162_rn(c[0], c[1]);
            *(__nv_bfloat162*)(Pb + (row + 8) * 280 + mc) = __floats2bfloat162_rn(c[2], c[3]);
        }
    }
    __syncthreads();

    // ---- masked softmax (paired bf16x2 traffic) ----
    {
        const int n = tid >> 4, l16 = tid & 15;
        float mx = -1e30f;
        for (int m2 = l16; m2 < 136; m2 += 16) {
            float2 p = __bfloat1622float2(*(__nv_bfloat162*)(Pb + n * 280 + (m2 << 1)));
            float2 ma = *(float2*)(maskadd + (m2 << 1));
            mx = fmaxf(mx, fmaxf(p.x + ma.x, p.y + ma.y));
        }
#pragma unroll
        for (int o = 8; o; o >>= 1) mx = fmaxf(mx, __shfl_xor_sync(0xffffffffu, mx, o));
        float sum = 0.f;
        for (int m2 = l16; m2 < 136; m2 += 16) {
            float2 p = __bfloat1622float2(*(__nv_bfloat162*)(Pb + n * 280 + (m2 << 1)));
            float2 ma = *(float2*)(maskadd + (m2 << 1));
            float e0 = __expf(p.x + ma.x - mx);
            float e1 = __expf(p.y + ma.y - mx);
            *(__nv_bfloat162*)(Pb + n * 280 + (m2 << 1)) = __floats2bfloat162_rn(e0, e1);
            sum += e0 + e1;
        }
#pragma unroll
        for (int o = 8; o; o >>= 1) sum += __shfl_xor_sync(0xffffffffu, sum, o);
        if (l16 == 0) rowinv[n] = 1.0f / sum;
    }
    __syncthreads();

    // ---- PV: ctx[16][32] = Pb @ Vb, k-split across warp pairs ----
    {
        const int d0  = (w & 3) << 3;
        const int ks0 = (w < 4) ? 0 : 9;
        const int ks1 = (w < 4) ? 9 : 17;
        float c[4] = {0.f, 0.f, 0.f, 0.f};
        for (int ks = ks0; ks < ks1; ks++) {
            int m0 = ks << 4;
            unsigned aaddr = sbase + PB_OFF +
                ((((lane & 15) * 280) + m0 + ((lane >> 4) << 3)) << 1);
            unsigned a0, a1, a2, a3;
            ldsm_x4(a0, a1, a2, a3, aaddr);
            unsigned baddr = sbase + VB_OFF + (((m0 + (lane & 15)) * 40 + d0) << 1);
            unsigned b0, b1;
            ldsm_x2t(b0, b1, baddr);
            mma_bf16(c, a0, a1, a2, a3, b0, b1);
        }
        *(float4*)(Rr + ((w << 5) + lane) * 4) = make_float4(c[0], c[1], c[2], c[3]);
    }
    __syncthreads();

    {
        const int n0 = tid >> 5, d = tid & 31;
        const int tile = d >> 3;
        const int fl = (n0 << 2) + ((d & 7) >> 1);
        const int r = d & 1;
        float v1 = Rr[((tile << 5) + fl) * 4 + r] + Rr[(((tile + 4) << 5) + fl) * 4 + r];
        float v2 = Rr[((tile << 5) + fl) * 4 + r + 2] + Rr[(((tile + 4) << 5) + fl) * 4 + r + 2];
        ctx[(bt * NDET + n0) * HDIM + h * DHEAD + d]     = v1 * rowinv[n0];
        ctx[(bt * NDET + n0 + 8) * HDIM + h * DHEAD + d] = v2 * rowinv[n0 + 8];
    }
}

// residual add + LayerNorm; optional fused bf16 copy of the output
template <bool DUAL>
__global__ __launch_bounds__(256) void add_ln_kernel(
    const float* __restrict__ A, const float* __restrict__ Bv,
    const float* __restrict__ gw, const float* __restrict__ bw,
    float* __restrict__ out, __nv_bfloat16* __restrict__ out16)
{
    const int tok  = (blockIdx.x << 3) + (threadIdx.x >> 5);
    const int lane = threadIdx.x & 31;
    const float4* a4 = (const float4*)(A  + (long)tok * HDIM);
    const float4* b4 = (const float4*)(Bv + (long)tok * HDIM);
    float4 p0 = a4[lane * 2], p1 = a4[lane * 2 + 1];
    float4 q0 = b4[lane * 2], q1 = b4[lane * 2 + 1];
    float vv[8] = { p0.x + q0.x, p0.y + q0.y, p0.z + q0.z, p0.w + q0.w,
                    p1.x + q1.x, p1.y + q1.y, p1.z + q1.z, p1.w + q1.w };
    float s = 0.f;
#pragma unroll
    for (int i = 0; i < 8; i++) s += vv[i];
#pragma unroll
    for (int o = 16; o; o >>= 1) s += __shfl_xor_sync(0xffffffffu, s, o);
    const float mean = s * (1.f / 256.f);
    float vs = 0.f;
#pragma unroll
    for (int i = 0; i < 8; i++) { float d = vv[i] - mean; vs += d * d; }
#pragma unroll
    for (int o = 16; o; o >>= 1) vs += __shfl_xor_sync(0xffffffffu, vs, o);
    const float rs = rsqrtf(vs * (1.f / 256.f) + 1e-5f);

    float4 g0 = ((const float4*)gw)[lane * 2], g1 = ((const float4*)gw)[lane * 2 + 1];
    float4 e0 = ((const float4*)bw)[lane * 2], e1 = ((const float4*)bw)[lane * 2 + 1];
    float r[8];
    r[0] = (vv[0]-mean)*rs*g0.x + e0.x;  r[1] = (vv[1]-mean)*rs*g0.y + e0.y;
    r[2] = (vv[2]-mean)*rs*g0.z + e0.z;  r[3] = (vv[3]-mean)*rs*g0.w + e0.w;
    r[4] = (vv[4]-mean)*rs*g1.x + e1.x;  r[5] = (vv[5]-mean)*rs*g1.y + e1.y;
    r[6] = (vv[6]-mean)*rs*g1.z + e1.z;  r[7] = (vv[7]-mean)*rs*g1.w + e1.w;
    float4* o4 = (float4*)(out + (long)tok * HDIM);
    o4[lane * 2]     = make_float4(r[0], r[1], r[2], r[3]);
    o4[lane * 2 + 1] = make_float4(r[4], r[5], r[6], r[7]);
    if (DUAL) {
        __nv_bfloat16* ob = out16 + (long)tok * HDIM + lane * 8;
        __nv_bfloat162 h[4];
        h[0] = __floats2bfloat162_rn(r[0], r[1]);
        h[1] = __floats2bfloat162_rn(r[2], r[3]);
        h[2] = __floats2bfloat162_rn(r[4], r[5]);
        h[3] = __floats2bfloat162_rn(r[6], r[7]);
        *(uint4*)ob = *(uint4*)&h[0];
    }
}

extern "C" void kernel_launch(void* const* d_in, const int* in_sizes, int n_in,
                              void* d_out, int out_size)
{
    const float* x   = (const float*)d_in[0];
    const unsigned char* kpm = (const unsigned char*)d_in[1];
    const float* Wq = (const float*)d_in[2];
    const float* bq = (const float*)d_in[3];
    const float* Wk = (const float*)d_in[4];
    const float* bk = (const float*)d_in[5];
    const float* Wv = (const float*)d_in[6];
    const float* bv = (const float*)d_in[7];
    const float* W1 = (const float*)d_in[8];
    const float* b1 = (const float*)d_in[9];
    const float* W2 = (const float*)d_in[10];
    const float* b2 = (const float*)d_in[11];
    const float* g1 = (const float*)d_in[12];
    const float* be1 = (const float*)d_in[13];
    const float* g2 = (const float*)d_in[14];
    const float* be2 = (const float*)d_in[15];
    float* out = (float*)d_out;

    float *cb, *yb, *zb;
    __nv_bfloat16 *xb, *qb, *kb, *vb, *y16, *h16, *wqb, *wkb, *wvb, *w1b, *w2b;
    cudaGetSymbolAddress((void**)&cb, g_c);
    cudaGetSymbolAddress((void**)&yb, g_y);
    cudaGetSymbolAddress((void**)&zb, g_z);
    cudaGetSymbolAddress((void**)&xb, g_xb);
    cudaGetSymbolAddress((void**)&qb, g_qb);
    cudaGetSymbolAddress((void**)&kb, g_kb);
    cudaGetSymbolAddress((void**)&vb, g_vb);
    cudaGetSymbolAddress((void**)&y16, g_y16);
    cudaGetSymbolAddress((void**)&h16, g_h16);
    cudaGetSymbolAddress((void**)&wqb, g_wq);
    cudaGetSymbolAddress((void**)&wkb, g_wk);
    cudaGetSymbolAddress((void**)&wvb, g_wv);
    cudaGetSymbolAddress((void**)&w1b, g_w1);
    cudaGetSymbolAddress((void**)&w2b, g_w2);

    cudaFuncSetAttribute(attn_kernel,
                         cudaFuncAttributeMaxDynamicSharedMemorySize, ATTN_SMEM_BYTES);

    const float qscale = 0.17677669529663687f; // 1/sqrt(32)
    dim3 blk(256);

    // conversions
    cvt3_kernel<<<dim3(NTOK * HDIM / 1024, 1), blk>>>(x, x, x, xb, xb, xb, NTOK * HDIM);
    cvt3_kernel<<<dim3(HDIM * HDIM / 1024, 3), blk>>>(Wq, Wk, Wv, wqb, wkb, wvb, HDIM * HDIM);
    cvt3_kernel<<<dim3(HDIM * FFN / 1024, 2), blk>>>(W1, W2, W1, w1b, w2b, w1b, HDIM * FFN);

    dim3 gProj(HDIM / 64, NTOK / 128);
    dim3 gF1(FFN / 64, NTOK / 128);
    dim3 gF2(HDIM / 64, NTOK / 128);

    gemm_cp<false, __nv_bfloat16><<<gProj, blk>>>(xb, wqb, bq, qb, NTOK, HDIM, HDIM, qscale);
    gemm_cp<false, __nv_bfloat16><<<gProj, blk>>>(xb, wkb, bk, kb, NTOK, HDIM, HDIM, 1.0f);
    gemm_cp<false, __nv_bfloat16><<<gProj, blk>>>(xb, wvb, bv, vb, NTOK, HDIM, HDIM, 1.0f);

    dim3 gAttn(T_FRAMES, 4, 8);
    attn_kernel<<<gAttn, blk, ATTN_SMEM_BYTES>>>(qb, kb, vb, kpm, cb);

    add_ln_kernel<true><<<NTOK / 8, blk>>>(x, cb, g1, be1, yb, y16);

    gemm_cp<true,  __nv_bfloat16><<<gF1, blk>>>(y16, w1b, b1, h16, NTOK, FFN, HDIM, 1.0f);
    gemm_cp<false, float><<<gF2, blk>>>(h16, w2b, b2, zb, NTOK, HDIM, FFN, 1.0f);

    add_ln_kernel<false><<<NTOK / 8, blk>>>(yb, zb, g2, be2, out, nullptr);
}

// round 11
// speedup vs baseline: 2.6523x; 1.0541x over previous
#include <cuda_runtime.h>
#include <cuda_bf16.h>
#include <math.h>

#define T_FRAMES 256
#define NDET     16
#define HDIM     256
#define DHEAD    32
#define WINR     8
#define MWIN     272         // (2*WINR+1)*NDET
#define NTOK     16384       // 4*256*16
#define FFN      1024
#define QKVN     768

// fp32 scratch
__device__ float g_c[NTOK * HDIM];
__device__ float g_y[NTOK * HDIM];
__device__ float g_z[NTOK * HDIM];
__device__ float g_bqkv[QKVN];
// bf16 scratch
__device__ __nv_bfloat16 g_xb[NTOK * HDIM];
__device__ __nv_bfloat16 g_qkv[NTOK * QKVN];
__device__ __nv_bfloat16 g_y16[NTOK * HDIM];
__device__ __nv_bfloat16 g_h16[NTOK * FFN];
__device__ __nv_bfloat16 g_wqkv[HDIM * QKVN];
__device__ __nv_bfloat16 g_w1[HDIM * FFN];
__device__ __nv_bfloat16 g_w2[FFN * HDIM];

__device__ __forceinline__ void mma_bf16(float c[4],
    unsigned a0, unsigned a1, unsigned a2, unsigned a3, unsigned b0, unsigned b1) {
    asm volatile(
        "mma.sync.aligned.m16n8k16.row.col.f32.bf16.bf16.f32 "
        "{%0,%1,%2,%3}, {%4,%5,%6,%7}, {%8,%9}, {%0,%1,%2,%3};\n"
        : "+f"(c[0]), "+f"(c[1]), "+f"(c[2]), "+f"(c[3])
        : "r"(a0), "r"(a1), "r"(a2), "r"(a3), "r"(b0), "r"(b1));
}
__device__ __forceinline__ void ldsm_x4(unsigned& r0, unsigned& r1, unsigned& r2, unsigned& r3,
                                        unsigned addr) {
    asm volatile("ldmatrix.sync.aligned.m8n8.x4.shared.b16 {%0,%1,%2,%3}, [%4];"
                 : "=r"(r0), "=r"(r1), "=r"(r2), "=r"(r3) : "r"(addr));
}
__device__ __forceinline__ void ldsm_x2(unsigned& r0, unsigned& r1, unsigned addr) {
    asm volatile("ldmatrix.sync.aligned.m8n8.x2.shared.b16 {%0,%1}, [%2];"
                 : "=r"(r0), "=r"(r1) : "r"(addr));
}
__device__ __forceinline__ void ldsm_x2t(unsigned& r0, unsigned& r1, unsigned addr) {
    asm volatile("ldmatrix.sync.aligned.m8n8.x2.trans.shared.b16 {%0,%1}, [%2];"
                 : "=r"(r0), "=r"(r1) : "r"(addr));
}
__device__ __forceinline__ void cp16(unsigned saddr, const void* gaddr) {
    asm volatile("cp.async.cg.shared.global [%0], [%1], 16;\n"
                 :: "r"(saddr), "l"(gaddr));
}
#define CP_COMMIT() asm volatile("cp.async.commit_group;\n" ::: "memory")
#define CP_WAIT1()  asm volatile("cp.async.wait_group 1;\n" ::: "memory")

__device__ __forceinline__ void store2(float* p, float a, float b) {
    *(float2*)p = make_float2(a, b);
}
__device__ __forceinline__ void store2(__nv_bfloat16* p, float a, float b) {
    *(__nv_bfloat162*)p = __floats2bfloat162_rn(a, b);
}

// ---- fp32 -> bf16 conversion: up to 3 tensors via blockIdx.y ----
__global__ __launch_bounds__(256) void cvt3_kernel(
    const float* __restrict__ a, const float* __restrict__ b, const float* __restrict__ c,
    __nv_bfloat16* oa, __nv_bfloat16* ob, __nv_bfloat16* oc, int n)
{
    const float* src = (blockIdx.y == 0) ? a : (blockIdx.y == 1) ? b : c;
    __nv_bfloat16* dst = (blockIdx.y == 0) ? oa : (blockIdx.y == 1) ? ob : oc;
    int i = (blockIdx.x * 256 + threadIdx.x) << 2;
    if (i < n) {
        float4 v = *(const float4*)(src + i);
        *(__nv_bfloat162*)(dst + i)     = __floats2bfloat162_rn(v.x, v.y);
        *(__nv_bfloat162*)(dst + i + 2) = __floats2bfloat162_rn(v.z, v.w);
    }
}

// ---- pack Wq*qs | Wk | Wv -> [HDIM][768] bf16, bias likewise ----
__global__ __launch_bounds__(256) void pack_qkv_kernel(
    const float* __restrict__ Wq, const float* __restrict__ Wk, const float* __restrict__ Wv,
    const float* __restrict__ bq, const float* __restrict__ bk, const float* __restrict__ bv,
    __nv_bfloat16* __restrict__ w, float* __restrict__ bias)
{
    const float qs = 0.17677669529663687f; // 1/sqrt(32)
    int i = (blockIdx.x * 256 + threadIdx.x) << 2;
    if (i < HDIM * HDIM) {
        int krow = i >> 8, j = i & 255;
        __nv_bfloat16* wr = w + krow * QKVN + j;
        float4 a = *(const float4*)(Wq + i);
        *(__nv_bfloat162*)(wr)     = __floats2bfloat162_rn(a.x * qs, a.y * qs);
        *(__nv_bfloat162*)(wr + 2) = __floats2bfloat162_rn(a.z * qs, a.w * qs);
        float4 bb = *(const float4*)(Wk + i);
        *(__nv_bfloat162*)(wr + 256)     = __floats2bfloat162_rn(bb.x, bb.y);
        *(__nv_bfloat162*)(wr + 256 + 2) = __floats2bfloat162_rn(bb.z, bb.w);
        float4 cc = *(const float4*)(Wv + i);
        *(__nv_bfloat162*)(wr + 512)     = __floats2bfloat162_rn(cc.x, cc.y);
        *(__nv_bfloat162*)(wr + 512 + 2) = __floats2bfloat162_rn(cc.z, cc.w);
    }
    if (blockIdx.x == 0 && threadIdx.x < 64) {
        int j = threadIdx.x << 2;
        float4 v = *(const float4*)(bq + j);
        *(float4*)(bias + j) = make_float4(v.x * qs, v.y * qs, v.z * qs, v.w * qs);
        *(float4*)(bias + 256 + j) = *(const float4*)(bk + j);
        *(float4*)(bias + 512 + j) = *(const float4*)(bv + j);
    }
}

// ---------------- bf16 TC GEMM, 3-stage cp.async, 1 barrier/ktile ----------------
// C[M,N] = act(A[M,K] @ B[K,N] + bias); A,B bf16 in gmem.
// BM=128 BN=64 BK=32, 256 threads (8 warps, 4m x 2n), warp tile 32x32.
template <bool RELU, typename OutT>
__global__ __launch_bounds__(256) void gemm_cp(
    const __nv_bfloat16* __restrict__ A, const __nv_bfloat16* __restrict__ B,
    const float* __restrict__ bias, OutT* __restrict__ C,
    int M, int N, int K)
{
    __shared__ __nv_bfloat16 As[3][128][40];   // 10240 B/stage
    __shared__ __nv_bfloat16 Bs[3][32][72];    // 4608 B/stage

    const int tid = threadIdx.x;
    const int warp = tid >> 5, lane = tid & 31;
    const int wm = (warp >> 1) << 5;
    const int wn = (warp & 1) << 5;
    const int gm0 = blockIdx.y << 7;
    const int gn0 = blockIdx.x << 6;

    const int arow = tid >> 1;
    const int ac16a = (tid & 1) << 1;
    const int brow = tid >> 3;
    const int bc16 = tid & 7;

    const unsigned asb = (unsigned)__cvta_generic_to_shared(&As[0][0][0]);
    const unsigned bsb = (unsigned)__cvta_generic_to_shared(&Bs[0][0][0]);
    const unsigned a_sdst = asb + ((arow * 40 + (ac16a << 3)) << 1);
    const unsigned b_sdst = bsb + ((brow * 72 + (bc16 << 3)) << 1);
    const __nv_bfloat16* a_gsrc = A + (long)(gm0 + arow) * K + (ac16a << 3);
    const __nv_bfloat16* b_gsrc = B + (long)brow * N + gn0 + (bc16 << 3);

    const unsigned abase = asb + (((wm + (lane & 15)) * 40 + ((lane >> 4) << 3)) << 1);
    const unsigned bbase = bsb + (((lane & 15) * 72 + wn) << 1);

    float acc[2][4][4];
#pragma unroll
    for (int i = 0; i < 2; i++)
#pragma unroll
        for (int j = 0; j < 4; j++)
#pragma unroll
            for (int l = 0; l < 4; l++) acc[i][j][l] = 0.f;

    const int nk = K >> 5;

    // prologue: stages 0 and 1
#pragma unroll
    for (int s = 0; s < 2; s++) {
        const __nv_bfloat16* ag = a_gsrc + s * 32;
        const __nv_bfloat16* bg = b_gsrc + (long)s * 32 * N;
        cp16(a_sdst + s * 10240,      ag);
        cp16(a_sdst + s * 10240 + 16, ag + 8);
        cp16(b_sdst + s * 4608,       bg);
        CP_COMMIT();
    }

    int sc = 0;                 // stage of kt
    for (int kt = 0; kt < nk; kt++) {
        CP_WAIT1();             // stage kt landed
        __syncthreads();        // visible to all; all readers of stage kt-1 done
        if (kt + 2 < nk) {
            int sp = sc - 1; if (sp < 0) sp = 2;   // (kt+2)%3 == (kt-1)%3
            const __nv_bfloat16* ag = a_gsrc + (kt + 2) * 32;
            const __nv_bfloat16* bg = b_gsrc + (long)(kt + 2) * 32 * N;
            cp16(a_sdst + sp * 10240,      ag);
            cp16(a_sdst + sp * 10240 + 16, ag + 8);
            cp16(b_sdst + sp * 4608,       bg);
        }
        CP_COMMIT();

        const unsigned ab = abase + sc * 10240;
        const unsigned bb = bbase + sc * 4608;
#pragma unroll
        for (int ks = 0; ks < 2; ks++) {
            unsigned af[2][4];
            ldsm_x4(af[0][0], af[0][1], af[0][2], af[0][3], ab + ks * 32);
            ldsm_x4(af[1][0], af[1][1], af[1][2], af[1][3], ab + 1280 + ks * 32);
            unsigned bf[4][2];
#pragma unroll
            for (int nt = 0; nt < 4; nt++)
                ldsm_x2t(bf[nt][0], bf[nt][1], bb + ks * 2304 + nt * 16);
#pragma unroll
            for (int mt = 0; mt < 2; mt++)
#pragma unroll
                for (int nt = 0; nt < 4; nt++)
                    mma_bf16(acc[mt][nt], af[mt][0], af[mt][1], af[mt][2], af[mt][3],
                             bf[nt][0], bf[nt][1]);
        }
        sc++; if (sc == 3) sc = 0;
    }

#pragma unroll
    for (int mt = 0; mt < 2; mt++) {
        int row = gm0 + wm + (mt << 4) + (lane >> 2);
#pragma unroll
        for (int nt = 0; nt < 4; nt++) {
            int col = gn0 + wn + (nt << 3) + ((lane & 3) << 1);
            float b0 = bias[col], b1 = bias[col + 1];
            float v0 = acc[mt][nt][0] + b0;
            float v1 = acc[mt][nt][1] + b1;
            float v2 = acc[mt][nt][2] + b0;
            float v3 = acc[mt][nt][3] + b1;
            if (RELU) {
                v0 = fmaxf(v0, 0.f); v1 = fmaxf(v1, 0.f);
                v2 = fmaxf(v2, 0.f); v3 = fmaxf(v3, 0.f);
            }
            store2(C + (long)row * N + col, v0, v1);
            store2(C + (long)(row + 8) * N + col, v2, v3);
        }
    }
}

// ---------------- windowed attention (qkv packed rows of 768) ----------------
#define KB_OFF   0
#define VB_OFF   21760
#define QB_OFF   43520
#define PB_OFF   44800
#define MASK_OFF 53760
#define RINV_OFF 54848
#define ATTN_SMEM_BYTES 54912

__global__ __launch_bounds__(256) void attn_kernel(
    const __nv_bfloat16* __restrict__ qkv, const unsigned char* __restrict__ kpm,
    float* __restrict__ ctx)
{
    extern __shared__ char smc[];
    __nv_bfloat16* Kb = (__nv_bfloat16*)(smc + KB_OFF);   // [272][40]
    __nv_bfloat16* Vb = (__nv_bfloat16*)(smc + VB_OFF);   // [272][40]
    __nv_bfloat16* Qb = (__nv_bfloat16*)(smc + QB_OFF);   // [16][40]
    __nv_bfloat16* Pb = (__nv_bfloat16*)(smc + PB_OFF);   // [16][280]
    float* maskadd = (float*)(smc + MASK_OFF);
    float* rowinv  = (float*)(smc + RINV_OFF);
    float* Rr      = (float*)(smc + KB_OFF);   // alias Kb after logits

    const unsigned sbase = (unsigned)__cvta_generic_to_shared(smc);
    const int tid = threadIdx.x;
    const int w = tid >> 5, lane = tid & 31;
    const int t = blockIdx.x, b = blockIdx.y, h = blockIdx.z;
    const long bt = (long)(b * T_FRAMES + t);

    // ---- stage K,V windows (16B copies from packed qkv) ----
    for (int slot = tid; slot < 4 * MWIN; slot += 256) {
        int m = slot >> 2, k8 = slot & 3;
        int wf = m >> 4, n = m & 15;
        int f = t + wf - WINR;
        uint4 kv = make_uint4(0, 0, 0, 0), vv = make_uint4(0, 0, 0, 0);
        if (f >= 0 && f < T_FRAMES) {
            long base = ((long)((b * T_FRAMES + f) * NDET + n)) * QKVN + h * DHEAD + (k8 << 3);
            kv = *(const uint4*)(qkv + base + 256);
            vv = *(const uint4*)(qkv + base + 512);
        }
        *(uint4*)(Kb + m * 40 + (k8 << 3)) = kv;
        *(uint4*)(Vb + m * 40 + (k8 << 3)) = vv;
    }
    if (tid < 64) {
        int n = tid >> 2, k8 = tid & 3;
        *(uint4*)(Qb + n * 40 + (k8 << 3)) =
            *(const uint4*)(qkv + (bt * NDET + n) * QKVN + h * DHEAD + (k8 << 3));
    }
    for (int m = tid; m < MWIN; m += 256) {
        int wf = m >> 4, n = m & 15;
        int f = t + wf - WINR;
        bool ok = (f >= 0) && (f < T_FRAMES) &&
                  (kpm[(b * T_FRAMES + f) * NDET + n] == 0);
        maskadd[m] = ok ? 0.f : -1e30f;
    }
    __syncthreads();

    // ---- logits: Pb[n][m] = Q @ K^T ----
    {
        unsigned qaddr = sbase + QB_OFF + (((lane & 15) * 40 + ((lane >> 4) << 3)) << 1);
        unsigned a0[4], a1[4];
        ldsm_x4(a0[0], a0[1], a0[2], a0[3], qaddr);
        ldsm_x4(a1[0], a1[1], a1[2], a1[3], qaddr + 32);

        const int lr = lane & 7;
        const int hg = (lane >> 3) & 1;
        for (int tw = w; tw < 34; tw += 8) {
            int m0 = tw << 3;
            float c[4] = {0.f, 0.f, 0.f, 0.f};
            unsigned baddr = sbase + KB_OFF + (((m0 + lr) * 40 + (hg << 3)) << 1);
            unsigned b0, b1, b2, b3;
            ldsm_x2(b0, b1, baddr);
            ldsm_x2(b2, b3, baddr + 32);
            mma_bf16(c, a0[0], a0[1], a0[2], a0[3], b0, b1);
            mma_bf16(c, a1[0], a1[1], a1[2], a1[3], b2, b3);
            int row = lane >> 2, mc = m0 + ((lane & 3) << 1);
            *(__nv_bfloat162*)(Pb + row * 280 + mc)       = __floats2bfloat162_rn(c[0], c[1]);
            *(__nv_bfloat162*)(Pb + (row + 8) * 280 + mc) = __floats2bfloat162_rn(c[2], c[3]);
        }
    }
    __syncthreads();

    // ---- masked softmax (bf16x2 traffic) ----
    {
        const int n = tid >> 4, l16 = tid & 15;
        float mx = -1e30f;
        for (int m2 = l16; m2 < 136; m2 += 16) {
            float2 p = __bfloat1622float2(*(__nv_bfloat162*)(Pb + n * 280 + (m2 << 1)));
            float2 ma = *(float2*)(maskadd + (m2 << 1));
            mx = fmaxf(mx, fmaxf(p.x + ma.x, p.y + ma.y));
        }
#pragma unroll
        for (int o = 8; o; o >>= 1) mx = fmaxf(mx, __shfl_xor_sync(0xffffffffu, mx, o));
        float sum = 0.f;
        for (int m2 = l16; m2 < 136; m2 += 16) {
            float2 p = __bfloat1622float2(*(__nv_bfloat162*)(Pb + n * 280 + (m2 << 1)));
            float2 ma = *(float2*)(maskadd + (m2 << 1));
            float e0 = __expf(p.x + ma.x - mx);
            float e1 = __expf(p.y + ma.y - mx);
            *(__nv_bfloat162*)(Pb + n * 280 + (m2 << 1)) = __floats2bfloat162_rn(e0, e1);
            sum += e0 + e1;
        }
#pragma unroll
        for (int o = 8; o; o >>= 1) sum += __shfl_xor_sync(0xffffffffu, sum, o);
        if (l16 == 0) rowinv[n] = 1.0f / sum;
    }
    __syncthreads();

    // ---- PV: ctx = Pb @ Vb, k-split across warp pairs ----
    {
        const int d0  = (w & 3) << 3;
        const int ks0 = (w < 4) ? 0 : 9;
        const int ks1 = (w < 4) ? 9 : 17;
        float c[4] = {0.f, 0.f, 0.f, 0.f};
        for (int ks = ks0; ks < ks1; ks++) {
            int m0 = ks << 4;
            unsigned aaddr = sbase + PB_OFF +
                ((((lane & 15) * 280) + m0 + ((lane >> 4) << 3)) << 1);
            unsigned a0, a1, a2, a3;
            ldsm_x4(a0, a1, a2, a3, aaddr);
            unsigned baddr = sbase + VB_OFF + (((m0 + (lane & 15)) * 40 + d0) << 1);
            unsigned b0, b1;
            ldsm_x2t(b0, b1, baddr);
            mma_bf16(c, a0, a1, a2, a3, b0, b1);
        }
        *(float4*)(Rr + ((w << 5) + lane) * 4) = make_float4(c[0], c[1], c[2], c[3]);
    }
    __syncthreads();

    {
        const int n0 = tid >> 5, d = tid & 31;
        const int tile = d >> 3;
        const int fl = (n0 << 2) + ((d & 7) >> 1);
        const int r = d & 1;
        float v1 = Rr[((tile << 5) + fl) * 4 + r] + Rr[(((tile + 4) << 5) + fl) * 4 + r];
        float v2 = Rr[((tile << 5) + fl) * 4 + r + 2] + Rr[(((tile + 4) << 5) + fl) * 4 + r + 2];
        ctx[(bt * NDET + n0) * HDIM + h * DHEAD + d]     = v1 * rowinv[n0];
        ctx[(bt * NDET + n0 + 8) * HDIM + h * DHEAD + d] = v2 * rowinv[n0 + 8];
    }
}

// residual add + LayerNorm; optional fused bf16 output copy
template <bool DUAL>
__global__ __launch_bounds__(256) void add_ln_kernel(
    const float* __restrict__ A, const float* __restrict__ Bv,
    const float* __restrict__ gw, const float* __restrict__ bw,
    float* __restrict__ out, __nv_bfloat16* __restrict__ out16)
{
    const int tok  = (blockIdx.x << 3) + (threadIdx.x >> 5);
    const int lane = threadIdx.x & 31;
    const float4* a4 = (const float4*)(A  + (long)tok * HDIM);
    const float4* b4 = (const float4*)(Bv + (long)tok * HDIM);
    float4 p0 = a4[lane * 2], p1 = a4[lane * 2 + 1];
    float4 q0 = b4[lane * 2], q1 = b4[lane * 2 + 1];
    float vv[8] = { p0.x + q0.x, p0.y + q0.y, p0.z + q0.z, p0.w + q0.w,
                    p1.x + q1.x, p1.y + q1.y, p1.z + q1.z, p1.w + q1.w };
    float s = 0.f;
#pragma unroll
    for (int i = 0; i < 8; i++) s += vv[i];
#pragma unroll
    for (int o = 16; o; o >>= 1) s += __shfl_xor_sync(0xffffffffu, s, o);
    const float mean = s * (1.f / 256.f);
    float vs = 0.f;
#pragma unroll
    for (int i = 0; i < 8; i++) { float d = vv[i] - mean; vs += d * d; }
#pragma unroll
    for (int o = 16; o; o >>= 1) vs += __shfl_xor_sync(0xffffffffu, vs, o);
    const float rs = rsqrtf(vs * (1.f / 256.f) + 1e-5f);

    float4 g0 = ((const float4*)gw)[lane * 2], g1 = ((const float4*)gw)[lane * 2 + 1];
    float4 e0 = ((const float4*)bw)[lane * 2], e1 = ((const float4*)bw)[lane * 2 + 1];
    float r[8];
    r[0] = (vv[0]-mean)*rs*g0.x + e0.x;  r[1] = (vv[1]-mean)*rs*g0.y + e0.y;
    r[2] = (vv[2]-mean)*rs*g0.z + e0.z;  r[3] = (vv[3]-mean)*rs*g0.w + e0.w;
    r[4] = (vv[4]-mean)*rs*g1.x + e1.x;  r[5] = (vv[5]-mean)*rs*g1.y + e1.y;
    r[6] = (vv[6]-mean)*rs*g1.z + e1.z;  r[7] = (vv[7]-mean)*rs*g1.w + e1.w;
    float4* o4 = (float4*)(out + (long)tok * HDIM);
    o4[lane * 2]     = make_float4(r[0], r[1], r[2], r[3]);
    o4[lane * 2 + 1] = make_float4(r[4], r[5], r[6], r[7]);
    if (DUAL) {
        __nv_bfloat16* ob = out16 + (long)tok * HDIM + lane * 8;
        __nv_bfloat162 h[4];
        h[0] = __floats2bfloat162_rn(r[0], r[1]);
        h[1] = __floats2bfloat162_rn(r[2], r[3]);
        h[2] = __floats2bfloat162_rn(r[4], r[5]);
        h[3] = __floats2bfloat162_rn(r[6], r[7]);
        *(uint4*)ob = *(uint4*)&h[0];
    }
}

extern "C" void kernel_launch(void* const* d_in, const int* in_sizes, int n_in,
                              void* d_out, int out_size)
{
    const float* x   = (const float*)d_in[0];
    const unsigned char* kpm = (const unsigned char*)d_in[1];
    const float* Wq = (const float*)d_in[2];
    const float* bq = (const float*)d_in[3];
    const float* Wk = (const float*)d_in[4];
    const float* bk = (const float*)d_in[5];
    const float* Wv = (const float*)d_in[6];
    const float* bv = (const float*)d_in[7];
    const float* W1 = (const float*)d_in[8];
    const float* b1 = (const float*)d_in[9];
    const float* W2 = (const float*)d_in[10];
    const float* b2 = (const float*)d_in[11];
    const float* g1 = (const float*)d_in[12];
    const float* be1 = (const float*)d_in[13];
    const float* g2 = (const float*)d_in[14];
    const float* be2 = (const float*)d_in[15];
    float* out = (float*)d_out;

    float *cb, *yb, *zb, *bqkv;
    __nv_bfloat16 *xb, *qkvb, *y16, *h16, *wqkvb, *w1b, *w2b;
    cudaGetSymbolAddress((void**)&cb, g_c);
    cudaGetSymbolAddress((void**)&yb, g_y);
    cudaGetSymbolAddress((void**)&zb, g_z);
    cudaGetSymbolAddress((void**)&bqkv, g_bqkv);
    cudaGetSymbolAddress((void**)&xb, g_xb);
    cudaGetSymbolAddress((void**)&qkvb, g_qkv);
    cudaGetSymbolAddress((void**)&y16, g_y16);
    cudaGetSymbolAddress((void**)&h16, g_h16);
    cudaGetSymbolAddress((void**)&wqkvb, g_wqkv);
    cudaGetSymbolAddress((void**)&w1b, g_w1);
    cudaGetSymbolAddress((void**)&w2b, g_w2);

    cudaFuncSetAttribute(attn_kernel,
                         cudaFuncAttributeMaxDynamicSharedMemorySize, ATTN_SMEM_BYTES);

    dim3 blk(256);

    // conversions + packing
    cvt3_kernel<<<dim3(NTOK * HDIM / 1024, 1), blk>>>(x, x, x, xb, xb, xb, NTOK * HDIM);
    pack_qkv_kernel<<<HDIM * HDIM / 1024, blk>>>(Wq, Wk, Wv, bq, bk, bv, wqkvb, bqkv);
    cvt3_kernel<<<dim3(HDIM * FFN / 1024, 2), blk>>>(W1, W2, W1, w1b, w2b, w1b, HDIM * FFN);

    // fused QKV projection
    gemm_cp<false, __nv_bfloat16><<<dim3(QKVN / 64, NTOK / 128), blk>>>(
        xb, wqkvb, bqkv, qkvb, NTOK, QKVN, HDIM);

    dim3 gAttn(T_FRAMES, 4, 8);
    attn_kernel<<<gAttn, blk, ATTN_SMEM_BYTES>>>(qkvb, kpm, cb);

    add_ln_kernel<true><<<NTOK / 8, blk>>>(x, cb, g1, be1, yb, y16);

    gemm_cp<true,  __nv_bfloat16><<<dim3(FFN / 64, NTOK / 128), blk>>>(
        y16, w1b, b1, h16, NTOK, FFN, HDIM);
    gemm_cp<false, float><<<dim3(HDIM / 64, NTOK / 128), blk>>>(
        h16, w2b, b2, zb, NTOK, HDIM, FFN);

    add_ln_kernel<false><<<NTOK / 8, blk>>>(yb, zb, g2, be2, out, nullptr);
}

// round 12
// speedup vs baseline: 3.0059x; 1.1333x over previous
#include <cuda_runtime.h>
#include <cuda_bf16.h>
#include <math.h>

#define T_FRAMES 256
#define NDET     16
#define HDIM     256
#define DHEAD    32
#define WINR     8
#define NTOK     16384       // 4*256*16
#define FFN      1024
#define QKVN     768
#define TG       4           // t per attn block
#define MB       320         // (TG-1 + 17) * 16 keys
#define QR       64          // TG*16 query rows
#define PST      328         // P row stride (halfs), 41 chunks % 8 == 1

// fp32 scratch
__device__ float g_c[NTOK * HDIM];
__device__ float g_y[NTOK * HDIM];
__device__ float g_z[NTOK * HDIM];
__device__ float g_bqkv[QKVN];
// bf16 scratch
__device__ __nv_bfloat16 g_xb[NTOK * HDIM];
__device__ __nv_bfloat16 g_qkv[NTOK * QKVN];
__device__ __nv_bfloat16 g_y16[NTOK * HDIM];
__device__ __nv_bfloat16 g_h16[NTOK * FFN];
__device__ __nv_bfloat16 g_wqkv[HDIM * QKVN];
__device__ __nv_bfloat16 g_w1[HDIM * FFN];
__device__ __nv_bfloat16 g_w2[FFN * HDIM];

__device__ __forceinline__ void mma_bf16(float c[4],
    unsigned a0, unsigned a1, unsigned a2, unsigned a3, unsigned b0, unsigned b1) {
    asm volatile(
        "mma.sync.aligned.m16n8k16.row.col.f32.bf16.bf16.f32 "
        "{%0,%1,%2,%3}, {%4,%5,%6,%7}, {%8,%9}, {%0,%1,%2,%3};\n"
        : "+f"(c[0]), "+f"(c[1]), "+f"(c[2]), "+f"(c[3])
        : "r"(a0), "r"(a1), "r"(a2), "r"(a3), "r"(b0), "r"(b1));
}
__device__ __forceinline__ void ldsm_x4(unsigned& r0, unsigned& r1, unsigned& r2, unsigned& r3,
                                        unsigned addr) {
    asm volatile("ldmatrix.sync.aligned.m8n8.x4.shared.b16 {%0,%1,%2,%3}, [%4];"
                 : "=r"(r0), "=r"(r1), "=r"(r2), "=r"(r3) : "r"(addr));
}
__device__ __forceinline__ void ldsm_x2(unsigned& r0, unsigned& r1, unsigned addr) {
    asm volatile("ldmatrix.sync.aligned.m8n8.x2.shared.b16 {%0,%1}, [%2];"
                 : "=r"(r0), "=r"(r1) : "r"(addr));
}
__device__ __forceinline__ void ldsm_x2t(unsigned& r0, unsigned& r1, unsigned addr) {
    asm volatile("ldmatrix.sync.aligned.m8n8.x2.trans.shared.b16 {%0,%1}, [%2];"
                 : "=r"(r0), "=r"(r1) : "r"(addr));
}
__device__ __forceinline__ void cp16(unsigned saddr, const void* gaddr) {
    asm volatile("cp.async.cg.shared.global [%0], [%1], 16;\n"
                 :: "r"(saddr), "l"(gaddr));
}
#define CP_COMMIT() asm volatile("cp.async.commit_group;\n" ::: "memory")
#define CP_WAIT1()  asm volatile("cp.async.wait_group 1;\n" ::: "memory")

__device__ __forceinline__ void store2(float* p, float a, float b) {
    *(float2*)p = make_float2(a, b);
}
__device__ __forceinline__ void store2(__nv_bfloat16* p, float a, float b) {
    *(__nv_bfloat162*)p = __floats2bfloat162_rn(a, b);
}

// ---- fp32 -> bf16 conversion: up to 3 tensors via blockIdx.y ----
__global__ __launch_bounds__(256) void cvt3_kernel(
    const float* __restrict__ a, const float* __restrict__ b, const float* __restrict__ c,
    __nv_bfloat16* oa, __nv_bfloat16* ob, __nv_bfloat16* oc, int n)
{
    const float* src = (blockIdx.y == 0) ? a : (blockIdx.y == 1) ? b : c;
    __nv_bfloat16* dst = (blockIdx.y == 0) ? oa : (blockIdx.y == 1) ? ob : oc;
    int i = (blockIdx.x * 256 + threadIdx.x) << 2;
    if (i < n) {
        float4 v = *(const float4*)(src + i);
        *(__nv_bfloat162*)(dst + i)     = __floats2bfloat162_rn(v.x, v.y);
        *(__nv_bfloat162*)(dst + i + 2) = __floats2bfloat162_rn(v.z, v.w);
    }
}

// ---- pack Wq*qs | Wk | Wv -> [HDIM][768] bf16, bias likewise ----
__global__ __launch_bounds__(256) void pack_qkv_kernel(
    const float* __restrict__ Wq, const float* __restrict__ Wk, const float* __restrict__ Wv,
    const float* __restrict__ bq, const float* __restrict__ bk, const float* __restrict__ bv,
    __nv_bfloat16* __restrict__ w, float* __restrict__ bias)
{
    const float qs = 0.17677669529663687f; // 1/sqrt(32)
    int i = (blockIdx.x * 256 + threadIdx.x) << 2;
    if (i < HDIM * HDIM) {
        int krow = i >> 8, j = i & 255;
        __nv_bfloat16* wr = w + krow * QKVN + j;
        float4 a = *(const float4*)(Wq + i);
        *(__nv_bfloat162*)(wr)     = __floats2bfloat162_rn(a.x * qs, a.y * qs);
        *(__nv_bfloat162*)(wr + 2) = __floats2bfloat162_rn(a.z * qs, a.w * qs);
        float4 bb = *(const float4*)(Wk + i);
        *(__nv_bfloat162*)(wr + 256)     = __floats2bfloat162_rn(bb.x, bb.y);
        *(__nv_bfloat162*)(wr + 256 + 2) = __floats2bfloat162_rn(bb.z, bb.w);
        float4 cc = *(const float4*)(Wv + i);
        *(__nv_bfloat162*)(wr + 512)     = __floats2bfloat162_rn(cc.x, cc.y);
        *(__nv_bfloat162*)(wr + 512 + 2) = __floats2bfloat162_rn(cc.z, cc.w);
    }
    if (blockIdx.x == 0 && threadIdx.x < 64) {
        int j = threadIdx.x << 2;
        float4 v = *(const float4*)(bq + j);
        *(float4*)(bias + j) = make_float4(v.x * qs, v.y * qs, v.z * qs, v.w * qs);
        *(float4*)(bias + 256 + j) = *(const float4*)(bk + j);
        *(float4*)(bias + 512 + j) = *(const float4*)(bv + j);
    }
}

// ---------------- bf16 TC GEMM, 3-stage cp.async, 1 barrier/ktile ----------------
template <bool RELU, typename OutT>
__global__ __launch_bounds__(256) void gemm_cp(
    const __nv_bfloat16* __restrict__ A, const __nv_bfloat16* __restrict__ B,
    const float* __restrict__ bias, OutT* __restrict__ C,
    int M, int N, int K)
{
    __shared__ __nv_bfloat16 As[3][128][40];
    __shared__ __nv_bfloat16 Bs[3][32][72];

    const int tid = threadIdx.x;
    const int warp = tid >> 5, lane = tid & 31;
    const int wm = (warp >> 1) << 5;
    const int wn = (warp & 1) << 5;
    const int gm0 = blockIdx.y << 7;
    const int gn0 = blockIdx.x << 6;

    const int arow = tid >> 1;
    const int ac16a = (tid & 1) << 1;
    const int brow = tid >> 3;
    const int bc16 = tid & 7;

    const unsigned asb = (unsigned)__cvta_generic_to_shared(&As[0][0][0]);
    const unsigned bsb = (unsigned)__cvta_generic_to_shared(&Bs[0][0][0]);
    const unsigned a_sdst = asb + ((arow * 40 + (ac16a << 3)) << 1);
    const unsigned b_sdst = bsb + ((brow * 72 + (bc16 << 3)) << 1);
    const __nv_bfloat16* a_gsrc = A + (long)(gm0 + arow) * K + (ac16a << 3);
    const __nv_bfloat16* b_gsrc = B + (long)brow * N + gn0 + (bc16 << 3);

    const unsigned abase = asb + (((wm + (lane & 15)) * 40 + ((lane >> 4) << 3)) << 1);
    const unsigned bbase = bsb + (((lane & 15) * 72 + wn) << 1);

    float acc[2][4][4];
#pragma unroll
    for (int i = 0; i < 2; i++)
#pragma unroll
        for (int j = 0; j < 4; j++)
#pragma unroll
            for (int l = 0; l < 4; l++) acc[i][j][l] = 0.f;

    const int nk = K >> 5;

#pragma unroll
    for (int s = 0; s < 2; s++) {
        const __nv_bfloat16* ag = a_gsrc + s * 32;
        const __nv_bfloat16* bg = b_gsrc + (long)s * 32 * N;
        cp16(a_sdst + s * 10240,      ag);
        cp16(a_sdst + s * 10240 + 16, ag + 8);
        cp16(b_sdst + s * 4608,       bg);
        CP_COMMIT();
    }

    int sc = 0;
    for (int kt = 0; kt < nk; kt++) {
        CP_WAIT1();
        __syncthreads();
        if (kt + 2 < nk) {
            int sp = sc - 1; if (sp < 0) sp = 2;
            const __nv_bfloat16* ag = a_gsrc + (kt + 2) * 32;
            const __nv_bfloat16* bg = b_gsrc + (long)(kt + 2) * 32 * N;
            cp16(a_sdst + sp * 10240,      ag);
            cp16(a_sdst + sp * 10240 + 16, ag + 8);
            cp16(b_sdst + sp * 4608,       bg);
        }
        CP_COMMIT();

        const unsigned ab = abase + sc * 10240;
        const unsigned bb = bbase + sc * 4608;
#pragma unroll
        for (int ks = 0; ks < 2; ks++) {
            unsigned af[2][4];
            ldsm_x4(af[0][0], af[0][1], af[0][2], af[0][3], ab + ks * 32);
            ldsm_x4(af[1][0], af[1][1], af[1][2], af[1][3], ab + 1280 + ks * 32);
            unsigned bf[4][2];
#pragma unroll
            for (int nt = 0; nt < 4; nt++)
                ldsm_x2t(bf[nt][0], bf[nt][1], bb + ks * 2304 + nt * 16);
#pragma unroll
            for (int mt = 0; mt < 2; mt++)
#pragma unroll
                for (int nt = 0; nt < 4; nt++)
                    mma_bf16(acc[mt][nt], af[mt][0], af[mt][1], af[mt][2], af[mt][3],
                             bf[nt][0], bf[nt][1]);
        }
        sc++; if (sc == 3) sc = 0;
    }

#pragma unroll
    for (int mt = 0; mt < 2; mt++) {
        int row = gm0 + wm + (mt << 4) + (lane >> 2);
#pragma unroll
        for (int nt = 0; nt < 4; nt++) {
            int col = gn0 + wn + (nt << 3) + ((lane & 3) << 1);
            float b0 = bias[col], b1 = bias[col + 1];
            float v0 = acc[mt][nt][0] + b0;
            float v1 = acc[mt][nt][1] + b1;
            float v2 = acc[mt][nt][2] + b0;
            float v3 = acc[mt][nt][3] + b1;
            if (RELU) {
                v0 = fmaxf(v0, 0.f); v1 = fmaxf(v1, 0.f);
                v2 = fmaxf(v2, 0.f); v3 = fmaxf(v3, 0.f);
            }
            store2(C + (long)row * N + col, v0, v1);
            store2(C + (long)(row + 8) * N + col, v2, v3);
        }
    }
}

// ---------------- windowed attention: 4 t per block ----------------
// smem: Kb[320][40] bf16 | Vb[320][40] bf16 | Qb[64][40] bf16 |
//       Pb[64][328] bf16 | mask[320] f32 | rinv[64] f32
#define KB_OFF   0
#define VB_OFF   25600
#define QB_OFF   51200
#define PB_OFF   56320
#define MASK_OFF 98304
#define RINV_OFF 99584
#define ATTN_SMEM_BYTES 99840

__global__ __launch_bounds__(256) void attn_kernel(
    const __nv_bfloat16* __restrict__ qkv, const unsigned char* __restrict__ kpm,
    float* __restrict__ ctx)
{
    extern __shared__ char smc[];
    __nv_bfloat16* Pb = (__nv_bfloat16*)(smc + PB_OFF);
    float* maskadd = (float*)(smc + MASK_OFF);
    float* rowinv  = (float*)(smc + RINV_OFF);

    const unsigned sbase = (unsigned)__cvta_generic_to_shared(smc);
    const int tid = threadIdx.x;
    const int w = tid >> 5, lane = tid & 31;
    const int t0 = blockIdx.x << 2, b = blockIdx.y, h = blockIdx.z;

    // ---- stage K,V: 320 rows x 40 halfs (16B copies from packed qkv) ----
    for (int slot = tid; slot < 4 * MB; slot += 256) {
        int m = slot >> 2, k8 = slot & 3;
        int f = t0 + (m >> 4) - WINR;
        int n = m & 15;
        uint4 kv = make_uint4(0, 0, 0, 0), vv = make_uint4(0, 0, 0, 0);
        if (f >= 0 && f < T_FRAMES) {
            long base = ((long)((b * T_FRAMES + f) * NDET + n)) * QKVN + h * DHEAD + (k8 << 3);
            kv = *(const uint4*)(qkv + base + 256);
            vv = *(const uint4*)(qkv + base + 512);
        }
        *(uint4*)((__nv_bfloat16*)(smc + KB_OFF) + m * 40 + (k8 << 3)) = kv;
        *(uint4*)((__nv_bfloat16*)(smc + VB_OFF) + m * 40 + (k8 << 3)) = vv;
    }
    // ---- Q: 64 rows (4 t x 16 det) ----
    {
        int r = tid >> 2, k8 = tid & 3;
        long tok = (long)(b * T_FRAMES + t0 + (r >> 4)) * NDET + (r & 15);
        *(uint4*)((__nv_bfloat16*)(smc + QB_OFF) + r * 40 + (k8 << 3)) =
            *(const uint4*)(qkv + tok * QKVN + h * DHEAD + (k8 << 3));
    }
    // ---- mask over 320 keys (frame range + key padding) ----
    for (int m = tid; m < MB; m += 256) {
        int f = t0 + (m >> 4) - WINR;
        int n = m & 15;
        bool ok = (f >= 0) && (f < T_FRAMES) &&
                  (kpm[(b * T_FRAMES + f) * NDET + n] == 0);
        maskadd[m] = ok ? 0.f : -1e30f;
    }
    __syncthreads();

    // ---- logits: Pb[64][320] = Q @ K^T ----
    {
        unsigned qa[4][2][4];
#pragma unroll
        for (int qt = 0; qt < 4; qt++) {
            unsigned qaddr = sbase + QB_OFF +
                ((((qt << 4) + (lane & 15)) * 40 + ((lane >> 4) << 3)) << 1);
            ldsm_x4(qa[qt][0][0], qa[qt][0][1], qa[qt][0][2], qa[qt][0][3], qaddr);
            ldsm_x4(qa[qt][1][0], qa[qt][1][1], qa[qt][1][2], qa[qt][1][3], qaddr + 32);
        }
        const int m0w = w * 40;
        const int lr = lane & 7;
        const int hg = (lane >> 3) & 1;
#pragma unroll
        for (int mt = 0; mt < 5; mt++) {
            int m0 = m0w + (mt << 3);
            unsigned baddr = sbase + KB_OFF + (((m0 + lr) * 40 + (hg << 3)) << 1);
            unsigned b0, b1, b2, b3;
            ldsm_x2(b0, b1, baddr);
            ldsm_x2(b2, b3, baddr + 32);
#pragma unroll
            for (int qt = 0; qt < 4; qt++) {
                float c[4] = {0.f, 0.f, 0.f, 0.f};
                mma_bf16(c, qa[qt][0][0], qa[qt][0][1], qa[qt][0][2], qa[qt][0][3], b0, b1);
                mma_bf16(c, qa[qt][1][0], qa[qt][1][1], qa[qt][1][2], qa[qt][1][3], b2, b3);
                int row = (qt << 4) + (lane >> 2), mc = m0 + ((lane & 3) << 1);
                *(__nv_bfloat162*)(Pb + row * PST + mc)       = __floats2bfloat162_rn(c[0], c[1]);
                *(__nv_bfloat162*)(Pb + (row + 8) * PST + mc) = __floats2bfloat162_rn(c[2], c[3]);
            }
        }
    }
    __syncthreads();

    // ---- masked softmax per row (4 lanes/row); window = [16*tloc, 16*tloc+272) ----
    {
        const int r = tid >> 2, l4 = tid & 3;
        const int p0 = (r >> 4) << 3;            // first valid pair
        const int p1 = p0 + 136;                 // one past last valid pair
        float mx = -1e30f;
        for (int p = p0 + l4; p < p1; p += 4) {
            float2 v = __bfloat1622float2(*(__nv_bfloat162*)(Pb + r * PST + (p << 1)));
            float2 ma = *(float2*)(maskadd + (p << 1));
            mx = fmaxf(mx, fmaxf(v.x + ma.x, v.y + ma.y));
        }
        mx = fmaxf(mx, __shfl_xor_sync(0xffffffffu, mx, 1));
        mx = fmaxf(mx, __shfl_xor_sync(0xffffffffu, mx, 2));
        float sum = 0.f;
        for (int p = l4; p < 160; p += 4) {
            float e0 = 0.f, e1 = 0.f;
            if (p >= p0 && p < p1) {
                float2 v = __bfloat1622float2(*(__nv_bfloat162*)(Pb + r * PST + (p << 1)));
                float2 ma = *(float2*)(maskadd + (p << 1));
                e0 = __expf(v.x + ma.x - mx);
                e1 = __expf(v.y + ma.y - mx);
                sum += e0 + e1;
            }
            *(__nv_bfloat162*)(Pb + r * PST + (p << 1)) = __floats2bfloat162_rn(e0, e1);
        }
        sum += __shfl_xor_sync(0xffffffffu, sum, 1);
        sum += __shfl_xor_sync(0xffffffffu, sum, 2);
        if (l4 == 0) rowinv[r] = 1.0f / sum;
    }
    __syncthreads();

    // ---- PV: ctx[64][32] = Pb @ Vb; warp owns 16 rows x 16 cols, full k ----
    {
        const int mrow = (w >> 1) << 4;           // 0,16,32,48
        const int nc0  = (w & 1) << 4;            // 0 or 16
        float c0[4] = {0.f, 0.f, 0.f, 0.f};
        float c1[4] = {0.f, 0.f, 0.f, 0.f};
#pragma unroll 5
        for (int ks = 0; ks < 20; ks++) {
            unsigned aaddr = sbase + PB_OFF +
                (((mrow + (lane & 15)) * PST + (ks << 4) + ((lane >> 4) << 3)) << 1);
            unsigned a0, a1, a2, a3;
            ldsm_x4(a0, a1, a2, a3, aaddr);
            unsigned baddr = sbase + VB_OFF + ((((ks << 4) + (lane & 15)) * 40 + nc0) << 1);
            unsigned b0, b1, b2, b3;
            ldsm_x2t(b0, b1, baddr);
            ldsm_x2t(b2, b3, baddr + 16);
            mma_bf16(c0, a0, a1, a2, a3, b0, b1);
            mma_bf16(c1, a0, a1, a2, a3, b2, b3);
        }
        const int rr = mrow + (lane >> 2);
        const int cc = nc0 + ((lane & 3) << 1);
        const float ri0 = rowinv[rr], ri1 = rowinv[rr + 8];
        long tok0 = (long)(b * T_FRAMES + t0 + (rr >> 4)) * NDET + (rr & 15);
        int r8 = rr + 8;
        long tok1 = (long)(b * T_FRAMES + t0 + (r8 >> 4)) * NDET + (r8 & 15);
        float* o0 = ctx + tok0 * HDIM + h * DHEAD + cc;
        float* o1 = ctx + tok1 * HDIM + h * DHEAD + cc;
        store2(o0,     c0[0] * ri0, c0[1] * ri0);
        store2(o0 + 8, c1[0] * ri0, c1[1] * ri0);
        store2(o1,     c0[2] * ri1, c0[3] * ri1);
        store2(o1 + 8, c1[2] * ri1, c1[3] * ri1);
    }
}

// residual add + LayerNorm; optional fused bf16 output copy
template <bool DUAL>
__global__ __launch_bounds__(256) void add_ln_kernel(
    const float* __restrict__ A, const float* __restrict__ Bv,
    const float* __restrict__ gw, const float* __restrict__ bw,
    float* __restrict__ out, __nv_bfloat16* __restrict__ out16)
{
    const int tok  = (blockIdx.x << 3) + (threadIdx.x >> 5);
    const int lane = threadIdx.x & 31;
    const float4* a4 = (const float4*)(A  + (long)tok * HDIM);
    const float4* b4 = (const float4*)(Bv + (long)tok * HDIM);
    float4 p0 = a4[lane * 2], p1 = a4[lane * 2 + 1];
    float4 q0 = b4[lane * 2], q1 = b4[lane * 2 + 1];
    float vv[8] = { p0.x + q0.x, p0.y + q0.y, p0.z + q0.z, p0.w + q0.w,
                    p1.x + q1.x, p1.y + q1.y, p1.z + q1.z, p1.w + q1.w };
    float s = 0.f;
#pragma unroll
    for (int i = 0; i < 8; i++) s += vv[i];
#pragma unroll
    for (int o = 16; o; o >>= 1) s += __shfl_xor_sync(0xffffffffu, s, o);
    const float mean = s * (1.f / 256.f);
    float vs = 0.f;
#pragma unroll
    for (int i = 0; i < 8; i++) { float d = vv[i] - mean; vs += d * d; }
#pragma unroll
    for (int o = 16; o; o >>= 1) vs += __shfl_xor_sync(0xffffffffu, vs, o);
    const float rs = rsqrtf(vs * (1.f / 256.f) + 1e-5f);

    float4 g0 = ((const float4*)gw)[lane * 2], g1 = ((const float4*)gw)[lane * 2 + 1];
    float4 e0 = ((const float4*)bw)[lane * 2], e1 = ((const float4*)bw)[lane * 2 + 1];
    float r[8];
    r[0] = (vv[0]-mean)*rs*g0.x + e0.x;  r[1] = (vv[1]-mean)*rs*g0.y + e0.y;
    r[2] = (vv[2]-mean)*rs*g0.z + e0.z;  r[3] = (vv[3]-mean)*rs*g0.w + e0.w;
    r[4] = (vv[4]-mean)*rs*g1.x + e1.x;  r[5] = (vv[5]-mean)*rs*g1.y + e1.y;
    r[6] = (vv[6]-mean)*rs*g1.z + e1.z;  r[7] = (vv[7]-mean)*rs*g1.w + e1.w;
    float4* o4 = (float4*)(out + (long)tok * HDIM);
    o4[lane * 2]     = make_float4(r[0], r[1], r[2], r[3]);
    o4[lane * 2 + 1] = make_float4(r[4], r[5], r[6], r[7]);
    if (DUAL) {
        __nv_bfloat16* ob = out16 + (long)tok * HDIM + lane * 8;
        __nv_bfloat162 hh[4];
        hh[0] = __floats2bfloat162_rn(r[0], r[1]);
        hh[1] = __floats2bfloat162_rn(r[2], r[3]);
        hh[2] = __floats2bfloat162_rn(r[4], r[5]);
        hh[3] = __floats2bfloat162_rn(r[6], r[7]);
        *(uint4*)ob = *(uint4*)&hh[0];
    }
}

extern "C" void kernel_launch(void* const* d_in, const int* in_sizes, int n_in,
                              void* d_out, int out_size)
{
    const float* x   = (const float*)d_in[0];
    const unsigned char* kpm = (const unsigned char*)d_in[1];
    const float* Wq = (const float*)d_in[2];
    const float* bq = (const float*)d_in[3];
    const float* Wk = (const float*)d_in[4];
    const float* bk = (const float*)d_in[5];
    const float* Wv = (const float*)d_in[6];
    const float* bv = (const float*)d_in[7];
    const float* W1 = (const float*)d_in[8];
    const float* b1 = (const float*)d_in[9];
    const float* W2 = (const float*)d_in[10];
    const float* b2 = (const float*)d_in[11];
    const float* g1 = (const float*)d_in[12];
    const float* be1 = (const float*)d_in[13];
    const float* g2 = (const float*)d_in[14];
    const float* be2 = (const float*)d_in[15];
    float* out = (float*)d_out;

    float *cb, *yb, *zb, *bqkv;
    __nv_bfloat16 *xb, *qkvb, *y16, *h16, *wqkvb, *w1b, *w2b;
    cudaGetSymbolAddress((void**)&cb, g_c);
    cudaGetSymbolAddress((void**)&yb, g_y);
    cudaGetSymbolAddress((void**)&zb, g_z);
    cudaGetSymbolAddress((void**)&bqkv, g_bqkv);
    cudaGetSymbolAddress((void**)&xb, g_xb);
    cudaGetSymbolAddress((void**)&qkvb, g_qkv);
    cudaGetSymbolAddress((void**)&y16, g_y16);
    cudaGetSymbolAddress((void**)&h16, g_h16);
    cudaGetSymbolAddress((void**)&wqkvb, g_wqkv);
    cudaGetSymbolAddress((void**)&w1b, g_w1);
    cudaGetSymbolAddress((void**)&w2b, g_w2);

    cudaFuncSetAttribute(attn_kernel,
                         cudaFuncAttributeMaxDynamicSharedMemorySize, ATTN_SMEM_BYTES);

    dim3 blk(256);

    cvt3_kernel<<<dim3(NTOK * HDIM / 1024, 1), blk>>>(x, x, x, xb, xb, xb, NTOK * HDIM);
    pack_qkv_kernel<<<HDIM * HDIM / 1024, blk>>>(Wq, Wk, Wv, bq, bk, bv, wqkvb, bqkv);
    cvt3_kernel<<<dim3(HDIM * FFN / 1024, 2), blk>>>(W1, W2, W1, w1b, w2b, w1b, HDIM * FFN);

    gemm_cp<false, __nv_bfloat16><<<dim3(QKVN / 64, NTOK / 128), blk>>>(
        xb, wqkvb, bqkv, qkvb, NTOK, QKVN, HDIM);

    dim3 gAttn(T_FRAMES / TG, 4, 8);
    attn_kernel<<<gAttn, blk, ATTN_SMEM_BYTES>>>(qkvb, kpm, cb);

    add_ln_kernel<true><<<NTOK / 8, blk>>>(x, cb, g1, be1, yb, y16);

    gemm_cp<true,  __nv_bfloat16><<<dim3(FFN / 64, NTOK / 128), blk>>>(
        y16, w1b, b1, h16, NTOK, FFN, HDIM);
    gemm_cp<false, float><<<dim3(HDIM / 64, NTOK / 128), blk>>>(
        h16, w2b, b2, zb, NTOK, HDIM, FFN);

    add_ln_kernel<false><<<NTOK / 8, blk>>>(yb, zb, g2, be2, out, nullptr);
}

// round 14
// speedup vs baseline: 3.1971x; 1.0636x over previous
#include <cuda_runtime.h>
#include <cuda_bf16.h>
#include <math.h>

#define T_FRAMES 256
#define NDET     16
#define HDIM     256
#define DHEAD    32
#define WINR     8
#define NTOK     16384       // 4*256*16
#define FFN      1024
#define QKVN     768
#define TG       4           // t per attn block
#define MB       320         // (TG-1 + 17) * 16 keys
#define PST      328         // P row stride (halfs), 41 chunks % 8 == 1

// fp32 scratch
__device__ float g_c[NTOK * HDIM];
__device__ float g_y[NTOK * HDIM];
__device__ float g_z[NTOK * HDIM];
__device__ float g_bqkv[QKVN];
// bf16 scratch
__device__ __nv_bfloat16 g_xb[NTOK * HDIM];
__device__ __nv_bfloat16 g_qkv[NTOK * QKVN];
__device__ __nv_bfloat16 g_y16[NTOK * HDIM];
__device__ __nv_bfloat16 g_h16[NTOK * FFN];
__device__ __nv_bfloat16 g_wqkv[HDIM * QKVN];
__device__ __nv_bfloat16 g_w1[HDIM * FFN];
__device__ __nv_bfloat16 g_w2[FFN * HDIM];

__device__ __forceinline__ void mma_bf16(float c[4],
    unsigned a0, unsigned a1, unsigned a2, unsigned a3, unsigned b0, unsigned b1) {
    asm volatile(
        "mma.sync.aligned.m16n8k16.row.col.f32.bf16.bf16.f32 "
        "{%0,%1,%2,%3}, {%4,%5,%6,%7}, {%8,%9}, {%0,%1,%2,%3};\n"
        : "+f"(c[0]), "+f"(c[1]), "+f"(c[2]), "+f"(c[3])
        : "r"(a0), "r"(a1), "r"(a2), "r"(a3), "r"(b0), "r"(b1));
}
__device__ __forceinline__ void ldsm_x4(unsigned& r0, unsigned& r1, unsigned& r2, unsigned& r3,
                                        unsigned addr) {
    asm volatile("ldmatrix.sync.aligned.m8n8.x4.shared.b16 {%0,%1,%2,%3}, [%4];"
                 : "=r"(r0), "=r"(r1), "=r"(r2), "=r"(r3) : "r"(addr));
}
__device__ __forceinline__ void ldsm_x4t(unsigned& r0, unsigned& r1, unsigned& r2, unsigned& r3,
                                         unsigned addr) {
    asm volatile("ldmatrix.sync.aligned.m8n8.x4.trans.shared.b16 {%0,%1,%2,%3}, [%4];"
                 : "=r"(r0), "=r"(r1), "=r"(r2), "=r"(r3) : "r"(addr));
}
__device__ __forceinline__ void ldsm_x2(unsigned& r0, unsigned& r1, unsigned addr) {
    asm volatile("ldmatrix.sync.aligned.m8n8.x2.shared.b16 {%0,%1}, [%2];"
                 : "=r"(r0), "=r"(r1) : "r"(addr));
}
__device__ __forceinline__ void ldsm_x2t(unsigned& r0, unsigned& r1, unsigned addr) {
    asm volatile("ldmatrix.sync.aligned.m8n8.x2.trans.shared.b16 {%0,%1}, [%2];"
                 : "=r"(r0), "=r"(r1) : "r"(addr));
}
__device__ __forceinline__ void cp16(unsigned saddr, const void* gaddr) {
    asm volatile("cp.async.cg.shared.global [%0], [%1], 16;\n"
                 :: "r"(saddr), "l"(gaddr));
}
#define CP_COMMIT() asm volatile("cp.async.commit_group;\n" ::: "memory")
#define CP_WAIT1()  asm volatile("cp.async.wait_group 1;\n" ::: "memory")

__device__ __forceinline__ void store2(float* p, float a, float b) {
    *(float2*)p = make_float2(a, b);
}
__device__ __forceinline__ void store2(__nv_bfloat16* p, float a, float b) {
    *(__nv_bfloat162*)p = __floats2bfloat162_rn(a, b);
}

// ---- fp32 -> bf16 conversion: up to 3 tensors via blockIdx.y ----
__global__ __launch_bounds__(256) void cvt3_kernel(
    const float* __restrict__ a, const float* __restrict__ b, const float* __restrict__ c,
    __nv_bfloat16* oa, __nv_bfloat16* ob, __nv_bfloat16* oc, int n)
{
    const float* src = (blockIdx.y == 0) ? a : (blockIdx.y == 1) ? b : c;
    __nv_bfloat16* dst = (blockIdx.y == 0) ? oa : (blockIdx.y == 1) ? ob : oc;
    int i = (blockIdx.x * 256 + threadIdx.x) << 2;
    if (i < n) {
        float4 v = *(const float4*)(src + i);
        *(__nv_bfloat162*)(dst + i)     = __floats2bfloat162_rn(v.x, v.y);
        *(__nv_bfloat162*)(dst + i + 2) = __floats2bfloat162_rn(v.z, v.w);
    }
}

// ---- pack Wq*qs | Wk | Wv -> [HDIM][768] bf16, bias likewise ----
__global__ __launch_bounds__(256) void pack_qkv_kernel(
    const float* __restrict__ Wq, const float* __restrict__ Wk, const float* __restrict__ Wv,
    const float* __restrict__ bq, const float* __restrict__ bk, const float* __restrict__ bv,
    __nv_bfloat16* __restrict__ w, float* __restrict__ bias)
{
    const float qs = 0.17677669529663687f; // 1/sqrt(32)
    int i = (blockIdx.x * 256 + threadIdx.x) << 2;
    if (i < HDIM * HDIM) {
        int krow = i >> 8, j = i & 255;
        __nv_bfloat16* wr = w + krow * QKVN + j;
        float4 a = *(const float4*)(Wq + i);
        *(__nv_bfloat162*)(wr)     = __floats2bfloat162_rn(a.x * qs, a.y * qs);
        *(__nv_bfloat162*)(wr + 2) = __floats2bfloat162_rn(a.z * qs, a.w * qs);
        float4 bb = *(const float4*)(Wk + i);
        *(__nv_bfloat162*)(wr + 256)     = __floats2bfloat162_rn(bb.x, bb.y);
        *(__nv_bfloat162*)(wr + 256 + 2) = __floats2bfloat162_rn(bb.z, bb.w);
        float4 cc = *(const float4*)(Wv + i);
        *(__nv_bfloat162*)(wr + 512)     = __floats2bfloat162_rn(cc.x, cc.y);
        *(__nv_bfloat162*)(wr + 512 + 2) = __floats2bfloat162_rn(cc.z, cc.w);
    }
    if (blockIdx.x == 0 && threadIdx.x < 64) {
        int j = threadIdx.x << 2;
        float4 v = *(const float4*)(bq + j);
        *(float4*)(bias + j) = make_float4(v.x * qs, v.y * qs, v.z * qs, v.w * qs);
        *(float4*)(bias + 256 + j) = *(const float4*)(bk + j);
        *(float4*)(bias + 512 + j) = *(const float4*)(bv + j);
    }
}

// ---------------- bf16 TC GEMM: BM=128 BN=128 BK=32, warp tile 32x64 ----------------
// 3-stage cp.async, 1 barrier/ktile. Dynamic smem: As 3x10240 @0, Bs 3x8704 @30720.
#define AS_STAGE 10240          // 128*40*2
#define BS_STAGE 8704           // 32*136*2
#define BS_BASE  30720          // 3*AS_STAGE
#define GEMM_SMEM_BYTES (BS_BASE + 3 * BS_STAGE)   // 56832

template <bool RELU, typename OutT>
__global__ __launch_bounds__(256) void gemm_cp(
    const __nv_bfloat16* __restrict__ A, const __nv_bfloat16* __restrict__ B,
    const float* __restrict__ bias, OutT* __restrict__ C,
    int M, int N, int K)
{
    extern __shared__ char gsm[];
    const unsigned asb = (unsigned)__cvta_generic_to_shared(gsm);
    const unsigned bsb = asb + BS_BASE;

    const int tid = threadIdx.x;
    const int warp = tid >> 5, lane = tid & 31;
    const int wm = (warp >> 1) << 5;      // 0,32,64,96
    const int wn = (warp & 1) << 6;       // 0,64
    const int gm0 = blockIdx.y << 7;
    const int gn0 = blockIdx.x << 7;

    // cp.async mapping
    const int arow = tid >> 1;            // 0..127
    const int ac16a = (tid & 1) << 1;     // chunk pair 0 or 2
    const int brow = tid >> 3;            // 0..31
    const int bc = tid & 7;               // chunk 0..7 (and +8)

    const unsigned a_sdst = asb + ((arow * 40 + (ac16a << 3)) << 1);
    const unsigned b_sdst = bsb + ((brow * 136 + (bc << 3)) << 1);
    const __nv_bfloat16* a_gsrc = A + (long)(gm0 + arow) * K + (ac16a << 3);
    const __nv_bfloat16* b_gsrc = B + (long)brow * N + gn0 + (bc << 3);

    // ldmatrix bases (stage 0)
    const unsigned abase = asb + (((wm + (lane & 15)) * 40 + ((lane >> 4) << 3)) << 1);
    const unsigned bbase = bsb + (((lane & 15) * 136 + wn + ((lane >> 4) << 3)) << 1);

    float acc[2][8][4];
#pragma unroll
    for (int i = 0; i < 2; i++)
#pragma unroll
        for (int j = 0; j < 8; j++)
#pragma unroll
            for (int l = 0; l < 4; l++) acc[i][j][l] = 0.f;

    const int nk = K >> 5;

    // prologue: stages 0 and 1
#pragma unroll
    for (int s = 0; s < 2; s++) {
        const __nv_bfloat16* ag = a_gsrc + s * 32;
        const __nv_bfloat16* bg = b_gsrc + (long)s * 32 * N;
        cp16(a_sdst + s * AS_STAGE,      ag);
        cp16(a_sdst + s * AS_STAGE + 16, ag + 8);
        cp16(b_sdst + s * BS_STAGE,       bg);
        cp16(b_sdst + s * BS_STAGE + 128, bg + 64);
        CP_COMMIT();
    }

    int sc = 0;
    for (int kt = 0; kt < nk; kt++) {
        CP_WAIT1();
        __syncthreads();
        if (kt + 2 < nk) {
            int sp = sc - 1; if (sp < 0) sp = 2;
            const __nv_bfloat16* ag = a_gsrc + (kt + 2) * 32;
            const __nv_bfloat16* bg = b_gsrc + (long)(kt + 2) * 32 * N;
            cp16(a_sdst + sp * AS_STAGE,      ag);
            cp16(a_sdst + sp * AS_STAGE + 16, ag + 8);
            cp16(b_sdst + sp * BS_STAGE,       bg);
            cp16(b_sdst + sp * BS_STAGE + 128, bg + 64);
        }
        CP_COMMIT();

        const unsigned ab = abase + sc * AS_STAGE;
        const unsigned bb = bbase + sc * BS_STAGE;
#pragma unroll
        for (int ks = 0; ks < 2; ks++) {
            unsigned af[2][4];
            ldsm_x4(af[0][0], af[0][1], af[0][2], af[0][3], ab + ks * 32);
            ldsm_x4(af[1][0], af[1][1], af[1][2], af[1][3], ab + 1280 + ks * 32);
            unsigned bf[4][4];
#pragma unroll
            for (int nt = 0; nt < 4; nt++)
                ldsm_x4t(bf[nt][0], bf[nt][1], bf[nt][2], bf[nt][3],
                         bb + ks * 4352 + nt * 32);
#pragma unroll
            for (int mt = 0; mt < 2; mt++)
#pragma unroll
                for (int nt = 0; nt < 4; nt++) {
                    mma_bf16(acc[mt][nt * 2],     af[mt][0], af[mt][1], af[mt][2], af[mt][3],
                             bf[nt][0], bf[nt][1]);
                    mma_bf16(acc[mt][nt * 2 + 1], af[mt][0], af[mt][1], af[mt][2], af[mt][3],
                             bf[nt][2], bf[nt][3]);
                }
        }
        sc++; if (sc == 3) sc = 0;
    }

#pragma unroll
    for (int mt = 0; mt < 2; mt++) {
        int row = gm0 + wm + (mt << 4) + (lane >> 2);
#pragma unroll
        for (int j = 0; j < 8; j++) {
            int col = gn0 + wn + (j << 3) + ((lane & 3) << 1);
            float b0 = bias[col], b1 = bias[col + 1];
            float v0 = acc[mt][j][0] + b0;
            float v1 = acc[mt][j][1] + b1;
            float v2 = acc[mt][j][2] + b0;
            float v3 = acc[mt][j][3] + b1;
            if (RELU) {
                v0 = fmaxf(v0, 0.f); v1 = fmaxf(v1, 0.f);
                v2 = fmaxf(v2, 0.f); v3 = fmaxf(v3, 0.f);
            }
            store2(C + (long)row * N + col, v0, v1);
            store2(C + (long)(row + 8) * N + col, v2, v3);
        }
    }
}

// ---------------- windowed attention: 4 t per block ----------------
#define KB_OFF   0
#define VB_OFF   25600
#define QB_OFF   51200
#define PB_OFF   56320
#define MASK_OFF 98304
#define RINV_OFF 99584
#define ATTN_SMEM_BYTES 99840

__global__ __launch_bounds__(256) void attn_kernel(
    const __nv_bfloat16* __restrict__ qkv, const unsigned char* __restrict__ kpm,
    float* __restrict__ ctx)
{
    extern __shared__ char smc[];
    __nv_bfloat16* Pb = (__nv_bfloat16*)(smc + PB_OFF);
    float* maskadd = (float*)(smc + MASK_OFF);
    float* rowinv  = (float*)(smc + RINV_OFF);

    const unsigned sbase = (unsigned)__cvta_generic_to_shared(smc);
    const int tid = threadIdx.x;
    const int w = tid >> 5, lane = tid & 31;
    const int t0 = blockIdx.x << 2, b = blockIdx.y, h = blockIdx.z;

    for (int slot = tid; slot < 4 * MB; slot += 256) {
        int m = slot >> 2, k8 = slot & 3;
        int f = t0 + (m >> 4) - WINR;
        int n = m & 15;
        uint4 kv = make_uint4(0, 0, 0, 0), vv = make_uint4(0, 0, 0, 0);
        if (f >= 0 && f < T_FRAMES) {
            long base = ((long)((b * T_FRAMES + f) * NDET + n)) * QKVN + h * DHEAD + (k8 << 3);
            kv = *(const uint4*)(qkv + base + 256);
            vv = *(const uint4*)(qkv + base + 512);
        }
        *(uint4*)((__nv_bfloat16*)(smc + KB_OFF) + m * 40 + (k8 << 3)) = kv;
        *(uint4*)((__nv_bfloat16*)(smc + VB_OFF) + m * 40 + (k8 << 3)) = vv;
    }
    {
        int r = tid >> 2, k8 = tid & 3;
        long tok = (long)(b * T_FRAMES + t0 + (r >> 4)) * NDET + (r & 15);
        *(uint4*)((__nv_bfloat16*)(smc + QB_OFF) + r * 40 + (k8 << 3)) =
            *(const uint4*)(qkv + tok * QKVN + h * DHEAD + (k8 << 3));
    }
    for (int m = tid; m < MB; m += 256) {
        int f = t0 + (m >> 4) - WINR;
        int n = m & 15;
        bool ok = (f >= 0) && (f < T_FRAMES) &&
                  (kpm[(b * T_FRAMES + f) * NDET + n] == 0);
        maskadd[m] = ok ? 0.f : -1e30f;
    }
    __syncthreads();

    // logits: Pb[64][320] = Q @ K^T
    {
        unsigned qa[4][2][4];
#pragma unroll
        for (int qt = 0; qt < 4; qt++) {
            unsigned qaddr = sbase + QB_OFF +
                ((((qt << 4) + (lane & 15)) * 40 + ((lane >> 4) << 3)) << 1);
            ldsm_x4(qa[qt][0][0], qa[qt][0][1], qa[qt][0][2], qa[qt][0][3], qaddr);
            ldsm_x4(qa[qt][1][0], qa[qt][1][1], qa[qt][1][2], qa[qt][1][3], qaddr + 32);
        }
        const int m0w = w * 40;
        const int lr = lane & 7;
        const int hg = (lane >> 3) & 1;
#pragma unroll
        for (int mt = 0; mt < 5; mt++) {
            int m0 = m0w + (mt << 3);
            unsigned baddr = sbase + KB_OFF + (((m0 + lr) * 40 + (hg << 3)) << 1);
            unsigned b0, b1, b2, b3;
            ldsm_x2(b0, b1, baddr);
            ldsm_x2(b2, b3, baddr + 32);
#pragma unroll
            for (int qt = 0; qt < 4; qt++) {
                float c[4] = {0.f, 0.f, 0.f, 0.f};
                mma_bf16(c, qa[qt][0][0], qa[qt][0][1], qa[qt][0][2], qa[qt][0][3], b0, b1);
                mma_bf16(c, qa[qt][1][0], qa[qt][1][1], qa[qt][1][2], qa[qt][1][3], b2, b3);
                int row = (qt << 4) + (lane >> 2), mc = m0 + ((lane & 3) << 1);
                *(__nv_bfloat162*)(Pb + row * PST + mc)       = __floats2bfloat162_rn(c[0], c[1]);
                *(__nv_bfloat162*)(Pb + (row + 8) * PST + mc) = __floats2bfloat162_rn(c[2], c[3]);
            }
        }
    }
    __syncthreads();

    // masked softmax per row (4 lanes/row); valid window = [16*tloc, 16*tloc+272)
    {
        const int r = tid >> 2, l4 = tid & 3;
        const int p0 = (r >> 4) << 3;
        const int p1 = p0 + 136;
        float mx = -1e30f;
        for (int p = p0 + l4; p < p1; p += 4) {
            float2 v = __bfloat1622float2(*(__nv_bfloat162*)(Pb + r * PST + (p << 1)));
            float2 ma = *(float2*)(maskadd + (p << 1));
            mx = fmaxf(mx, fmaxf(v.x + ma.x, v.y + ma.y));
        }
        mx = fmaxf(mx, __shfl_xor_sync(0xffffffffu, mx, 1));
        mx = fmaxf(mx, __shfl_xor_sync(0xffffffffu, mx, 2));
        float sum = 0.f;
        for (int p = l4; p < 160; p += 4) {
            float e0 = 0.f, e1 = 0.f;
            if (p >= p0 && p < p1) {
                float2 v = __bfloat1622float2(*(__nv_bfloat162*)(Pb + r * PST + (p << 1)));
                float2 ma = *(float2*)(maskadd + (p << 1));
                e0 = __expf(v.x + ma.x - mx);
                e1 = __expf(v.y + ma.y - mx);
                sum += e0 + e1;
            }
            *(__nv_bfloat162*)(Pb + r * PST + (p << 1)) = __floats2bfloat162_rn(e0, e1);
        }
        sum += __shfl_xor_sync(0xffffffffu, sum, 1);
        sum += __shfl_xor_sync(0xffffffffu, sum, 2);
        if (l4 == 0) rowinv[r] = 1.0f / sum;
    }
    __syncthreads();

    // PV: ctx[64][32] = Pb @ Vb; warp owns 16 rows x 16 cols, full k
    {
        const int mrow = (w >> 1) << 4;
        const int nc0  = (w & 1) << 4;
        float c0[4] = {0.f, 0.f, 0.f, 0.f};
        float c1[4] = {0.f, 0.f, 0.f, 0.f};
#pragma unroll 5
        for (int ks = 0; ks < 20; ks++) {
            unsigned aaddr = sbase + PB_OFF +
                (((mrow + (lane & 15)) * PST + (ks << 4) + ((lane >> 4) << 3)) << 1);
            unsigned a0, a1, a2, a3;
            ldsm_x4(a0, a1, a2, a3, aaddr);
            unsigned baddr = sbase + VB_OFF + ((((ks << 4) + (lane & 15)) * 40 + nc0) << 1);
            unsigned b0, b1, b2, b3;
            ldsm_x2t(b0, b1, baddr);
            ldsm_x2t(b2, b3, baddr + 16);
            mma_bf16(c0, a0, a1, a2, a3, b0, b1);
            mma_bf16(c1, a0, a1, a2, a3, b2, b3);
        }
        const int rr = mrow + (lane >> 2);
        const int cc = nc0 + ((lane & 3) << 1);
        const float ri0 = rowinv[rr], ri1 = rowinv[rr + 8];
        long tok0 = (long)(b * T_FRAMES + t0 + (rr >> 4)) * NDET + (rr & 15);
        int r8 = rr + 8;
        long tok1 = (long)(b * T_FRAMES + t0 + (r8 >> 4)) * NDET + (r8 & 15);
        float* o0 = ctx + tok0 * HDIM + h * DHEAD + cc;
        float* o1 = ctx + tok1 * HDIM + h * DHEAD + cc;
        store2(o0,     c0[0] * ri0, c0[1] * ri0);
        store2(o0 + 8, c1[0] * ri0, c1[1] * ri0);
        store2(o1,     c0[2] * ri1, c0[3] * ri1);
        store2(o1 + 8, c1[2] * ri1, c1[3] * ri1);
    }
}

// residual add + LayerNorm; optional fused bf16 output copy
template <bool DUAL>
__global__ __launch_bounds__(256) void add_ln_kernel(
    const float* __restrict__ A, const float* __restrict__ Bv,
    const float* __restrict__ gw, const float* __restrict__ bw,
    float* __restrict__ out, __nv_bfloat16* __restrict__ out16)
{
    const int tok  = (blockIdx.x << 3) + (threadIdx.x >> 5);
    const int lane = threadIdx.x & 31;
    const float4* a4 = (const float4*)(A  + (long)tok * HDIM);
    const float4* b4 = (const float4*)(Bv + (long)tok * HDIM);
    float4 p0 = a4[lane * 2], p1 = a4[lane * 2 + 1];
    float4 q0 = b4[lane * 2], q1 = b4[lane * 2 + 1];
    float vv[8] = { p0.x + q0.x, p0.y + q0.y, p0.z + q0.z, p0.w + q0.w,
                    p1.x + q1.x, p1.y + q1.y, p1.z + q1.z, p1.w + q1.w };
    float s = 0.f;
#pragma unroll
    for (int i = 0; i < 8; i++) s += vv[i];
#pragma unroll
    for (int o = 16; o; o >>= 1) s += __shfl_xor_sync(0xffffffffu, s, o);
    const float mean = s * (1.f / 256.f);
    float vs = 0.f;
#pragma unroll
    for (int i = 0; i < 8; i++) { float d = vv[i] - mean; vs += d * d; }
#pragma unroll
    for (int o = 16; o; o >>= 1) vs += __shfl_xor_sync(0xffffffffu, vs, o);
    const float rs = rsqrtf(vs * (1.f / 256.f) + 1e-5f);

    float4 g0 = ((const float4*)gw)[lane * 2], g1 = ((const float4*)gw)[lane * 2 + 1];
    float4 e0 = ((const float4*)bw)[lane * 2], e1 = ((const float4*)bw)[lane * 2 + 1];
    float r[8];
    r[0] = (vv[0]-mean)*rs*g0.x + e0.x;  r[1] = (vv[1]-mean)*rs*g0.y + e0.y;
    r[2] = (vv[2]-mean)*rs*g0.z + e0.z;  r[3] = (vv[3]-mean)*rs*g0.w + e0.w;
    r[4] = (vv[4]-mean)*rs*g1.x + e1.x;  r[5] = (vv[5]-mean)*rs*g1.y + e1.y;
    r[6] = (vv[6]-mean)*rs*g1.z + e1.z;  r[7] = (vv[7]-mean)*rs*g1.w + e1.w;
    float4* o4 = (float4*)(out + (long)tok * HDIM);
    o4[lane * 2]     = make_float4(r[0], r[1], r[2], r[3]);
    o4[lane * 2 + 1] = make_float4(r[4], r[5], r[6], r[7]);
    if (DUAL) {
        __nv_bfloat16* ob = out16 + (long)tok * HDIM + lane * 8;
        __nv_bfloat162 hh[4];
        hh[0] = __floats2bfloat162_rn(r[0], r[1]);
        hh[1] = __floats2bfloat162_rn(r[2], r[3]);
        hh[2] = __floats2bfloat162_rn(r[4], r[5]);
        hh[3] = __floats2bfloat162_rn(r[6], r[7]);
        *(uint4*)ob = *(uint4*)&hh[0];
    }
}

extern "C" void kernel_launch(void* const* d_in, const int* in_sizes, int n_in,
                              void* d_out, int out_size)
{
    const float* x   = (const float*)d_in[0];
    const unsigned char* kpm = (const unsigned char*)d_in[1];
    const float* Wq = (const float*)d_in[2];
    const float* bq = (const float*)d_in[3];
    const float* Wk = (const float*)d_in[4];
    const float* bk = (const float*)d_in[5];
    const float* Wv = (const float*)d_in[6];
    const float* bv = (const float*)d_in[7];
    const float* W1 = (const float*)d_in[8];
    const float* b1 = (const float*)d_in[9];
    const float* W2 = (const float*)d_in[10];
    const float* b2 = (const float*)d_in[11];
    const float* g1 = (const float*)d_in[12];
    const float* be1 = (const float*)d_in[13];
    const float* g2 = (const float*)d_in[14];
    const float* be2 = (const float*)d_in[15];
    float* out = (float*)d_out;

    float *cb, *yb, *zb, *bqkv;
    __nv_bfloat16 *xb, *qkvb, *y16, *h16, *wqkvb, *w1b, *w2b;
    cudaGetSymbolAddress((void**)&cb, g_c);
    cudaGetSymbolAddress((void**)&yb, g_y);
    cudaGetSymbolAddress((void**)&zb, g_z);
    cudaGetSymbolAddress((void**)&bqkv, g_bqkv);
    cudaGetSymbolAddress((void**)&xb, g_xb);
    cudaGetSymbolAddress((void**)&qkvb, g_qkv);
    cudaGetSymbolAddress((void**)&y16, g_y16);
    cudaGetSymbolAddress((void**)&h16, g_h16);
    cudaGetSymbolAddress((void**)&wqkvb, g_wqkv);
    cudaGetSymbolAddress((void**)&w1b, g_w1);
    cudaGetSymbolAddress((void**)&w2b, g_w2);

    cudaFuncSetAttribute(attn_kernel,
                         cudaFuncAttributeMaxDynamicSharedMemorySize, ATTN_SMEM_BYTES);
    cudaFuncSetAttribute(gemm_cp<false, __nv_bfloat16>,
                         cudaFuncAttributeMaxDynamicSharedMemorySize, GEMM_SMEM_BYTES);
    cudaFuncSetAttribute(gemm_cp<true, __nv_bfloat16>,
                         cudaFuncAttributeMaxDynamicSharedMemorySize, GEMM_SMEM_BYTES);
    cudaFuncSetAttribute(gemm_cp<false, float>,
                         cudaFuncAttributeMaxDynamicSharedMemorySize, GEMM_SMEM_BYTES);

    dim3 blk(256);

    cvt3_kernel<<<dim3(NTOK * HDIM / 1024, 1), blk>>>(x, x, x, xb, xb, xb, NTOK * HDIM);
    pack_qkv_kernel<<<HDIM * HDIM / 1024, blk>>>(Wq, Wk, Wv, bq, bk, bv, wqkvb, bqkv);
    cvt3_kernel<<<dim3(HDIM * FFN / 1024, 2), blk>>>(W1, W2, W1, w1b, w2b, w1b, HDIM * FFN);

    gemm_cp<false, __nv_bfloat16><<<dim3(QKVN / 128, NTOK / 128), blk, GEMM_SMEM_BYTES>>>(
        xb, wqkvb, bqkv, qkvb, NTOK, QKVN, HDIM);

    dim3 gAttn(T_FRAMES / TG, 4, 8);
    attn_kernel<<<gAttn, blk, ATTN_SMEM_BYTES>>>(qkvb, kpm, cb);

    add_ln_kernel<true><<<NTOK / 8, blk>>>(x, cb, g1, be1, yb, y16);

    gemm_cp<true,  __nv_bfloat16><<<dim3(FFN / 128, NTOK / 128), blk, GEMM_SMEM_BYTES>>>(
        y16, w1b, b1, h16, NTOK, FFN, HDIM);
    gemm_cp<false, float><<<dim3(HDIM / 128, NTOK / 128), blk, GEMM_SMEM_BYTES>>>(
        h16, w2b, b2, zb, NTOK, HDIM, FFN);

    add_ln_kernel<false><<<NTOK / 8, blk>>>(yb, zb, g2, be2, out, nullptr);
}

// round 16
// speedup vs baseline: 3.2343x; 1.0116x over previous
#include <cuda_runtime.h>
#include <cuda_bf16.h>
#include <math.h>

#define T_FRAMES 256
#define NDET     16
#define HDIM     256
#define DHEAD    32
#define WINR     8
#define NTOK     16384       // 4*256*16
#define FFN      1024
#define QKVN     768
#define TG       4           // t per attn block
#define MB       320         // (TG-1 + 17) * 16 keys
#define PST      328         // P row stride (halfs)

// fp32 scratch
__device__ float g_c[NTOK * HDIM];
__device__ float g_y[NTOK * HDIM];
__device__ float g_z[NTOK * HDIM];
__device__ float g_bqkv[QKVN];
// bf16 scratch
__device__ __nv_bfloat16 g_xb[NTOK * HDIM];
__device__ __nv_bfloat16 g_qkv[NTOK * QKVN];
__device__ __nv_bfloat16 g_y16[NTOK * HDIM];
__device__ __nv_bfloat16 g_h16[NTOK * FFN];
__device__ __nv_bfloat16 g_wqkv[HDIM * QKVN];
__device__ __nv_bfloat16 g_w1[HDIM * FFN];
__device__ __nv_bfloat16 g_w2[FFN * HDIM];

__device__ __forceinline__ void mma_bf16(float c[4],
    unsigned a0, unsigned a1, unsigned a2, unsigned a3, unsigned b0, unsigned b1) {
    asm volatile(
        "mma.sync.aligned.m16n8k16.row.col.f32.bf16.bf16.f32 "
        "{%0,%1,%2,%3}, {%4,%5,%6,%7}, {%8,%9}, {%0,%1,%2,%3};\n"
        : "+f"(c[0]), "+f"(c[1]), "+f"(c[2]), "+f"(c[3])
        : "r"(a0), "r"(a1), "r"(a2), "r"(a3), "r"(b0), "r"(b1));
}
__device__ __forceinline__ void ldsm_x4(unsigned& r0, unsigned& r1, unsigned& r2, unsigned& r3,
                                        unsigned addr) {
    asm volatile("ldmatrix.sync.aligned.m8n8.x4.shared.b16 {%0,%1,%2,%3}, [%4];"
                 : "=r"(r0), "=r"(r1), "=r"(r2), "=r"(r3) : "r"(addr));
}
__device__ __forceinline__ void ldsm_x4t(unsigned& r0, unsigned& r1, unsigned& r2, unsigned& r3,
                                         unsigned addr) {
    asm volatile("ldmatrix.sync.aligned.m8n8.x4.trans.shared.b16 {%0,%1,%2,%3}, [%4];"
                 : "=r"(r0), "=r"(r1), "=r"(r2), "=r"(r3) : "r"(addr));
}
__device__ __forceinline__ void ldsm_x2(unsigned& r0, unsigned& r1, unsigned addr) {
    asm volatile("ldmatrix.sync.aligned.m8n8.x2.shared.b16 {%0,%1}, [%2];"
                 : "=r"(r0), "=r"(r1) : "r"(addr));
}
__device__ __forceinline__ void ldsm_x2t(unsigned& r0, unsigned& r1, unsigned addr) {
    asm volatile("ldmatrix.sync.aligned.m8n8.x2.trans.shared.b16 {%0,%1}, [%2];"
                 : "=r"(r0), "=r"(r1) : "r"(addr));
}
__device__ __forceinline__ void cp16(unsigned saddr, const void* gaddr) {
    asm volatile("cp.async.cg.shared.global [%0], [%1], 16;\n"
                 :: "r"(saddr), "l"(gaddr));
}
#define CP_COMMIT() asm volatile("cp.async.commit_group;\n" ::: "memory")
#define CP_WAIT1()  asm volatile("cp.async.wait_group 1;\n" ::: "memory")

__device__ __forceinline__ void store2(float* p, float a, float b) {
    *(float2*)p = make_float2(a, b);
}
__device__ __forceinline__ void store2(__nv_bfloat16* p, float a, float b) {
    *(__nv_bfloat162*)p = __floats2bfloat162_rn(a, b);
}

// ---- fp32 -> bf16 conversion: up to 3 tensors via blockIdx.y ----
__global__ __launch_bounds__(256) void cvt3_kernel(
    const float* __restrict__ a, const float* __restrict__ b, const float* __restrict__ c,
    __nv_bfloat16* oa, __nv_bfloat16* ob, __nv_bfloat16* oc, int n)
{
    const float* src = (blockIdx.y == 0) ? a : (blockIdx.y == 1) ? b : c;
    __nv_bfloat16* dst = (blockIdx.y == 0) ? oa : (blockIdx.y == 1) ? ob : oc;
    int i = (blockIdx.x * 256 + threadIdx.x) << 2;
    if (i < n) {
        float4 v = *(const float4*)(src + i);
        *(__nv_bfloat162*)(dst + i)     = __floats2bfloat162_rn(v.x, v.y);
        *(__nv_bfloat162*)(dst + i + 2) = __floats2bfloat162_rn(v.z, v.w);
    }
}

// ---- pack Wq*qs | Wk | Wv -> [HDIM][768] bf16, bias likewise ----
__global__ __launch_bounds__(256) void pack_qkv_kernel(
    const float* __restrict__ Wq, const float* __restrict__ Wk, const float* __restrict__ Wv,
    const float* __restrict__ bq, const float* __restrict__ bk, const float* __restrict__ bv,
    __nv_bfloat16* __restrict__ w, float* __restrict__ bias)
{
    const float qs = 0.17677669529663687f; // 1/sqrt(32)
    int i = (blockIdx.x * 256 + threadIdx.x) << 2;
    if (i < HDIM * HDIM) {
        int krow = i >> 8, j = i & 255;
        __nv_bfloat16* wr = w + krow * QKVN + j;
        float4 a = *(const float4*)(Wq + i);
        *(__nv_bfloat162*)(wr)     = __floats2bfloat162_rn(a.x * qs, a.y * qs);
        *(__nv_bfloat162*)(wr + 2) = __floats2bfloat162_rn(a.z * qs, a.w * qs);
        float4 bb = *(const float4*)(Wk + i);
        *(__nv_bfloat162*)(wr + 256)     = __floats2bfloat162_rn(bb.x, bb.y);
        *(__nv_bfloat162*)(wr + 256 + 2) = __floats2bfloat162_rn(bb.z, bb.w);
        float4 cc = *(const float4*)(Wv + i);
        *(__nv_bfloat162*)(wr + 512)     = __floats2bfloat162_rn(cc.x, cc.y);
        *(__nv_bfloat162*)(wr + 512 + 2) = __floats2bfloat162_rn(cc.z, cc.w);
    }
    if (blockIdx.x == 0 && threadIdx.x < 64) {
        int j = threadIdx.x << 2;
        float4 v = *(const float4*)(bq + j);
        *(float4*)(bias + j) = make_float4(v.x * qs, v.y * qs, v.z * qs, v.w * qs);
        *(float4*)(bias + 256 + j) = *(const float4*)(bk + j);
        *(float4*)(bias + 512 + j) = *(const float4*)(bv + j);
    }
}

// ---------------- bf16 TC GEMM: BM=128 BN=128 BK=32, warp tile 32x64 ----------------
// 3-stage cp.async, 1 barrier/ktile, FULL fragment hoist (12 ldsm then 32 mma).
#define AS_STAGE 10240          // 128*40*2
#define BS_STAGE 8704           // 32*136*2
#define BS_BASE  30720          // 3*AS_STAGE
#define GEMM_SMEM_BYTES (BS_BASE + 3 * BS_STAGE)   // 56832

template <bool RELU, typename OutT>
__global__ __launch_bounds__(256, 2) void gemm_cp(
    const __nv_bfloat16* __restrict__ A, const __nv_bfloat16* __restrict__ B,
    const float* __restrict__ bias, OutT* __restrict__ C,
    int M, int N, int K)
{
    extern __shared__ char gsm[];
    const unsigned asb = (unsigned)__cvta_generic_to_shared(gsm);
    const unsigned bsb = asb + BS_BASE;

    const int tid = threadIdx.x;
    const int warp = tid >> 5, lane = tid & 31;
    const int wm = (warp >> 1) << 5;      // 0,32,64,96
    const int wn = (warp & 1) << 6;       // 0,64
    const int gm0 = blockIdx.y << 7;
    const int gn0 = blockIdx.x << 7;

    const int arow = tid >> 1;
    const int ac16a = (tid & 1) << 1;
    const int brow = tid >> 3;
    const int bc = tid & 7;

    const unsigned a_sdst = asb + ((arow * 40 + (ac16a << 3)) << 1);
    const unsigned b_sdst = bsb + ((brow * 136 + (bc << 3)) << 1);
    const __nv_bfloat16* a_gsrc = A + (long)(gm0 + arow) * K + (ac16a << 3);
    const __nv_bfloat16* b_gsrc = B + (long)brow * N + gn0 + (bc << 3);

    const unsigned abase = asb + (((wm + (lane & 15)) * 40 + ((lane >> 4) << 3)) << 1);
    const unsigned bbase = bsb + (((lane & 15) * 136 + wn + ((lane >> 4) << 3)) << 1);

    float acc[2][8][4];
#pragma unroll
    for (int i = 0; i < 2; i++)
#pragma unroll
        for (int j = 0; j < 8; j++)
#pragma unroll
            for (int l = 0; l < 4; l++) acc[i][j][l] = 0.f;

    const int nk = K >> 5;

    // prologue: stages 0 and 1
#pragma unroll
    for (int s = 0; s < 2; s++) {
        const __nv_bfloat16* ag = a_gsrc + s * 32;
        const __nv_bfloat16* bg = b_gsrc + (long)s * 32 * N;
        cp16(a_sdst + s * AS_STAGE,      ag);
        cp16(a_sdst + s * AS_STAGE + 16, ag + 8);
        cp16(b_sdst + s * BS_STAGE,       bg);
        cp16(b_sdst + s * BS_STAGE + 128, bg + 64);
        CP_COMMIT();
    }

    int sc = 0;
    for (int kt = 0; kt < nk; kt++) {
        CP_WAIT1();
        __syncthreads();
        if (kt + 2 < nk) {
            int sp = sc - 1; if (sp < 0) sp = 2;
            const __nv_bfloat16* ag = a_gsrc + (kt + 2) * 32;
            const __nv_bfloat16* bg = b_gsrc + (long)(kt + 2) * 32 * N;
            cp16(a_sdst + sp * AS_STAGE,      ag);
            cp16(a_sdst + sp * AS_STAGE + 16, ag + 8);
            cp16(b_sdst + sp * BS_STAGE,       bg);
            cp16(b_sdst + sp * BS_STAGE + 128, bg + 64);
        }
        CP_COMMIT();

        const unsigned ab = abase + sc * AS_STAGE;
        const unsigned bb = bbase + sc * BS_STAGE;

        // ---- hoist ALL fragment loads for this ktile (12 ldsm issues) ----
        unsigned af[2][2][4];   // [ks][mt][4]
        unsigned bf[2][4][4];   // [ks][nt][4]
#pragma unroll
        for (int ks = 0; ks < 2; ks++) {
            ldsm_x4(af[ks][0][0], af[ks][0][1], af[ks][0][2], af[ks][0][3],
                    ab + ks * 32);
            ldsm_x4(af[ks][1][0], af[ks][1][1], af[ks][1][2], af[ks][1][3],
                    ab + 1280 + ks * 32);
        }
#pragma unroll
        for (int ks = 0; ks < 2; ks++)
#pragma unroll
            for (int nt = 0; nt < 4; nt++)
                ldsm_x4t(bf[ks][nt][0], bf[ks][nt][1], bf[ks][nt][2], bf[ks][nt][3],
                         bb + ks * 4352 + nt * 32);

        // ---- 32 back-to-back mma ----
#pragma unroll
        for (int ks = 0; ks < 2; ks++)
#pragma unroll
            for (int mt = 0; mt < 2; mt++)
#pragma unroll
                for (int nt = 0; nt < 4; nt++) {
                    mma_bf16(acc[mt][nt * 2],
                             af[ks][mt][0], af[ks][mt][1], af[ks][mt][2], af[ks][mt][3],
                             bf[ks][nt][0], bf[ks][nt][1]);
                    mma_bf16(acc[mt][nt * 2 + 1],
                             af[ks][mt][0], af[ks][mt][1], af[ks][mt][2], af[ks][mt][3],
                             bf[ks][nt][2], bf[ks][nt][3]);
                }
        sc++; if (sc == 3) sc = 0;
    }

#pragma unroll
    for (int mt = 0; mt < 2; mt++) {
        int row = gm0 + wm + (mt << 4) + (lane >> 2);
#pragma unroll
        for (int j = 0; j < 8; j++) {
            int col = gn0 + wn + (j << 3) + ((lane & 3) << 1);
            float b0 = bias[col], b1 = bias[col + 1];
            float v0 = acc[mt][j][0] + b0;
            float v1 = acc[mt][j][1] + b1;
            float v2 = acc[mt][j][2] + b0;
            float v3 = acc[mt][j][3] + b1;
            if (RELU) {
                v0 = fmaxf(v0, 0.f); v1 = fmaxf(v1, 0.f);
                v2 = fmaxf(v2, 0.f); v3 = fmaxf(v3, 0.f);
            }
            store2(C + (long)row * N + col, v0, v1);
            store2(C + (long)(row + 8) * N + col, v2, v3);
        }
    }
}

// ---------------- windowed attention: 4 t per block ----------------
#define KB_OFF   0
#define VB_OFF   25600
#define QB_OFF   51200
#define PB_OFF   56320
#define MASK_OFF 98304
#define RINV_OFF 99584
#define ATTN_SMEM_BYTES 99840

__global__ __launch_bounds__(256) void attn_kernel(
    const __nv_bfloat16* __restrict__ qkv, const unsigned char* __restrict__ kpm,
    float* __restrict__ ctx)
{
    extern __shared__ char smc[];
    __nv_bfloat16* Pb = (__nv_bfloat16*)(smc + PB_OFF);
    float* maskadd = (float*)(smc + MASK_OFF);
    float* rowinv  = (float*)(smc + RINV_OFF);

    const unsigned sbase = (unsigned)__cvta_generic_to_shared(smc);
    const int tid = threadIdx.x;
    const int w = tid >> 5, lane = tid & 31;
    const int t0 = blockIdx.x << 2, b = blockIdx.y, h = blockIdx.z;

    for (int slot = tid; slot < 4 * MB; slot += 256) {
        int m = slot >> 2, k8 = slot & 3;
        int f = t0 + (m >> 4) - WINR;
        int n = m & 15;
        uint4 kv = make_uint4(0, 0, 0, 0), vv = make_uint4(0, 0, 0, 0);
        if (f >= 0 && f < T_FRAMES) {
            long base = ((long)((b * T_FRAMES + f) * NDET + n)) * QKVN + h * DHEAD + (k8 << 3);
            kv = *(const uint4*)(qkv + base + 256);
            vv = *(const uint4*)(qkv + base + 512);
        }
        *(uint4*)((__nv_bfloat16*)(smc + KB_OFF) + m * 40 + (k8 << 3)) = kv;
        *(uint4*)((__nv_bfloat16*)(smc + VB_OFF) + m * 40 + (k8 << 3)) = vv;
    }
    {
        int r = tid >> 2, k8 = tid & 3;
        long tok = (long)(b * T_FRAMES + t0 + (r >> 4)) * NDET + (r & 15);
        *(uint4*)((__nv_bfloat16*)(smc + QB_OFF) + r * 40 + (k8 << 3)) =
            *(const uint4*)(qkv + tok * QKVN + h * DHEAD + (k8 << 3));
    }
    for (int m = tid; m < MB; m += 256) {
        int f = t0 + (m >> 4) - WINR;
        int n = m & 15;
        bool ok = (f >= 0) && (f < T_FRAMES) &&
                  (kpm[(b * T_FRAMES + f) * NDET + n] == 0);
        maskadd[m] = ok ? 0.f : -1e30f;
    }
    __syncthreads();

    // logits: Pb[64][320] = Q @ K^T
    {
        unsigned qa[4][2][4];
#pragma unroll
        for (int qt = 0; qt < 4; qt++) {
            unsigned qaddr = sbase + QB_OFF +
                ((((qt << 4) + (lane & 15)) * 40 + ((lane >> 4) << 3)) << 1);
            ldsm_x4(qa[qt][0][0], qa[qt][0][1], qa[qt][0][2], qa[qt][0][3], qaddr);
            ldsm_x4(qa[qt][1][0], qa[qt][1][1], qa[qt][1][2], qa[qt][1][3], qaddr + 32);
        }
        const int m0w = w * 40;
        const int lr = lane & 7;
        const int hg = (lane >> 3) & 1;
#pragma unroll
        for (int mt = 0; mt < 5; mt++) {
            int m0 = m0w + (mt << 3);
            unsigned baddr = sbase + KB_OFF + (((m0 + lr) * 40 + (hg << 3)) << 1);
            unsigned b0, b1, b2, b3;
            ldsm_x2(b0, b1, baddr);
            ldsm_x2(b2, b3, baddr + 32);
#pragma unroll
            for (int qt = 0; qt < 4; qt++) {
                float c[4] = {0.f, 0.f, 0.f, 0.f};
                mma_bf16(c, qa[qt][0][0], qa[qt][0][1], qa[qt][0][2], qa[qt][0][3], b0, b1);
                mma_bf16(c, qa[qt][1][0], qa[qt][1][1], qa[qt][1][2], qa[qt][1][3], b2, b3);
                int row = (qt << 4) + (lane >> 2), mc = m0 + ((lane & 3) << 1);
                *(__nv_bfloat162*)(Pb + row * PST + mc)       = __floats2bfloat162_rn(c[0], c[1]);
                *(__nv_bfloat162*)(Pb + (row + 8) * PST + mc) = __floats2bfloat162_rn(c[2], c[3]);
            }
        }
    }
    __syncthreads();

    // masked softmax per row (4 lanes/row); valid window = [16*tloc, 16*tloc+272)
    {
        const int r = tid >> 2, l4 = tid & 3;
        const int p0 = (r >> 4) << 3;
        const int p1 = p0 + 136;
        float mx = -1e30f;
        for (int p = p0 + l4; p < p1; p += 4) {
            float2 v = __bfloat1622float2(*(__nv_bfloat162*)(Pb + r * PST + (p << 1)));
            float2 ma = *(float2*)(maskadd + (p << 1));
            mx = fmaxf(mx, fmaxf(v.x + ma.x, v.y + ma.y));
        }
        mx = fmaxf(mx, __shfl_xor_sync(0xffffffffu, mx, 1));
        mx = fmaxf(mx, __shfl_xor_sync(0xffffffffu, mx, 2));
        float sum = 0.f;
        for (int p = l4; p < 160; p += 4) {
            float e0 = 0.f, e1 = 0.f;
            if (p >= p0 && p < p1) {
                float2 v = __bfloat1622float2(*(__nv_bfloat162*)(Pb + r * PST + (p << 1)));
                float2 ma = *(float2*)(maskadd + (p << 1));
                e0 = __expf(v.x + ma.x - mx);
                e1 = __expf(v.y + ma.y - mx);
                sum += e0 + e1;
            }
            *(__nv_bfloat162*)(Pb + r * PST + (p << 1)) = __floats2bfloat162_rn(e0, e1);
        }
        sum += __shfl_xor_sync(0xffffffffu, sum, 1);
        sum += __shfl_xor_sync(0xffffffffu, sum, 2);
        if (l4 == 0) rowinv[r] = 1.0f / sum;
    }
    __syncthreads();

    // PV: ctx[64][32] = Pb @ Vb; warp owns 16 rows x 16 cols, full k
    {
        const int mrow = (w >> 1) << 4;
        const int nc0  = (w & 1) << 4;
        float c0[4] = {0.f, 0.f, 0.f, 0.f};
        float c1[4] = {0.f, 0.f, 0.f, 0.f};
#pragma unroll 5
        for (int ks = 0; ks < 20; ks++) {
            unsigned aaddr = sbase + PB_OFF +
                (((mrow + (lane & 15)) * PST + (ks << 4) + ((lane >> 4) << 3)) << 1);
            unsigned a0, a1, a2, a3;
            ldsm_x4(a0, a1, a2, a3, aaddr);
            unsigned baddr = sbase + VB_OFF + ((((ks << 4) + (lane & 15)) * 40 + nc0) << 1);
            unsigned b0, b1, b2, b3;
            ldsm_x2t(b0, b1, baddr);
            ldsm_x2t(b2, b3, baddr + 16);
            mma_bf16(c0, a0, a1, a2, a3, b0, b1);
            mma_bf16(c1, a0, a1, a2, a3, b2, b3);
        }
        const int rr = mrow + (lane >> 2);
        const int cc = nc0 + ((lane & 3) << 1);
        const float ri0 = rowinv[rr], ri1 = rowinv[rr + 8];
        long tok0 = (long)(b * T_FRAMES + t0 + (rr >> 4)) * NDET + (rr & 15);
        int r8 = rr + 8;
        long tok1 = (long)(b * T_FRAMES + t0 + (r8 >> 4)) * NDET + (r8 & 15);
        float* o0 = ctx + tok0 * HDIM + h * DHEAD + cc;
        float* o1 = ctx + tok1 * HDIM + h * DHEAD + cc;
        store2(o0,     c0[0] * ri0, c0[1] * ri0);
        store2(o0 + 8, c1[0] * ri0, c1[1] * ri0);
        store2(o1,     c0[2] * ri1, c0[3] * ri1);
        store2(o1 + 8, c1[2] * ri1, c1[3] * ri1);
    }
}

// residual add + LayerNorm; optional fused bf16 output copy
template <bool DUAL>
__global__ __launch_bounds__(256) void add_ln_kernel(
    const float* __restrict__ A, const float* __restrict__ Bv,
    const float* __restrict__ gw, const float* __restrict__ bw,
    float* __restrict__ out, __nv_bfloat16* __restrict__ out16)
{
    const int tok  = (blockIdx.x << 3) + (threadIdx.x >> 5);
    const int lane = threadIdx.x & 31;
    const float4* a4 = (const float4*)(A  + (long)tok * HDIM);
    const float4* b4 = (const float4*)(Bv + (long)tok * HDIM);
    float4 p0 = a4[lane * 2], p1 = a4[lane * 2 + 1];
    float4 q0 = b4[lane * 2], q1 = b4[lane * 2 + 1];
    float vv[8] = { p0.x + q0.x, p0.y + q0.y, p0.z + q0.z, p0.w + q0.w,
                    p1.x + q1.x, p1.y + q1.y, p1.z + q1.z, p1.w + q1.w };
    float s = 0.f;
#pragma unroll
    for (int i = 0; i < 8; i++) s += vv[i];
#pragma unroll
    for (int o = 16; o; o >>= 1) s += __shfl_xor_sync(0xffffffffu, s, o);
    const float mean = s * (1.f / 256.f);
    float vs = 0.f;
#pragma unroll
    for (int i = 0; i < 8; i++) { float d = vv[i] - mean; vs += d * d; }
#pragma unroll
    for (int o = 16; o; o >>= 1) vs += __shfl_xor_sync(0xffffffffu, vs, o);
    const float rs = rsqrtf(vs * (1.f / 256.f) + 1e-5f);

    float4 g0 = ((const float4*)gw)[lane * 2], g1 = ((const float4*)gw)[lane * 2 + 1];
    float4 e0 = ((const float4*)bw)[lane * 2], e1 = ((const float4*)bw)[lane * 2 + 1];
    float r[8];
    r[0] = (vv[0]-mean)*rs*g0.x + e0.x;  r[1] = (vv[1]-mean)*rs*g0.y + e0.y;
    r[2] = (vv[2]-mean)*rs*g0.z + e0.z;  r[3] = (vv[3]-mean)*rs*g0.w + e0.w;
    r[4] = (vv[4]-mean)*rs*g1.x + e1.x;  r[5] = (vv[5]-mean)*rs*g1.y + e1.y;
    r[6] = (vv[6]-mean)*rs*g1.z + e1.z;  r[7] = (vv[7]-mean)*rs*g1.w + e1.w;
    float4* o4 = (float4*)(out + (long)tok * HDIM);
    o4[lane * 2]     = make_float4(r[0], r[1], r[2], r[3]);
    o4[lane * 2 + 1] = make_float4(r[4], r[5], r[6], r[7]);
    if (DUAL) {
        __nv_bfloat16* ob = out16 + (long)tok * HDIM + lane * 8;
        __nv_bfloat162 hh[4];
        hh[0] = __floats2bfloat162_rn(r[0], r[1]);
        hh[1] = __floats2bfloat162_rn(r[2], r[3]);
        hh[2] = __floats2bfloat162_rn(r[4], r[5]);
        hh[3] = __floats2bfloat162_rn(r[6], r[7]);
        *(uint4*)ob = *(uint4*)&hh[0];
    }
}

extern "C" void kernel_launch(void* const* d_in, const int* in_sizes, int n_in,
                              void* d_out, int out_size)
{
    const float* x   = (const float*)d_in[0];
    const unsigned char* kpm = (const unsigned char*)d_in[1];
    const float* Wq = (const float*)d_in[2];
    const float* bq = (const float*)d_in[3];
    const float* Wk = (const float*)d_in[4];
    const float* bk = (const float*)d_in[5];
    const float* Wv = (const float*)d_in[6];
    const float* bv = (const float*)d_in[7];
    const float* W1 = (const float*)d_in[8];
    const float* b1 = (const float*)d_in[9];
    const float* W2 = (const float*)d_in[10];
    const float* b2 = (const float*)d_in[11];
    const float* g1 = (const float*)d_in[12];
    const float* be1 = (const float*)d_in[13];
    const float* g2 = (const float*)d_in[14];
    const float* be2 = (const float*)d_in[15];
    float* out = (float*)d_out;

    float *cb, *yb, *zb, *bqkv;
    __nv_bfloat16 *xb, *qkvb, *y16, *h16, *wqkvb, *w1b, *w2b;
    cudaGetSymbolAddress((void**)&cb, g_c);
    cudaGetSymbolAddress((void**)&yb, g_y);
    cudaGetSymbolAddress((void**)&zb, g_z);
    cudaGetSymbolAddress((void**)&bqkv, g_bqkv);
    cudaGetSymbolAddress((void**)&xb, g_xb);
    cudaGetSymbolAddress((void**)&qkvb, g_qkv);
    cudaGetSymbolAddress((void**)&y16, g_y16);
    cudaGetSymbolAddress((void**)&h16, g_h16);
    cudaGetSymbolAddress((void**)&wqkvb, g_wqkv);
    cudaGetSymbolAddress((void**)&w1b, g_w1);
    cudaGetSymbolAddress((void**)&w2b, g_w2);

    cudaFuncSetAttribute(attn_kernel,
                         cudaFuncAttributeMaxDynamicSharedMemorySize, ATTN_SMEM_BYTES);
    cudaFuncSetAttribute(gemm_cp<false, __nv_bfloat16>,
                         cudaFuncAttributeMaxDynamicSharedMemorySize, GEMM_SMEM_BYTES);
    cudaFuncSetAttribute(gemm_cp<true, __nv_bfloat16>,
                         cudaFuncAttributeMaxDynamicSharedMemorySize, GEMM_SMEM_BYTES);
    cudaFuncSetAttribute(gemm_cp<false, float>,
                         cudaFuncAttributeMaxDynamicSharedMemorySize, GEMM_SMEM_BYTES);

    dim3 blk(256);

    cvt3_kernel<<<dim3(NTOK * HDIM / 1024, 1), blk>>>(x, x, x, xb, xb, xb, NTOK * HDIM);
    pack_qkv_kernel<<<HDIM * HDIM / 1024, blk>>>(Wq, Wk, Wv, bq, bk, bv, wqkvb, bqkv);
    cvt3_kernel<<<dim3(HDIM * FFN / 1024, 2), blk>>>(W1, W2, W1, w1b, w2b, w1b, HDIM * FFN);

    gemm_cp<false, __nv_bfloat16><<<dim3(QKVN / 128, NTOK / 128), blk, GEMM_SMEM_BYTES>>>(
        xb, wqkvb, bqkv, qkvb, NTOK, QKVN, HDIM);

    dim3 gAttn(T_FRAMES / TG, 4, 8);
    attn_kernel<<<gAttn, blk, ATTN_SMEM_BYTES>>>(qkvb, kpm, cb);

    add_ln_kernel<true><<<NTOK / 8, blk>>>(x, cb, g1, be1, yb, y16);

    gemm_cp<true,  __nv_bfloat16><<<dim3(FFN / 128, NTOK / 128), blk, GEMM_SMEM_BYTES>>>(
        y16, w1b, b1, h16, NTOK, FFN, HDIM);
    gemm_cp<false, float><<<dim3(HDIM / 128, NTOK / 128), blk, GEMM_SMEM_BYTES>>>(
        h16, w2b, b2, zb, NTOK, HDIM, FFN);

    add_ln_kernel<false><<<NTOK / 8, blk>>>(yb, zb, g2, be2, out, nullptr);
}